// round 1
// baseline (speedup 1.0000x reference)
#include <cuda_runtime.h>

// ---------------- problem constants ----------------
#define D_      256
#define B_      4
#define M_      64
#define N_      512
#define H_      8
#define F_      1024
#define ROWS_M  256        // B*M
#define ROWS_O  2048       // B*N
#define NEDGE   131072     // B*N*M
#define SCALE_  0.17677669529663687f   // 1/sqrt(32)
#define EPS_    1e-5f
#define NEG_INF (-1e30f)

// ---------------- scratch (device globals; no runtime allocation) ----------------
__device__ float g_mnorm[ROWS_M * D_];
__device__ float g_onorm[ROWS_O * D_];
__device__ float g_q   [ROWS_M * D_];
__device__ float g_ksf [ROWS_M * D_];
__device__ float g_vsf [ROWS_M * D_];
__device__ float g_k   [ROWS_O * D_];
__device__ float g_v   [ROWS_O * D_];
__device__ float g_E   [(size_t)NEDGE * D_];   // compacted projected edges
__device__ float g_me2 [ROWS_M * D_];
__device__ float g_hbuf[ROWS_M * D_];
__device__ float g_f1  [ROWS_M * F_];
__device__ int   g_rowIdx[NEDGE];
__device__ int   g_map  [NEDGE];               // (b*M+m)*N + n -> compact row or -1
__device__ int   g_count;
__device__ int   g_maskMode;                   // 0=int32, 1=bool/int8, 2=float32

// ---------------- helpers ----------------
__device__ __forceinline__ float warpSum(float v) {
#pragma unroll
    for (int o = 16; o; o >>= 1) v += __shfl_xor_sync(0xffffffffu, v, o);
    return v;
}
__device__ __forceinline__ float warpMax(float v) {
#pragma unroll
    for (int o = 16; o; o >>= 1) v = fmaxf(v, __shfl_xor_sync(0xffffffffu, v, o));
    return v;
}

// ---------------- small utility kernels ----------------
__global__ void zero_kernel() { g_count = 0; }

// Determine mask storage dtype from byte patterns. Scanning `nelem` bytes is
// safe for every candidate dtype (bool buffer has exactly nelem bytes).
__global__ void detect_kernel(const unsigned char* __restrict__ p, int nelem) {
    __shared__ int sgt1, snz;
    if (threadIdx.x == 0) { sgt1 = 0; snz = 0; }
    __syncthreads();
    int gt1 = 0, nz = 0;
    for (int i = threadIdx.x; i < nelem; i += blockDim.x) {
        unsigned char v = p[i];
        if (v > 1) gt1 = 1;
        if (v != 0 && (i & 3) != 0) nz = 1;
    }
    if (gt1) atomicOr(&sgt1, 1);
    if (nz)  atomicOr(&snz, 1);
    __syncthreads();
    if (threadIdx.x == 0) g_maskMode = sgt1 ? 2 : (snz ? 1 : 0);
}

// Compact active (mask true) edge rows: build gather list + per-(b,m) n-map.
__global__ void compact_kernel(const void* __restrict__ mask) {
    int i = blockIdx.x * blockDim.x + threadIdx.x;   // linear over (B,N,M)
    if (i >= NEDGE) return;
    int mode = g_maskMode;
    bool a;
    if (mode == 2)      a = ((const float*)mask)[i] != 0.0f;
    else if (mode == 1) a = ((const unsigned char*)mask)[i] != 0;
    else                a = ((const int*)mask)[i] != 0;
    int b = i >> 15;            // / (N*M)
    int r = i & 32767;
    int n = r >> 6;             // / M
    int m = r & 63;
    int mi = ((b << 6) + m) * N_ + n;
    if (a) {
        int pos = atomicAdd(&g_count, 1);
        g_rowIdx[pos] = i;
        g_map[mi] = pos;
    } else {
        g_map[mi] = -1;
    }
}

// ---------------- layernorm (one CTA per row of 256) ----------------
__global__ void ln_kernel(const float* __restrict__ x, const float* __restrict__ g,
                          const float* __restrict__ beta, float* __restrict__ y) {
    __shared__ float red[16];
    int row = blockIdx.x;
    int tid = threadIdx.x;
    float v = x[(size_t)row * D_ + tid];
    float s  = warpSum(v);
    float s2 = warpSum(v * v);
    if ((tid & 31) == 0) { red[tid >> 5] = s; red[8 + (tid >> 5)] = s2; }
    __syncthreads();
    float sum = 0.f, sum2 = 0.f;
#pragma unroll
    for (int i = 0; i < 8; i++) { sum += red[i]; sum2 += red[8 + i]; }
    float mu  = sum * (1.0f / D_);
    float var = sum2 * (1.0f / D_) - mu * mu;
    float inv = rsqrtf(var + EPS_);
    y[(size_t)row * D_ + tid] = (v - mu) * inv * g[tid] + beta[tid];
}

// ---------------- generic small SGEMM: 64x64 tile, TM=TN=4 ----------------
// C[r,n] = act(sum_k A[r,k]*W[k,n] + bias[n]) (+ resid[r,n])
__global__ __launch_bounds__(256)
void gemm64(const float* __restrict__ A, const float* __restrict__ W,
            const float* __restrict__ bias, const float* __restrict__ resid,
            float* __restrict__ C, int K, int N, int doRelu) {
    __shared__ float As[16][68];
    __shared__ float Ws[16][64];
    int tid = threadIdx.x;
    int tx = tid & 15, ty = tid >> 4;
    int r0 = blockIdx.x * 64, n0 = blockIdx.y * 64;
    float acc[4][4] = {};
    int aRow = tid >> 2, aKq = tid & 3;          // one float4 of A per thread
    int wKr  = tid >> 4, wNq = tid & 15;         // one float4 of W per thread

    for (int kb = 0; kb < K; kb += 16) {
        float4 av = *(const float4*)&A[(size_t)(r0 + aRow) * K + kb + aKq * 4];
        float4 wv = *(const float4*)&W[(size_t)(kb + wKr) * N + n0 + wNq * 4];
        __syncthreads();
        As[aKq * 4 + 0][aRow] = av.x;
        As[aKq * 4 + 1][aRow] = av.y;
        As[aKq * 4 + 2][aRow] = av.z;
        As[aKq * 4 + 3][aRow] = av.w;
        *(float4*)&Ws[wKr][wNq * 4] = wv;
        __syncthreads();
#pragma unroll
        for (int k = 0; k < 16; k++) {
            float4 a4 = *(const float4*)&As[k][ty * 4];
            float4 w4 = *(const float4*)&Ws[k][tx * 4];
            float a[4] = {a4.x, a4.y, a4.z, a4.w};
            float w[4] = {w4.x, w4.y, w4.z, w4.w};
#pragma unroll
            for (int i = 0; i < 4; i++)
#pragma unroll
                for (int j = 0; j < 4; j++) acc[i][j] = fmaf(a[i], w[j], acc[i][j]);
        }
    }
#pragma unroll
    for (int i = 0; i < 4; i++) {
        int rr = r0 + ty * 4 + i;
#pragma unroll
        for (int j = 0; j < 4; j++) {
            int cc = n0 + tx * 4 + j;
            float v = acc[i][j] + bias[cc];
            if (doRelu) v = fmaxf(v, 0.0f);
            if (resid)  v += resid[(size_t)rr * N + cc];
            C[(size_t)rr * N + cc] = v;
        }
    }
}

// ---------------- gathered edge GEMM: 128x128 tile, TM=TN=8, double-buffered ----------------
// E[g, :] = edge_emb[rowIdx[g], :] @ We + be    for g < g_count.  K=N=256 fixed.
__global__ __launch_bounds__(256)
void gemm128_gather(const float* __restrict__ A, const float* __restrict__ W,
                    const float* __restrict__ bias) {
    __shared__ float As[2][16][132];
    __shared__ float Ws[2][16][128];
    __shared__ int   rsrc[128];
    int count = g_count;
    int r0 = blockIdx.x * 128;
    if (r0 >= count) return;
    int n0 = blockIdx.y * 128;
    int tid = threadIdx.x;
    int tx = tid & 15, ty = tid >> 4;

    if (tid < 128) {
        int g = r0 + tid;
        rsrc[tid] = g_rowIdx[g < count ? g : count - 1];
    }
    __syncthreads();

    // per-thread gather bases (2 float4 for A, 2 for W per k-block)
    int aRow0 = tid >> 2;                 // 0..63
    int aKq   = tid & 3;
    const float* aP0 = A + (size_t)rsrc[aRow0]      * 256 + aKq * 4;
    const float* aP1 = A + (size_t)rsrc[aRow0 + 64] * 256 + aKq * 4;
    int wKr = tid >> 5;                   // 0..7
    int wNq = tid & 31;
    const float* wP0 = W + (size_t)wKr * 256 + n0 + wNq * 4;
    const float* wP1 = wP0 + 8 * 256;

    float4 a0 = *(const float4*)(aP0);
    float4 a1 = *(const float4*)(aP1);
    float4 w0 = *(const float4*)(wP0);
    float4 w1 = *(const float4*)(wP1);

    float acc[8][8] = {};
    int buf = 0;

    // store helpers inlined
#define STORE_TILES(BUF)                                                     \
    do {                                                                     \
        As[BUF][aKq * 4 + 0][aRow0] = a0.x;                                  \
        As[BUF][aKq * 4 + 1][aRow0] = a0.y;                                  \
        As[BUF][aKq * 4 + 2][aRow0] = a0.z;                                  \
        As[BUF][aKq * 4 + 3][aRow0] = a0.w;                                  \
        As[BUF][aKq * 4 + 0][aRow0 + 64] = a1.x;                             \
        As[BUF][aKq * 4 + 1][aRow0 + 64] = a1.y;                             \
        As[BUF][aKq * 4 + 2][aRow0 + 64] = a1.z;                             \
        As[BUF][aKq * 4 + 3][aRow0 + 64] = a1.w;                             \
        *(float4*)&Ws[BUF][wKr][wNq * 4]     = w0;                           \
        *(float4*)&Ws[BUF][wKr + 8][wNq * 4] = w1;                           \
    } while (0)

    STORE_TILES(0);
    __syncthreads();

#pragma unroll 1
    for (int kb = 0; kb < 256; kb += 16) {
        int nxt = kb + 16;
        if (nxt < 256) {
            a0 = *(const float4*)(aP0 + nxt);
            a1 = *(const float4*)(aP1 + nxt);
            w0 = *(const float4*)(wP0 + (size_t)nxt * 256);
            w1 = *(const float4*)(wP1 + (size_t)nxt * 256);
        }
#pragma unroll
        for (int k = 0; k < 16; k++) {
            float4 av0 = *(const float4*)&As[buf][k][ty * 8];
            float4 av1 = *(const float4*)&As[buf][k][ty * 8 + 4];
            float4 wv0 = *(const float4*)&Ws[buf][k][tx * 8];
            float4 wv1 = *(const float4*)&Ws[buf][k][tx * 8 + 4];
            float a[8] = {av0.x, av0.y, av0.z, av0.w, av1.x, av1.y, av1.z, av1.w};
            float w[8] = {wv0.x, wv0.y, wv0.z, wv0.w, wv1.x, wv1.y, wv1.z, wv1.w};
#pragma unroll
            for (int i = 0; i < 8; i++)
#pragma unroll
                for (int j = 0; j < 8; j++) acc[i][j] = fmaf(a[i], w[j], acc[i][j]);
        }
        if (nxt < 256) {
            int nb = buf ^ 1;
            STORE_TILES(nb);
        }
        __syncthreads();
        buf ^= 1;
    }
#undef STORE_TILES

    float bi[8];
#pragma unroll
    for (int j = 0; j < 8; j++) bi[j] = bias[n0 + tx * 8 + j];
#pragma unroll
    for (int i = 0; i < 8; i++) {
        int g = r0 + ty * 8 + i;
        if (g < count) {
            float4 o0 = make_float4(acc[i][0] + bi[0], acc[i][1] + bi[1],
                                    acc[i][2] + bi[2], acc[i][3] + bi[3]);
            float4 o1 = make_float4(acc[i][4] + bi[4], acc[i][5] + bi[5],
                                    acc[i][6] + bi[6], acc[i][7] + bi[7]);
            *(float4*)&g_E[(size_t)g * 256 + n0 + tx * 8]     = o0;
            *(float4*)&g_E[(size_t)g * 256 + n0 + tx * 8 + 4] = o1;
        }
    }
}

// ---------------- attention: one CTA per (b,m), warp per head, lane per dk ----------------
__global__ __launch_bounds__(256)
void attn_kernel(const float* __restrict__ machine_emb,
                 const float* __restrict__ Wo, const float* __restrict__ bo) {
    __shared__ float sc[H_ * N_];   // 16 KB
    __shared__ int   mp[N_];
    __shared__ float ao[D_];
    int row = blockIdx.x;           // b*M + m
    int b = row >> 6;
    int tid = threadIdx.x, lane = tid & 31, h = tid >> 5;

    for (int n = tid; n < N_; n += 256) mp[n] = g_map[(size_t)row * N_ + n];
    __syncthreads();

    size_t base = (size_t)row * D_ + h * 32 + lane;
    float qv  = g_q[base];
    float ksv = g_ksf[base];
    float vsv = g_vsf[base];
    float sSelf = warpSum(qv * ksv) * SCALE_;

    const float* Kbase = g_k + (size_t)b * N_ * D_ + h * 32 + lane;
    const float* Vbase = g_v + (size_t)b * N_ * D_ + h * 32 + lane;
    float* scRow = &sc[h * N_];

    // pass 1: scores
#pragma unroll 4
    for (int n = 0; n < N_; n++) {
        int pos = mp[n];
        float tt = 0.0f;
        if (pos >= 0) {
            float e  = g_E[(size_t)pos * D_ + h * 32 + lane];
            float kv = Kbase[(size_t)n * D_];
            float qe = qv + e;
            float ke = kv + e;
            tt = qe * ke;
        }
        float s = warpSum(tt) * SCALE_;
        if (lane == 0) scRow[n] = (pos >= 0) ? s : NEG_INF;
    }
    __syncwarp();

    // softmax over [self, 512 cross]
    float mx = sSelf;
    for (int n = lane; n < N_; n += 32) mx = fmaxf(mx, scRow[n]);
    mx = warpMax(mx);
    float psum = 0.0f;
    for (int n = lane; n < N_; n += 32) {
        float p = __expf(scRow[n] - mx);
        scRow[n] = p;
        psum += p;
    }
    psum = warpSum(psum);
    float pSelf = __expf(sSelf - mx);
    float inv = 1.0f / (psum + pSelf);
    __syncwarp();

    // pass 2: weighted value accumulation
    float acc = pSelf * vsv;
#pragma unroll 4
    for (int n = 0; n < N_; n++) {
        int pos = mp[n];
        if (pos >= 0) {
            float p  = scRow[n];
            float e  = g_E[(size_t)pos * D_ + h * 32 + lane];
            float vv = Vbase[(size_t)n * D_];
            acc = fmaf(p, vv + e, acc);
        }
    }
    ao[h * 32 + lane] = acc * inv;
    __syncthreads();

    // output projection + residual
    float r = machine_emb[(size_t)row * D_ + tid] + bo[tid];
#pragma unroll 8
    for (int k = 0; k < D_; k++) r = fmaf(ao[k], Wo[(size_t)k * D_ + tid], r);
    g_me2[(size_t)row * D_ + tid] = r;
}

// ---------------- launch ----------------
static float* symAddr(const void* sym) {
    void* p = nullptr;
    cudaGetSymbolAddress(&p, sym);
    return (float*)p;
}

extern "C" void kernel_launch(void* const* d_in, const int* in_sizes, int n_in,
                              void* d_out, int out_size) {
    const float* machine_emb = (const float*)d_in[0];
    const float* op_emb      = (const float*)d_in[1];
    const float* edge_emb    = (const float*)d_in[2];
    const void*  mask        = d_in[3];
    const float* Wq  = (const float*)d_in[4];
    const float* bq  = (const float*)d_in[5];
    const float* Wk  = (const float*)d_in[6];
    const float* bk  = (const float*)d_in[7];
    const float* Wv  = (const float*)d_in[8];
    const float* bv  = (const float*)d_in[9];
    const float* Wo  = (const float*)d_in[10];
    const float* bo  = (const float*)d_in[11];
    const float* Wks = (const float*)d_in[12];
    const float* bks = (const float*)d_in[13];
    const float* Wvs = (const float*)d_in[14];
    const float* bvs = (const float*)d_in[15];
    const float* We  = (const float*)d_in[16];
    const float* be  = (const float*)d_in[17];
    const float* g1  = (const float*)d_in[18];
    const float* bn1 = (const float*)d_in[19];
    const float* g2  = (const float*)d_in[20];
    const float* bn2 = (const float*)d_in[21];
    const float* gop = (const float*)d_in[22];
    const float* bnop= (const float*)d_in[23];
    const float* Wf1 = (const float*)d_in[24];
    const float* bf1 = (const float*)d_in[25];
    const float* Wf2 = (const float*)d_in[26];
    const float* bf2 = (const float*)d_in[27];
    float* out = (float*)d_out;

    float* p_mnorm = symAddr(g_mnorm);
    float* p_onorm = symAddr(g_onorm);
    float* p_q     = symAddr(g_q);
    float* p_ks    = symAddr(g_ksf);
    float* p_vs    = symAddr(g_vsf);
    float* p_k     = symAddr(g_k);
    float* p_v     = symAddr(g_v);
    float* p_me2   = symAddr(g_me2);
    float* p_h     = symAddr(g_hbuf);
    float* p_f1    = symAddr(g_f1);

    // mask preprocessing + compaction
    zero_kernel<<<1, 1>>>();
    detect_kernel<<<1, 256>>>((const unsigned char*)mask, in_sizes[3]);
    compact_kernel<<<NEDGE / 256, 256>>>(mask);

    // layernorms
    ln_kernel<<<ROWS_M, 256>>>(machine_emb, g1, bn1, p_mnorm);
    ln_kernel<<<ROWS_O, 256>>>(op_emb, gop, bnop, p_onorm);

    // machine-side projections (rows=256, K=N=256)
    dim3 gS(ROWS_M / 64, D_ / 64);
    gemm64<<<gS, 256>>>(p_mnorm, Wq,  bq,  nullptr, p_q,  D_, D_, 0);
    gemm64<<<gS, 256>>>(p_mnorm, Wks, bks, nullptr, p_ks, D_, D_, 0);
    gemm64<<<gS, 256>>>(p_mnorm, Wvs, bvs, nullptr, p_vs, D_, D_, 0);

    // op-side projections (rows=2048)
    dim3 gO(ROWS_O / 64, D_ / 64);
    gemm64<<<gO, 256>>>(p_onorm, Wk, bk, nullptr, p_k, D_, D_, 0);
    gemm64<<<gO, 256>>>(p_onorm, Wv, bv, nullptr, p_v, D_, D_, 0);

    // gathered edge projection (only active mask rows)
    dim3 gE(NEDGE / 128, D_ / 128);
    gemm128_gather<<<gE, 256>>>(edge_emb, We, be);

    // fused attention + output projection + residual
    attn_kernel<<<ROWS_M, 256>>>(machine_emb, Wo, bo);

    // FFN: LN2 -> relu(h@Wf1+bf1)@Wf2+bf2 + me2
    ln_kernel<<<ROWS_M, 256>>>(p_me2, g2, bn2, p_h);
    dim3 gF1(ROWS_M / 64, F_ / 64);
    gemm64<<<gF1, 256>>>(p_h, Wf1, bf1, nullptr, p_f1, D_, F_, 1);
    dim3 gF2(ROWS_M / 64, D_ / 64);
    gemm64<<<gF2, 256>>>(p_f1, Wf2, bf2, p_me2, out, F_, D_, 0);
}

// round 3
// speedup vs baseline: 2.4702x; 2.4702x over previous
#include <cuda_runtime.h>
#include <cstdint>

// ---------------- problem constants ----------------
#define D_      256
#define B_      4
#define M_      64
#define N_      512
#define H_      8
#define F_      1024
#define ROWS_M  256        // B*M
#define ROWS_O  2048       // B*N
#define NEDGE   131072     // B*N*M
#define SCALE_  0.17677669529663687f   // 1/sqrt(32)
#define EPS_    1e-5f

#define FLAG_RELU   1
#define FLAG_GATHER 2

// ---------------- scratch (device globals; no runtime allocation) ----------------
__device__ float g_mnorm[ROWS_M * D_];
__device__ float g_onorm[ROWS_O * D_];
__device__ float g_q   [ROWS_M * D_];
__device__ float g_ksf [ROWS_M * D_];
__device__ float g_vsf [ROWS_M * D_];
__device__ float g_k   [ROWS_O * D_];
__device__ float g_v   [ROWS_O * D_];
__device__ float g_E   [(size_t)NEDGE * D_];   // compacted projected edges
__device__ float g_me2 [ROWS_M * D_];
__device__ float g_hbuf[ROWS_M * D_];
__device__ float g_f1  [ROWS_M * F_];
__device__ int   g_actN[ROWS_M * N_];          // per-row active n list (sorted)
__device__ int   g_actCnt[ROWS_M];
__device__ int   g_rowStart[ROWS_M + 1];       // exclusive prefix of counts
__device__ int   g_rowIdx[NEDGE];              // compact -> edge linear index
__device__ int   g_count;
__device__ int   g_flagGt1, g_flagNz;

// ---------------- helpers ----------------
__device__ __forceinline__ float warpSum(float v) {
#pragma unroll
    for (int o = 16; o; o >>= 1) v += __shfl_xor_sync(0xffffffffu, v, o);
    return v;
}
__device__ __forceinline__ float warpMax(float v) {
#pragma unroll
    for (int o = 16; o; o >>= 1) v = fmaxf(v, __shfl_xor_sync(0xffffffffu, v, o));
    return v;
}
__device__ __forceinline__ unsigned f2tf(float x) {
    unsigned r;
    asm("cvt.rna.tf32.f32 %0, %1;" : "=r"(r) : "f"(x));
    return r;
}

// ---------------- mask preprocessing ----------------
__global__ void zero_kernel() { g_flagGt1 = 0; g_flagNz = 0; }

// Detect mask storage dtype from byte patterns (scan nbytes — safe for all dtypes).
__global__ void detect_kernel(const unsigned char* __restrict__ p, int nbytes) {
    int i = blockIdx.x * blockDim.x + threadIdx.x;
    int stride = gridDim.x * blockDim.x;
    int gt1 = 0, nz = 0;
    for (; i < nbytes; i += stride) {
        unsigned char v = p[i];
        gt1 |= (v > 1);
        nz  |= (v != 0 && (i & 3) != 0);
    }
    if (__any_sync(0xffffffffu, gt1) && (threadIdx.x & 31) == 0) atomicOr(&g_flagGt1, 1);
    if (__any_sync(0xffffffffu, nz)  && (threadIdx.x & 31) == 0) atomicOr(&g_flagNz, 1);
}

// Build per-row (b,m) sorted active-n lists deterministically (ballot scan).
__global__ void actlist_kernel(const void* __restrict__ mask) {
    int wid = threadIdx.x >> 5, lane = threadIdx.x & 31;
    int row = blockIdx.x * 8 + wid;            // grid 32, 8 warps each
    int b = row >> 6, m = row & 63;
    int mode = g_flagGt1 ? 2 : (g_flagNz ? 1 : 0);
    int base = 0;
#pragma unroll 1
    for (int c = 0; c < 16; c++) {
        int n = c * 32 + lane;
        size_t mi = ((size_t)(b * N_ + n)) * M_ + m;
        bool a;
        if (mode == 2)      a = ((const float*)mask)[mi] != 0.0f;
        else if (mode == 1) a = ((const unsigned char*)mask)[mi] != 0;
        else                a = ((const int*)mask)[mi] != 0;
        unsigned bal = __ballot_sync(0xffffffffu, a);
        if (a) g_actN[row * N_ + base + __popc(bal & ((1u << lane) - 1u))] = n;
        base += __popc(bal);
    }
    if (lane == 0) g_actCnt[row] = base;
}

// Exclusive prefix over 256 row counts.
__global__ void prefix_kernel() {
    __shared__ int ws[8];
    int tid = threadIdx.x;
    int v = g_actCnt[tid];
    int lane = tid & 31, w = tid >> 5;
    int inc = v;
#pragma unroll
    for (int o = 1; o < 32; o <<= 1) {
        int t = __shfl_up_sync(0xffffffffu, inc, o);
        if (lane >= o) inc += t;
    }
    if (lane == 31) ws[w] = inc;
    __syncthreads();
    int add = 0;
#pragma unroll
    for (int i = 0; i < 8; i++) if (i < w) add += ws[i];
    int excl = inc - v + add;
    g_rowStart[tid] = excl;
    if (tid == 255) { g_rowStart[256] = excl + v; g_count = excl + v; }
}

// Compact -> edge-linear-index table for the gathered GEMM.
__global__ void fill_kernel() {
    int row = blockIdx.x;
    int cnt = g_actCnt[row];
    int tid = threadIdx.x;
    if (tid < cnt) {
        int n = g_actN[row * N_ + tid];
        int b = row >> 6, m = row & 63;
        g_rowIdx[g_rowStart[row] + tid] = (b * N_ + n) * M_ + m;
    }
}

// ---------------- layernorm (one CTA per row of 256) ----------------
__global__ void ln_kernel(const float* __restrict__ x, const float* __restrict__ g,
                          const float* __restrict__ beta, float* __restrict__ y) {
    __shared__ float red[16];
    int row = blockIdx.x;
    int tid = threadIdx.x;
    float v = x[(size_t)row * D_ + tid];
    float s  = warpSum(v);
    float s2 = warpSum(v * v);
    if ((tid & 31) == 0) { red[tid >> 5] = s; red[8 + (tid >> 5)] = s2; }
    __syncthreads();
    float sum = 0.f, sum2 = 0.f;
#pragma unroll
    for (int i = 0; i < 8; i++) { sum += red[i]; sum2 += red[8 + i]; }
    float mu  = sum * (1.0f / D_);
    float var = sum2 * (1.0f / D_) - mu * mu;
    float inv = rsqrtf(var + EPS_);
    y[(size_t)row * D_ + tid] = (v - mu) * inv * g[tid] + beta[tid];
}

// ---------------- tf32 tensor-core GEMM: 128x128 tile, 8 warps (32x64 warp tile) ----
// C[r,n] = act( sum_k A[src(r),k] * W[k,n] + bias[n] ) (+ resid[r,n])
// K multiple of 16, N multiple of 128. Gather mode: rows = g_count, src = g_rowIdx.
__global__ __launch_bounds__(256)
void gemm_tf32(const float* __restrict__ A, const float* __restrict__ W,
               const float* __restrict__ bias, const float* __restrict__ resid,
               float* __restrict__ C, int K, int N, int flags) {
    __shared__ unsigned As[2][128][20];   // [buf][m][k] pad->conflict-free frag loads
    __shared__ unsigned Bs[2][16][136];   // [buf][k][n] pad 8
    __shared__ int src[128];

    int tid = threadIdx.x;
    int count = 0x7fffffff;
    int r0 = blockIdx.x * 128;
    if (flags & FLAG_GATHER) {
        count = g_count;
        if (r0 >= count) return;
        if (tid < 128) {
            int gidx = r0 + tid;
            src[tid] = g_rowIdx[gidx < count ? gidx : count - 1];
        }
    } else {
        if (tid < 128) src[tid] = r0 + tid;
    }
    __syncthreads();
    int n0 = blockIdx.y * 128;

    int aRow = tid >> 1, aHalf = tid & 1;             // 2 float4 of A per thread
    const float* aPtr = A + (size_t)src[aRow] * K + aHalf * 8;
    int bK = tid >> 5, bN4 = tid & 31;                // 2 float4 of W per thread
    const float* bPtr = W + (size_t)bK * N + n0 + bN4 * 4;

    float4 a0 = *(const float4*)(aPtr);
    float4 a1 = *(const float4*)(aPtr + 4);
    float4 b0 = *(const float4*)(bPtr);
    float4 b1 = *(const float4*)(bPtr + (size_t)8 * N);

    float acc[2][8][4];
#pragma unroll
    for (int i = 0; i < 2; i++)
#pragma unroll
        for (int j = 0; j < 8; j++)
#pragma unroll
            for (int l = 0; l < 4; l++) acc[i][j][l] = 0.0f;

    int wid = tid >> 5, lane = tid & 31;
    int wm = wid & 3, wn = wid >> 2;
    int gid = lane >> 2, tig = lane & 3;
    int buf = 0;

#define STORE_TILES(BF)                                                          \
    do {                                                                         \
        uint4 ua0 = make_uint4(f2tf(a0.x), f2tf(a0.y), f2tf(a0.z), f2tf(a0.w));  \
        uint4 ua1 = make_uint4(f2tf(a1.x), f2tf(a1.y), f2tf(a1.z), f2tf(a1.w));  \
        uint4 ub0 = make_uint4(f2tf(b0.x), f2tf(b0.y), f2tf(b0.z), f2tf(b0.w));  \
        uint4 ub1 = make_uint4(f2tf(b1.x), f2tf(b1.y), f2tf(b1.z), f2tf(b1.w));  \
        *(uint4*)&As[BF][aRow][aHalf * 8]     = ua0;                             \
        *(uint4*)&As[BF][aRow][aHalf * 8 + 4] = ua1;                             \
        *(uint4*)&Bs[BF][bK][bN4 * 4]         = ub0;                             \
        *(uint4*)&Bs[BF][bK + 8][bN4 * 4]     = ub1;                             \
    } while (0)

    STORE_TILES(0);
    __syncthreads();

#pragma unroll 1
    for (int kb = 0; kb < K; kb += 16) {
        int nxt = kb + 16;
        if (nxt < K) {
            a0 = *(const float4*)(aPtr + nxt);
            a1 = *(const float4*)(aPtr + nxt + 4);
            b0 = *(const float4*)(bPtr + (size_t)nxt * N);
            b1 = *(const float4*)(bPtr + (size_t)(nxt + 8) * N);
        }
#pragma unroll
        for (int s = 0; s < 2; s++) {
            int ks = s * 8;
            unsigned af[2][4];
#pragma unroll
            for (int mf = 0; mf < 2; mf++) {
                int mr = wm * 32 + mf * 16 + gid;
                af[mf][0] = As[buf][mr][ks + tig];
                af[mf][1] = As[buf][mr + 8][ks + tig];
                af[mf][2] = As[buf][mr][ks + tig + 4];
                af[mf][3] = As[buf][mr + 8][ks + tig + 4];
            }
#pragma unroll
            for (int nf = 0; nf < 8; nf++) {
                int nc = wn * 64 + nf * 8 + gid;
                unsigned bf0 = Bs[buf][ks + tig][nc];
                unsigned bf1 = Bs[buf][ks + tig + 4][nc];
#pragma unroll
                for (int mf = 0; mf < 2; mf++) {
                    asm volatile(
                        "mma.sync.aligned.m16n8k8.row.col.f32.tf32.tf32.f32 "
                        "{%0,%1,%2,%3},{%4,%5,%6,%7},{%8,%9},{%0,%1,%2,%3};"
                        : "+f"(acc[mf][nf][0]), "+f"(acc[mf][nf][1]),
                          "+f"(acc[mf][nf][2]), "+f"(acc[mf][nf][3])
                        : "r"(af[mf][0]), "r"(af[mf][1]), "r"(af[mf][2]), "r"(af[mf][3]),
                          "r"(bf0), "r"(bf1));
                }
            }
        }
        if (nxt < K) STORE_TILES(buf ^ 1);
        __syncthreads();
        buf ^= 1;
    }
#undef STORE_TILES

    // epilogue: c0: (gid, 2*tig) c1: (gid, 2*tig+1) c2: (gid+8, ...) c3: ...
#pragma unroll
    for (int mf = 0; mf < 2; mf++) {
#pragma unroll
        for (int half = 0; half < 2; half++) {
            int r = r0 + wm * 32 + mf * 16 + gid + half * 8;
            bool rok = r < count;
#pragma unroll
            for (int nf = 0; nf < 8; nf++) {
                int cb = n0 + wn * 64 + nf * 8 + tig * 2;
                float v0 = acc[mf][nf][half * 2 + 0] + bias[cb];
                float v1 = acc[mf][nf][half * 2 + 1] + bias[cb + 1];
                if (flags & FLAG_RELU) { v0 = fmaxf(v0, 0.f); v1 = fmaxf(v1, 0.f); }
                if (rok) {
                    if (resid) {
                        v0 += resid[(size_t)r * N + cb];
                        v1 += resid[(size_t)r * N + cb + 1];
                    }
                    C[(size_t)r * N + cb]     = v0;
                    C[(size_t)r * N + cb + 1] = v1;
                }
            }
        }
    }
}

// ---------------- attention: CTA per (b,m), warp per head, active-only ----------------
// lanes split into 4 groups of 8; each group handles one n, float4 per lane over dk=32.
__global__ __launch_bounds__(256)
void attn_kernel(const float* __restrict__ machine_emb,
                 const float* __restrict__ Wo, const float* __restrict__ bo) {
    __shared__ float sc[H_][N_];   // 16 KB
    __shared__ float ao[D_];
    __shared__ int   sn[N_];
    int row = blockIdx.x;          // b*M + m
    int b = row >> 6;
    int tid = threadIdx.x, lane = tid & 31, h = tid >> 5;
    int cnt = g_actCnt[row];
    int start = g_rowStart[row];

    for (int i = tid; i < cnt; i += 256) sn[i] = g_actN[row * N_ + i];
    __syncthreads();

    int g = lane >> 3, d8 = lane & 7;
    float4 q4  = ((const float4*)(g_q   + (size_t)row * D_ + h * 32))[d8];
    float4 ks4 = ((const float4*)(g_ksf + (size_t)row * D_ + h * 32))[d8];
    float4 vs4 = ((const float4*)(g_vsf + (size_t)row * D_ + h * 32))[d8];

    float sSelf = q4.x * ks4.x + q4.y * ks4.y + q4.z * ks4.z + q4.w * ks4.w;
#pragma unroll
    for (int o = 1; o < 8; o <<= 1) sSelf += __shfl_xor_sync(0xffffffffu, sSelf, o);
    sSelf *= SCALE_;

    const float* Eb = g_E + (size_t)start * D_ + h * 32;
    const float* Kb = g_k + (size_t)b * N_ * D_ + h * 32;
    const float* Vb = g_v + (size_t)b * N_ * D_ + h * 32;

    // pass 1: scores over active n only
#pragma unroll 2
    for (int j0 = 0; j0 < cnt; j0 += 4) {
        int j = j0 + g;
        bool ok = j < cnt;
        float t = 0.0f;
        if (ok) {
            float4 e4 = *(const float4*)(Eb + (size_t)j * D_ + d8 * 4);
            int n = sn[j];
            float4 k4 = *(const float4*)(Kb + (size_t)n * D_ + d8 * 4);
            t = (q4.x + e4.x) * (k4.x + e4.x) + (q4.y + e4.y) * (k4.y + e4.y)
              + (q4.z + e4.z) * (k4.z + e4.z) + (q4.w + e4.w) * (k4.w + e4.w);
        }
#pragma unroll
        for (int o = 1; o < 8; o <<= 1) t += __shfl_xor_sync(0xffffffffu, t, o);
        if (ok && d8 == 0) sc[h][j] = t * SCALE_;
    }
    __syncwarp();

    // softmax over [self, active]
    float mx = sSelf;
    for (int i = lane; i < cnt; i += 32) mx = fmaxf(mx, sc[h][i]);
    mx = warpMax(mx);
    float ps = 0.0f;
    for (int i = lane; i < cnt; i += 32) {
        float p = __expf(sc[h][i] - mx);
        sc[h][i] = p;
        ps += p;
    }
    ps = warpSum(ps);
    float pSelf = __expf(sSelf - mx);
    float inv = 1.0f / (ps + pSelf);
    __syncwarp();

    // pass 2: weighted values
    float4 acc = make_float4(0.f, 0.f, 0.f, 0.f);
    if (g == 0) {
        acc.x = pSelf * vs4.x; acc.y = pSelf * vs4.y;
        acc.z = pSelf * vs4.z; acc.w = pSelf * vs4.w;
    }
#pragma unroll 2
    for (int j0 = 0; j0 < cnt; j0 += 4) {
        int j = j0 + g;
        if (j < cnt) {
            float p = sc[h][j];
            float4 e4 = *(const float4*)(Eb + (size_t)j * D_ + d8 * 4);
            int n = sn[j];
            float4 v4 = *(const float4*)(Vb + (size_t)n * D_ + d8 * 4);
            acc.x = fmaf(p, v4.x + e4.x, acc.x);
            acc.y = fmaf(p, v4.y + e4.y, acc.y);
            acc.z = fmaf(p, v4.z + e4.z, acc.z);
            acc.w = fmaf(p, v4.w + e4.w, acc.w);
        }
    }
#pragma unroll
    for (int o = 8; o < 32; o <<= 1) {
        acc.x += __shfl_xor_sync(0xffffffffu, acc.x, o);
        acc.y += __shfl_xor_sync(0xffffffffu, acc.y, o);
        acc.z += __shfl_xor_sync(0xffffffffu, acc.z, o);
        acc.w += __shfl_xor_sync(0xffffffffu, acc.w, o);
    }
    if (g == 0) {
        float4 r = make_float4(acc.x * inv, acc.y * inv, acc.z * inv, acc.w * inv);
        *(float4*)(ao + h * 32 + d8 * 4) = r;
    }
    __syncthreads();

    // output projection + residual
    float r = machine_emb[(size_t)row * D_ + tid] + bo[tid];
#pragma unroll 8
    for (int k = 0; k < D_; k++) r = fmaf(ao[k], Wo[(size_t)k * D_ + tid], r);
    g_me2[(size_t)row * D_ + tid] = r;
}

// ---------------- launch ----------------
static float* symAddr(const void* sym) {
    void* p = nullptr;
    cudaGetSymbolAddress(&p, sym);
    return (float*)p;
}

extern "C" void kernel_launch(void* const* d_in, const int* in_sizes, int n_in,
                              void* d_out, int out_size) {
    const float* machine_emb = (const float*)d_in[0];
    const float* op_emb      = (const float*)d_in[1];
    const float* edge_emb    = (const float*)d_in[2];
    const void*  mask        = d_in[3];
    const float* Wq  = (const float*)d_in[4];
    const float* bq  = (const float*)d_in[5];
    const float* Wk  = (const float*)d_in[6];
    const float* bk  = (const float*)d_in[7];
    const float* Wv  = (const float*)d_in[8];
    const float* bv  = (const float*)d_in[9];
    const float* Wo  = (const float*)d_in[10];
    const float* bo  = (const float*)d_in[11];
    const float* Wks = (const float*)d_in[12];
    const float* bks = (const float*)d_in[13];
    const float* Wvs = (const float*)d_in[14];
    const float* bvs = (const float*)d_in[15];
    const float* We  = (const float*)d_in[16];
    const float* be  = (const float*)d_in[17];
    const float* g1  = (const float*)d_in[18];
    const float* bn1 = (const float*)d_in[19];
    const float* g2  = (const float*)d_in[20];
    const float* bn2 = (const float*)d_in[21];
    const float* gop = (const float*)d_in[22];
    const float* bnop= (const float*)d_in[23];
    const float* Wf1 = (const float*)d_in[24];
    const float* bf1 = (const float*)d_in[25];
    const float* Wf2 = (const float*)d_in[26];
    const float* bf2 = (const float*)d_in[27];
    float* out = (float*)d_out;

    float* p_mnorm = symAddr(g_mnorm);
    float* p_onorm = symAddr(g_onorm);
    float* p_q     = symAddr(g_q);
    float* p_ks    = symAddr(g_ksf);
    float* p_vs    = symAddr(g_vsf);
    float* p_k     = symAddr(g_k);
    float* p_v     = symAddr(g_v);
    float* p_E     = symAddr(g_E);
    float* p_me2   = symAddr(g_me2);
    float* p_h     = symAddr(g_hbuf);
    float* p_f1    = symAddr(g_f1);

    // mask preprocessing + deterministic compaction
    zero_kernel<<<1, 1>>>();
    detect_kernel<<<256, 256>>>((const unsigned char*)mask, in_sizes[3]);
    actlist_kernel<<<32, 256>>>(mask);
    prefix_kernel<<<1, 256>>>();
    fill_kernel<<<ROWS_M, 512>>>();

    // layernorms
    ln_kernel<<<ROWS_M, 256>>>(machine_emb, g1, bn1, p_mnorm);
    ln_kernel<<<ROWS_O, 256>>>(op_emb, gop, bnop, p_onorm);

    // machine-side projections (rows=256)
    dim3 gS(ROWS_M / 128, D_ / 128);
    gemm_tf32<<<gS, 256>>>(p_mnorm, Wq,  bq,  nullptr, p_q,  D_, D_, 0);
    gemm_tf32<<<gS, 256>>>(p_mnorm, Wks, bks, nullptr, p_ks, D_, D_, 0);
    gemm_tf32<<<gS, 256>>>(p_mnorm, Wvs, bvs, nullptr, p_vs, D_, D_, 0);

    // op-side projections (rows=2048)
    dim3 gO(ROWS_O / 128, D_ / 128);
    gemm_tf32<<<gO, 256>>>(p_onorm, Wk, bk, nullptr, p_k, D_, D_, 0);
    gemm_tf32<<<gO, 256>>>(p_onorm, Wv, bv, nullptr, p_v, D_, D_, 0);

    // gathered edge projection (active rows only; inactive tiles exit early)
    dim3 gE(NEDGE / 128, D_ / 128);
    gemm_tf32<<<gE, 256>>>(edge_emb, We, be, nullptr, p_E, D_, D_, FLAG_GATHER);

    // fused attention + output projection + residual
    attn_kernel<<<ROWS_M, 256>>>(machine_emb, Wo, bo);

    // FFN: LN2 -> relu(h@Wf1+bf1)@Wf2+bf2 + me2
    ln_kernel<<<ROWS_M, 256>>>(p_me2, g2, bn2, p_h);
    dim3 gF1(ROWS_M / 128, F_ / 128);
    gemm_tf32<<<gF1, 256>>>(p_h, Wf1, bf1, nullptr, p_f1, D_, F_, FLAG_RELU);
    dim3 gF2(ROWS_M / 128, D_ / 128);
    gemm_tf32<<<gF2, 256>>>(p_f1, Wf2, bf2, p_me2, out, F_, D_, 0);
}

// round 4
// speedup vs baseline: 3.9890x; 1.6149x over previous
#include <cuda_runtime.h>
#include <cstdint>

// ---------------- problem constants ----------------
#define D_      256
#define B_      4
#define M_      64
#define N_      512
#define H_      8
#define F_      1024
#define ROWS_M  256        // B*M
#define ROWS_O  2048       // B*N
#define NEDGE   131072     // B*N*M
#define SCALE_  0.17677669529663687f   // 1/sqrt(32)
#define EPS_    1e-5f

#define FLAG_RELU   1
#define FLAG_GATHER 2
#define FLAG_SPLIT  4

// ---------------- scratch (device globals; no runtime allocation) ----------------
__device__ float g_mnorm[ROWS_M * D_];
__device__ float g_onorm[ROWS_O * D_];
__device__ float g_Wqkv[D_ * 768];
__device__ float g_bqkv[768];
__device__ float g_Wkv [D_ * 512];
__device__ float g_bkv [512];
__device__ float g_qkv [ROWS_M * 768];        // cols: 0:256 q | 256:512 ks | 512:768 vs
__device__ float g_kv  [ROWS_O * 512];        // cols: 0:256 k | 256:512 v
__device__ float g_E   [(size_t)NEDGE * D_];  // compacted projected edges
__device__ float g_me2 [ROWS_M * D_];
__device__ float g_hbuf[ROWS_M * D_];
__device__ float g_f1  [ROWS_M * F_];
__device__ float g_f2part[4 * ROWS_M * D_];
__device__ int   g_actN[ROWS_M * N_];
__device__ int   g_actCnt[ROWS_M];
__device__ int   g_rowStart[ROWS_M + 1];
__device__ int   g_rowIdx[NEDGE];
__device__ int   g_count;
__device__ int   g_flagGt1, g_flagNz;

// ---------------- helpers ----------------
__device__ __forceinline__ float warpSum(float v) {
#pragma unroll
    for (int o = 16; o; o >>= 1) v += __shfl_xor_sync(0xffffffffu, v, o);
    return v;
}
__device__ __forceinline__ float warpMax(float v) {
#pragma unroll
    for (int o = 16; o; o >>= 1) v = fmaxf(v, __shfl_xor_sync(0xffffffffu, v, o));
    return v;
}
__device__ __forceinline__ unsigned f2tf(float x) {
    unsigned r;
    asm("cvt.rna.tf32.f32 %0, %1;" : "=r"(r) : "f"(x));
    return r;
}

// ---------------- mask preprocessing ----------------
__global__ void zero_kernel() { g_flagGt1 = 0; g_flagNz = 0; }

__global__ void detect_kernel(const unsigned char* __restrict__ p, int nbytes) {
    int i = blockIdx.x * blockDim.x + threadIdx.x;
    int stride = gridDim.x * blockDim.x;
    int gt1 = 0, nz = 0;
    for (; i < nbytes; i += stride) {
        unsigned char v = p[i];
        gt1 |= (v > 1);
        nz  |= (v != 0 && (i & 3) != 0);
    }
    if (__any_sync(0xffffffffu, gt1) && (threadIdx.x & 31) == 0) atomicOr(&g_flagGt1, 1);
    if (__any_sync(0xffffffffu, nz)  && (threadIdx.x & 31) == 0) atomicOr(&g_flagNz, 1);
}

__global__ void actlist_kernel(const void* __restrict__ mask) {
    int wid = threadIdx.x >> 5, lane = threadIdx.x & 31;
    int row = blockIdx.x * 8 + wid;
    int b = row >> 6, m = row & 63;
    int mode = g_flagGt1 ? 2 : (g_flagNz ? 1 : 0);
    int base = 0;
#pragma unroll 1
    for (int c = 0; c < 16; c++) {
        int n = c * 32 + lane;
        size_t mi = ((size_t)(b * N_ + n)) * M_ + m;
        bool a;
        if (mode == 2)      a = ((const float*)mask)[mi] != 0.0f;
        else if (mode == 1) a = ((const unsigned char*)mask)[mi] != 0;
        else                a = ((const int*)mask)[mi] != 0;
        unsigned bal = __ballot_sync(0xffffffffu, a);
        if (a) g_actN[row * N_ + base + __popc(bal & ((1u << lane) - 1u))] = n;
        base += __popc(bal);
    }
    if (lane == 0) g_actCnt[row] = base;
}

__global__ void prefix_kernel() {
    __shared__ int ws[8];
    int tid = threadIdx.x;
    int v = g_actCnt[tid];
    int lane = tid & 31, w = tid >> 5;
    int inc = v;
#pragma unroll
    for (int o = 1; o < 32; o <<= 1) {
        int t = __shfl_up_sync(0xffffffffu, inc, o);
        if (lane >= o) inc += t;
    }
    if (lane == 31) ws[w] = inc;
    __syncthreads();
    int add = 0;
#pragma unroll
    for (int i = 0; i < 8; i++) if (i < w) add += ws[i];
    int excl = inc - v + add;
    g_rowStart[tid] = excl;
    if (tid == 255) { g_rowStart[256] = excl + v; g_count = excl + v; }
}

__global__ void fill_kernel() {
    int row = blockIdx.x;
    int cnt = g_actCnt[row];
    int tid = threadIdx.x;
    if (tid < cnt) {
        int n = g_actN[row * N_ + tid];
        int b = row >> 6, m = row & 63;
        g_rowIdx[g_rowStart[row] + tid] = (b * N_ + n) * M_ + m;
    }
}

// ---------------- weight packing: Wq|Wks|Wvs -> g_Wqkv, Wk|Wv -> g_Wkv ----------------
__global__ void pack_kernel(const float* __restrict__ Wq,  const float* __restrict__ bq,
                            const float* __restrict__ Wks, const float* __restrict__ bks,
                            const float* __restrict__ Wvs, const float* __restrict__ bvs,
                            const float* __restrict__ Wk,  const float* __restrict__ bk,
                            const float* __restrict__ Wv,  const float* __restrict__ bv) {
    int stride = gridDim.x * blockDim.x;
    int i0 = blockIdx.x * blockDim.x + threadIdx.x;
    for (int i = i0; i < D_ * 768; i += stride) {
        int k = i / 768, c = i % 768;
        float v = (c < 256) ? Wq[k * 256 + c]
                : (c < 512) ? Wks[k * 256 + c - 256]
                            : Wvs[k * 256 + c - 512];
        g_Wqkv[i] = v;
    }
    for (int i = i0; i < D_ * 512; i += stride) {
        int k = i / 512, c = i % 512;
        g_Wkv[i] = (c < 256) ? Wk[k * 256 + c] : Wv[k * 256 + c - 256];
    }
    if (i0 < 768)
        g_bqkv[i0] = (i0 < 256) ? bq[i0] : (i0 < 512) ? bks[i0 - 256] : bvs[i0 - 512];
    if (i0 < 512)
        g_bkv[i0] = (i0 < 256) ? bk[i0] : bv[i0 - 256];
}

// ---------------- layernorm ----------------
__global__ void ln_kernel(const float* __restrict__ x, const float* __restrict__ g,
                          const float* __restrict__ beta, float* __restrict__ y) {
    __shared__ float red[16];
    int row = blockIdx.x;
    int tid = threadIdx.x;
    float v = x[(size_t)row * D_ + tid];
    float s  = warpSum(v);
    float s2 = warpSum(v * v);
    if ((tid & 31) == 0) { red[tid >> 5] = s; red[8 + (tid >> 5)] = s2; }
    __syncthreads();
    float sum = 0.f, sum2 = 0.f;
#pragma unroll
    for (int i = 0; i < 8; i++) { sum += red[i]; sum2 += red[8 + i]; }
    float mu  = sum * (1.0f / D_);
    float var = sum2 * (1.0f / D_) - mu * mu;
    float inv = rsqrtf(var + EPS_);
    y[(size_t)row * D_ + tid] = (v - mu) * inv * g[tid] + beta[tid];
}

// ---------------- tf32 tensor-core GEMM: 128x128 tile, 8 warps ----------------
// kChunk: k-range per z-slice (== K for non-split). partStride: output offset per z.
__global__ __launch_bounds__(256)
void gemm_tf32(const float* __restrict__ A, const float* __restrict__ W,
               const float* __restrict__ bias, const float* __restrict__ resid,
               float* __restrict__ C, int K, int N, int kChunk, int partStride,
               int flags) {
    __shared__ unsigned As[2][128][20];
    __shared__ unsigned Bs[2][16][136];
    __shared__ int src[128];

    int tid = threadIdx.x;
    int count = 0x7fffffff;
    int r0 = blockIdx.x * 128;
    if (flags & FLAG_GATHER) {
        count = g_count;
        if (r0 >= count) return;
        if (tid < 128) {
            int gidx = r0 + tid;
            src[tid] = g_rowIdx[gidx < count ? gidx : count - 1];
        }
    } else {
        if (tid < 128) src[tid] = r0 + tid;
    }
    __syncthreads();
    int n0 = blockIdx.y * 128;
    int kb0 = blockIdx.z * kChunk;
    int kb1 = kb0 + kChunk;
    float* Cout = C + (size_t)blockIdx.z * partStride;

    int aRow = tid >> 1, aHalf = tid & 1;
    const float* aPtr = A + (size_t)src[aRow] * K + kb0 + aHalf * 8;
    int bK = tid >> 5, bN4 = tid & 31;
    const float* bPtr = W + (size_t)(kb0 + bK) * N + n0 + bN4 * 4;

    float4 a0 = *(const float4*)(aPtr);
    float4 a1 = *(const float4*)(aPtr + 4);
    float4 b0 = *(const float4*)(bPtr);
    float4 b1 = *(const float4*)(bPtr + (size_t)8 * N);

    float acc[2][8][4];
#pragma unroll
    for (int i = 0; i < 2; i++)
#pragma unroll
        for (int j = 0; j < 8; j++)
#pragma unroll
            for (int l = 0; l < 4; l++) acc[i][j][l] = 0.0f;

    int wid = tid >> 5, lane = tid & 31;
    int wm = wid & 3, wn = wid >> 2;
    int gid = lane >> 2, tig = lane & 3;
    int buf = 0;

#define STORE_TILES(BF)                                                          \
    do {                                                                         \
        uint4 ua0 = make_uint4(f2tf(a0.x), f2tf(a0.y), f2tf(a0.z), f2tf(a0.w));  \
        uint4 ua1 = make_uint4(f2tf(a1.x), f2tf(a1.y), f2tf(a1.z), f2tf(a1.w));  \
        uint4 ub0 = make_uint4(f2tf(b0.x), f2tf(b0.y), f2tf(b0.z), f2tf(b0.w));  \
        uint4 ub1 = make_uint4(f2tf(b1.x), f2tf(b1.y), f2tf(b1.z), f2tf(b1.w));  \
        *(uint4*)&As[BF][aRow][aHalf * 8]     = ua0;                             \
        *(uint4*)&As[BF][aRow][aHalf * 8 + 4] = ua1;                             \
        *(uint4*)&Bs[BF][bK][bN4 * 4]         = ub0;                             \
        *(uint4*)&Bs[BF][bK + 8][bN4 * 4]     = ub1;                             \
    } while (0)

    STORE_TILES(0);
    __syncthreads();

#pragma unroll 1
    for (int kb = kb0; kb < kb1; kb += 16) {
        int nxt = kb + 16;
        if (nxt < kb1) {
            int off = nxt - kb0;
            a0 = *(const float4*)(aPtr + off);
            a1 = *(const float4*)(aPtr + off + 4);
            b0 = *(const float4*)(bPtr + (size_t)off * N);
            b1 = *(const float4*)(bPtr + (size_t)(off + 8) * N);
        }
#pragma unroll
        for (int s = 0; s < 2; s++) {
            int ks = s * 8;
            unsigned af[2][4];
#pragma unroll
            for (int mf = 0; mf < 2; mf++) {
                int mr = wm * 32 + mf * 16 + gid;
                af[mf][0] = As[buf][mr][ks + tig];
                af[mf][1] = As[buf][mr + 8][ks + tig];
                af[mf][2] = As[buf][mr][ks + tig + 4];
                af[mf][3] = As[buf][mr + 8][ks + tig + 4];
            }
#pragma unroll
            for (int nf = 0; nf < 8; nf++) {
                int nc = wn * 64 + nf * 8 + gid;
                unsigned bf0 = Bs[buf][ks + tig][nc];
                unsigned bf1 = Bs[buf][ks + tig + 4][nc];
#pragma unroll
                for (int mf = 0; mf < 2; mf++) {
                    asm volatile(
                        "mma.sync.aligned.m16n8k8.row.col.f32.tf32.tf32.f32 "
                        "{%0,%1,%2,%3},{%4,%5,%6,%7},{%8,%9},{%0,%1,%2,%3};"
                        : "+f"(acc[mf][nf][0]), "+f"(acc[mf][nf][1]),
                          "+f"(acc[mf][nf][2]), "+f"(acc[mf][nf][3])
                        : "r"(af[mf][0]), "r"(af[mf][1]), "r"(af[mf][2]), "r"(af[mf][3]),
                          "r"(bf0), "r"(bf1));
                }
            }
        }
        if (nxt < kb1) STORE_TILES(buf ^ 1);
        __syncthreads();
        buf ^= 1;
    }
#undef STORE_TILES

#pragma unroll
    for (int mf = 0; mf < 2; mf++) {
#pragma unroll
        for (int half = 0; half < 2; half++) {
            int r = r0 + wm * 32 + mf * 16 + gid + half * 8;
            bool rok = r < count;
#pragma unroll
            for (int nf = 0; nf < 8; nf++) {
                int cb = n0 + wn * 64 + nf * 8 + tig * 2;
                float v0 = acc[mf][nf][half * 2 + 0];
                float v1 = acc[mf][nf][half * 2 + 1];
                if (!(flags & FLAG_SPLIT)) {
                    v0 += bias[cb];
                    v1 += bias[cb + 1];
                    if (flags & FLAG_RELU) { v0 = fmaxf(v0, 0.f); v1 = fmaxf(v1, 0.f); }
                }
                if (rok) {
                    if (resid) {
                        v0 += resid[(size_t)r * N + cb];
                        v1 += resid[(size_t)r * N + cb + 1];
                    }
                    Cout[(size_t)r * N + cb]     = v0;
                    Cout[(size_t)r * N + cb + 1] = v1;
                }
            }
        }
    }
}

// ---------------- split-K reduction for FFN-2 (+bias +residual) -> out ----------------
__global__ void f2red_kernel(const float* __restrict__ bias, float* __restrict__ out) {
    int i = blockIdx.x * 256 + threadIdx.x;     // 65536 elems
    int c = i & 255;
    float v = g_me2[i] + bias[c]
            + g_f2part[i] + g_f2part[65536 + i]
            + g_f2part[131072 + i] + g_f2part[196608 + i];
    out[i] = v;
}

// ---------------- attention ----------------
__global__ __launch_bounds__(256)
void attn_kernel(const float* __restrict__ machine_emb,
                 const float* __restrict__ Wo, const float* __restrict__ bo) {
    __shared__ float sc[H_][N_];
    __shared__ float ao[D_];
    __shared__ int   sn[N_];
    int row = blockIdx.x;
    int b = row >> 6;
    int tid = threadIdx.x, lane = tid & 31, h = tid >> 5;
    int cnt = g_actCnt[row];
    int start = g_rowStart[row];

    for (int i = tid; i < cnt; i += 256) sn[i] = g_actN[row * N_ + i];
    __syncthreads();

    int g = lane >> 3, d8 = lane & 7;
    const float* qkvRow = g_qkv + (size_t)row * 768;
    float4 q4  = ((const float4*)(qkvRow +       h * 32))[d8];
    float4 ks4 = ((const float4*)(qkvRow + 256 + h * 32))[d8];
    float4 vs4 = ((const float4*)(qkvRow + 512 + h * 32))[d8];

    float sSelf = q4.x * ks4.x + q4.y * ks4.y + q4.z * ks4.z + q4.w * ks4.w;
#pragma unroll
    for (int o = 1; o < 8; o <<= 1) sSelf += __shfl_xor_sync(0xffffffffu, sSelf, o);
    sSelf *= SCALE_;

    const float* Eb = g_E  + (size_t)start * D_ + h * 32;
    const float* Kb = g_kv + (size_t)b * N_ * 512 + h * 32;        // k cols 0:256
    const float* Vb = Kb + 256;                                    // v cols 256:512

    // pass 1: scores over active n only
#pragma unroll 2
    for (int j0 = 0; j0 < cnt; j0 += 4) {
        int j = j0 + g;
        bool ok = j < cnt;
        float t = 0.0f;
        if (ok) {
            float4 e4 = *(const float4*)(Eb + (size_t)j * D_ + d8 * 4);
            int n = sn[j];
            float4 k4 = *(const float4*)(Kb + (size_t)n * 512 + d8 * 4);
            t = (q4.x + e4.x) * (k4.x + e4.x) + (q4.y + e4.y) * (k4.y + e4.y)
              + (q4.z + e4.z) * (k4.z + e4.z) + (q4.w + e4.w) * (k4.w + e4.w);
        }
#pragma unroll
        for (int o = 1; o < 8; o <<= 1) t += __shfl_xor_sync(0xffffffffu, t, o);
        if (ok && d8 == 0) sc[h][j] = t * SCALE_;
    }
    __syncwarp();

    float mx = sSelf;
    for (int i = lane; i < cnt; i += 32) mx = fmaxf(mx, sc[h][i]);
    mx = warpMax(mx);
    float ps = 0.0f;
    for (int i = lane; i < cnt; i += 32) {
        float p = __expf(sc[h][i] - mx);
        sc[h][i] = p;
        ps += p;
    }
    ps = warpSum(ps);
    float pSelf = __expf(sSelf - mx);
    float inv = 1.0f / (ps + pSelf);
    __syncwarp();

    float4 acc = make_float4(0.f, 0.f, 0.f, 0.f);
    if (g == 0) {
        acc.x = pSelf * vs4.x; acc.y = pSelf * vs4.y;
        acc.z = pSelf * vs4.z; acc.w = pSelf * vs4.w;
    }
#pragma unroll 2
    for (int j0 = 0; j0 < cnt; j0 += 4) {
        int j = j0 + g;
        if (j < cnt) {
            float p = sc[h][j];
            float4 e4 = *(const float4*)(Eb + (size_t)j * D_ + d8 * 4);
            int n = sn[j];
            float4 v4 = *(const float4*)(Vb + (size_t)n * 512 + d8 * 4);
            acc.x = fmaf(p, v4.x + e4.x, acc.x);
            acc.y = fmaf(p, v4.y + e4.y, acc.y);
            acc.z = fmaf(p, v4.z + e4.z, acc.z);
            acc.w = fmaf(p, v4.w + e4.w, acc.w);
        }
    }
#pragma unroll
    for (int o = 8; o < 32; o <<= 1) {
        acc.x += __shfl_xor_sync(0xffffffffu, acc.x, o);
        acc.y += __shfl_xor_sync(0xffffffffu, acc.y, o);
        acc.z += __shfl_xor_sync(0xffffffffu, acc.z, o);
        acc.w += __shfl_xor_sync(0xffffffffu, acc.w, o);
    }
    if (g == 0) {
        float4 r = make_float4(acc.x * inv, acc.y * inv, acc.z * inv, acc.w * inv);
        *(float4*)(ao + h * 32 + d8 * 4) = r;
    }
    __syncthreads();

    float r = machine_emb[(size_t)row * D_ + tid] + bo[tid];
#pragma unroll 8
    for (int k = 0; k < D_; k++) r = fmaf(ao[k], Wo[(size_t)k * D_ + tid], r);
    g_me2[(size_t)row * D_ + tid] = r;
}

// ---------------- launch ----------------
static float* symAddr(const void* sym) {
    void* p = nullptr;
    cudaGetSymbolAddress(&p, sym);
    return (float*)p;
}

extern "C" void kernel_launch(void* const* d_in, const int* in_sizes, int n_in,
                              void* d_out, int out_size) {
    const float* machine_emb = (const float*)d_in[0];
    const float* op_emb      = (const float*)d_in[1];
    const float* edge_emb    = (const float*)d_in[2];
    const void*  mask        = d_in[3];
    const float* Wq  = (const float*)d_in[4];
    const float* bq  = (const float*)d_in[5];
    const float* Wk  = (const float*)d_in[6];
    const float* bk  = (const float*)d_in[7];
    const float* Wv  = (const float*)d_in[8];
    const float* bv  = (const float*)d_in[9];
    const float* Wo  = (const float*)d_in[10];
    const float* bo  = (const float*)d_in[11];
    const float* Wks = (const float*)d_in[12];
    const float* bks = (const float*)d_in[13];
    const float* Wvs = (const float*)d_in[14];
    const float* bvs = (const float*)d_in[15];
    const float* We  = (const float*)d_in[16];
    const float* be  = (const float*)d_in[17];
    const float* g1  = (const float*)d_in[18];
    const float* bn1 = (const float*)d_in[19];
    const float* g2  = (const float*)d_in[20];
    const float* bn2 = (const float*)d_in[21];
    const float* gop = (const float*)d_in[22];
    const float* bnop= (const float*)d_in[23];
    const float* Wf1 = (const float*)d_in[24];
    const float* bf1 = (const float*)d_in[25];
    const float* Wf2 = (const float*)d_in[26];
    const float* bf2 = (const float*)d_in[27];
    float* out = (float*)d_out;

    float* p_mnorm = symAddr(g_mnorm);
    float* p_onorm = symAddr(g_onorm);
    float* p_Wqkv  = symAddr(g_Wqkv);
    float* p_bqkv  = symAddr(g_bqkv);
    float* p_Wkv   = symAddr(g_Wkv);
    float* p_bkv   = symAddr(g_bkv);
    float* p_qkv   = symAddr(g_qkv);
    float* p_kv    = symAddr(g_kv);
    float* p_E     = symAddr(g_E);
    float* p_me2   = symAddr(g_me2);
    float* p_h     = symAddr(g_hbuf);
    float* p_f1    = symAddr(g_f1);
    float* p_f2p   = symAddr(g_f2part);

    // one-time stream/event setup (first call is the uncaptured correctness run)
    static cudaStream_t s1 = nullptr, s2 = nullptr;
    static cudaEvent_t eFork = nullptr, ePack = nullptr, eS1 = nullptr;
    if (!s1) {
        cudaStreamCreateWithFlags(&s1, cudaStreamNonBlocking);
        cudaStreamCreateWithFlags(&s2, cudaStreamNonBlocking);
        cudaEventCreateWithFlags(&eFork, cudaEventDisableTiming);
        cudaEventCreateWithFlags(&ePack, cudaEventDisableTiming);
        cudaEventCreateWithFlags(&eS1,   cudaEventDisableTiming);
    }

    // ---- fork ----
    cudaEventRecord(eFork, 0);
    cudaStreamWaitEvent(s1, eFork, 0);
    cudaStreamWaitEvent(s2, eFork, 0);

    // branch s2: weight packing
    pack_kernel<<<320, 1024, 0, s2>>>(Wq, bq, Wks, bks, Wvs, bvs, Wk, bk, Wv, bv);
    cudaEventRecord(ePack, s2);

    // branch s1: layernorms -> fused projections
    ln_kernel<<<ROWS_M, 256, 0, s1>>>(machine_emb, g1, bn1, p_mnorm);
    ln_kernel<<<ROWS_O, 256, 0, s1>>>(op_emb, gop, bnop, p_onorm);
    cudaStreamWaitEvent(s1, ePack, 0);
    {
        dim3 gQ(ROWS_M / 128, 768 / 128);
        gemm_tf32<<<gQ, 256, 0, s1>>>(p_mnorm, p_Wqkv, p_bqkv, nullptr, p_qkv,
                                      D_, 768, D_, 0, 0);
        dim3 gKV(ROWS_O / 128, 512 / 128);
        gemm_tf32<<<gKV, 256, 0, s1>>>(p_onorm, p_Wkv, p_bkv, nullptr, p_kv,
                                       D_, 512, D_, 0, 0);
    }
    cudaEventRecord(eS1, s1);

    // main branch: compaction chain -> gathered edge GEMM
    zero_kernel<<<1, 1>>>();
    detect_kernel<<<256, 256>>>((const unsigned char*)mask, in_sizes[3]);
    actlist_kernel<<<32, 256>>>(mask);
    prefix_kernel<<<1, 256>>>();
    fill_kernel<<<ROWS_M, 512>>>();
    {
        dim3 gE(NEDGE / 128, D_ / 128);
        gemm_tf32<<<gE, 256>>>(edge_emb, We, be, nullptr, p_E,
                               D_, D_, D_, 0, FLAG_GATHER);
    }

    // ---- join ----
    cudaStreamWaitEvent(0, eS1, 0);

    attn_kernel<<<ROWS_M, 256>>>(machine_emb, Wo, bo);

    ln_kernel<<<ROWS_M, 256>>>(p_me2, g2, bn2, p_h);
    {
        dim3 gF1(ROWS_M / 128, F_ / 128);
        gemm_tf32<<<gF1, 256>>>(p_h, Wf1, bf1, nullptr, p_f1,
                                D_, F_, D_, 0, FLAG_RELU);
        dim3 gF2(ROWS_M / 128, D_ / 128, 4);    // split-K, deterministic partials
        gemm_tf32<<<gF2, 256>>>(p_f1, Wf2, bf2, nullptr, p_f2p,
                                F_, D_, F_ / 4, ROWS_M * D_, FLAG_SPLIT);
    }
    f2red_kernel<<<ROWS_M, 256>>>(bf2, out);
}

// round 5
// speedup vs baseline: 4.4571x; 1.1173x over previous
#include <cuda_runtime.h>
#include <cuda_fp16.h>
#include <cstdint>

// ---------------- problem constants ----------------
#define D_      256
#define B_      4
#define M_      64
#define N_      512
#define H_      8
#define F_      1024
#define ROWS_M  256        // B*M
#define ROWS_O  2048       // B*N
#define NEDGE   131072     // B*N*M
#define SCALE_  0.17677669529663687f   // 1/sqrt(32)
#define EPS_    1e-5f

#define FLAG_RELU   1
#define FLAG_GATHER 2
#define FLAG_SPLIT  4

// ---------------- scratch (device globals; no runtime allocation) ----------------
__device__ float g_mnorm[ROWS_M * D_];
__device__ float g_onorm[ROWS_O * D_];
__device__ float g_Wqkv[D_ * 768];
__device__ float g_bqkv[768];
__device__ float g_Wkv [D_ * 512];
__device__ float g_bkv [512];
__device__ float g_qkv [ROWS_M * 768];        // cols: 0:256 q | 256:512 ks | 512:768 vs
__device__ float g_kv  [ROWS_O * 512];        // cols: 0:256 k | 256:512 v
__device__ float g_E   [(size_t)NEDGE * D_];  // compacted projected edges
__device__ float g_me2 [ROWS_M * D_];
__device__ float g_hbuf[ROWS_M * D_];
__device__ float g_f1  [ROWS_M * F_];
__device__ float g_f2part[4 * ROWS_M * D_];
__device__ int   g_actN[ROWS_M * N_];
__device__ int   g_actCnt[ROWS_M];
__device__ int   g_rowStart[ROWS_M + 1];
__device__ int   g_rowIdx[NEDGE];
__device__ int   g_count;
__device__ int   g_flagGt1, g_flagNz;

// ---------------- helpers ----------------
__device__ __forceinline__ float warpSum(float v) {
#pragma unroll
    for (int o = 16; o; o >>= 1) v += __shfl_xor_sync(0xffffffffu, v, o);
    return v;
}
__device__ __forceinline__ float warpMax(float v) {
#pragma unroll
    for (int o = 16; o; o >>= 1) v = fmaxf(v, __shfl_xor_sync(0xffffffffu, v, o));
    return v;
}
__device__ __forceinline__ uint32_t packh2(float x, float y) {
    __half2 h = __floats2half2_rn(x, y);
    return *reinterpret_cast<uint32_t*>(&h);
}
__device__ __forceinline__ uint32_t smemAddr(const void* p) {
    return (uint32_t)__cvta_generic_to_shared(p);
}

#define LDSM4(r, addr)                                                          \
    asm volatile("ldmatrix.sync.aligned.m8n8.x4.shared.b16 {%0,%1,%2,%3}, [%4];"\
                 : "=r"((r)[0]), "=r"((r)[1]), "=r"((r)[2]), "=r"((r)[3])       \
                 : "r"(addr))
#define LDSM4T(r, addr)                                                         \
    asm volatile("ldmatrix.sync.aligned.m8n8.x4.trans.shared.b16 {%0,%1,%2,%3}, [%4];" \
                 : "=r"((r)[0]), "=r"((r)[1]), "=r"((r)[2]), "=r"((r)[3])       \
                 : "r"(addr))
#define MMA16816(d, a, b0v, b1v)                                                \
    asm volatile("mma.sync.aligned.m16n8k16.row.col.f32.f16.f16.f32 "           \
                 "{%0,%1,%2,%3},{%4,%5,%6,%7},{%8,%9},{%0,%1,%2,%3};"           \
                 : "+f"((d)[0]), "+f"((d)[1]), "+f"((d)[2]), "+f"((d)[3])       \
                 : "r"((a)[0]), "r"((a)[1]), "r"((a)[2]), "r"((a)[3]),          \
                   "r"(b0v), "r"(b1v))

// ---------------- mask preprocessing ----------------
__global__ void detect_kernel(const unsigned char* __restrict__ p, int nbytes) {
    int i = blockIdx.x * blockDim.x + threadIdx.x;
    int stride = gridDim.x * blockDim.x;
    int gt1 = 0, nz = 0;
    for (; i < nbytes; i += stride) {
        unsigned char v = p[i];
        gt1 |= (v > 1);
        nz  |= (v != 0 && (i & 3) != 0);
    }
    if (__any_sync(0xffffffffu, gt1) && (threadIdx.x & 31) == 0) atomicOr(&g_flagGt1, 1);
    if (__any_sync(0xffffffffu, nz)  && (threadIdx.x & 31) == 0) atomicOr(&g_flagNz, 1);
}

__global__ void actlist_kernel(const void* __restrict__ mask) {
    int wid = threadIdx.x >> 5, lane = threadIdx.x & 31;
    int row = blockIdx.x * 8 + wid;
    int b = row >> 6, m = row & 63;
    int mode = g_flagGt1 ? 2 : (g_flagNz ? 1 : 0);
    int base = 0;
#pragma unroll 1
    for (int c = 0; c < 16; c++) {
        int n = c * 32 + lane;
        size_t mi = ((size_t)(b * N_ + n)) * M_ + m;
        bool a;
        if (mode == 2)      a = ((const float*)mask)[mi] != 0.0f;
        else if (mode == 1) a = ((const unsigned char*)mask)[mi] != 0;
        else                a = ((const int*)mask)[mi] != 0;
        unsigned bal = __ballot_sync(0xffffffffu, a);
        if (a) g_actN[row * N_ + base + __popc(bal & ((1u << lane) - 1u))] = n;
        base += __popc(bal);
    }
    if (lane == 0) g_actCnt[row] = base;
}

// Merged prefix scan + gather-list fill (256 CTAs; each redundantly scans 256 counts).
// Also resets the mask dtype flags (already consumed by actlist) for the next replay.
__global__ void prefixfill_kernel() {
    __shared__ int ws[8];
    __shared__ int startS;
    int tid = threadIdx.x;
    int row = blockIdx.x;
    int v = g_actCnt[tid];
    int lane = tid & 31, w = tid >> 5;
    int inc = v;
#pragma unroll
    for (int o = 1; o < 32; o <<= 1) {
        int t = __shfl_up_sync(0xffffffffu, inc, o);
        if (lane >= o) inc += t;
    }
    if (lane == 31) ws[w] = inc;
    __syncthreads();
    int add = 0;
#pragma unroll
    for (int i = 0; i < 8; i++) if (i < w) add += ws[i];
    int excl = inc - v + add;
    if (row == 0) {
        g_rowStart[tid] = excl;
        if (tid == 255) { g_rowStart[256] = excl + v; g_count = excl + v; }
        if (tid == 0) { g_flagGt1 = 0; g_flagNz = 0; }
    }
    if (tid == row) startS = excl;
    __syncthreads();
    int myStart = startS;
    int myCnt = g_actCnt[row];
    int b = row >> 6, m = row & 63;
    for (int i = tid; i < myCnt; i += 256) {
        int n = g_actN[row * N_ + i];
        g_rowIdx[myStart + i] = (b * N_ + n) * M_ + m;
    }
}

// ---------------- weight packing: Wq|Wks|Wvs -> g_Wqkv, Wk|Wv -> g_Wkv ----------------
__global__ void pack_kernel(const float* __restrict__ Wq,  const float* __restrict__ bq,
                            const float* __restrict__ Wks, const float* __restrict__ bks,
                            const float* __restrict__ Wvs, const float* __restrict__ bvs,
                            const float* __restrict__ Wk,  const float* __restrict__ bk,
                            const float* __restrict__ Wv,  const float* __restrict__ bv) {
    int stride = gridDim.x * blockDim.x;
    int i0 = blockIdx.x * blockDim.x + threadIdx.x;
    for (int i = i0; i < D_ * 768; i += stride) {
        int k = i / 768, c = i % 768;
        float v = (c < 256) ? Wq[k * 256 + c]
                : (c < 512) ? Wks[k * 256 + c - 256]
                            : Wvs[k * 256 + c - 512];
        g_Wqkv[i] = v;
    }
    for (int i = i0; i < D_ * 512; i += stride) {
        int k = i / 512, c = i % 512;
        g_Wkv[i] = (c < 256) ? Wk[k * 256 + c] : Wv[k * 256 + c - 256];
    }
    if (i0 < 768)
        g_bqkv[i0] = (i0 < 256) ? bq[i0] : (i0 < 512) ? bks[i0 - 256] : bvs[i0 - 512];
    if (i0 < 512)
        g_bkv[i0] = (i0 < 256) ? bk[i0] : bv[i0 - 256];
}

// ---------------- layernorm ----------------
__global__ void ln_kernel(const float* __restrict__ x, const float* __restrict__ g,
                          const float* __restrict__ beta, float* __restrict__ y) {
    __shared__ float red[16];
    int row = blockIdx.x;
    int tid = threadIdx.x;
    float v = x[(size_t)row * D_ + tid];
    float s  = warpSum(v);
    float s2 = warpSum(v * v);
    if ((tid & 31) == 0) { red[tid >> 5] = s; red[8 + (tid >> 5)] = s2; }
    __syncthreads();
    float sum = 0.f, sum2 = 0.f;
#pragma unroll
    for (int i = 0; i < 8; i++) { sum += red[i]; sum2 += red[8 + i]; }
    float mu  = sum * (1.0f / D_);
    float var = sum2 * (1.0f / D_) - mu * mu;
    float inv = rsqrtf(var + EPS_);
    y[(size_t)row * D_ + tid] = (v - mu) * inv * g[tid] + beta[tid];
}

// ---------------- fp16 tensor-core GEMM: 128x128 tile, 8 warps, ldmatrix + m16n8k16 ----
// fp32 in (converted to fp16 at smem store), fp32 accumulate/out. K mult of 32.
__global__ __launch_bounds__(256)
void gemm_fp16(const float* __restrict__ A, const float* __restrict__ W,
               const float* __restrict__ bias, const float* __restrict__ resid,
               float* __restrict__ C, int K, int N, int kChunk, int partStride,
               int flags) {
    __shared__ __align__(16) __half A_sh[2][128][40];   // pitch 40 halves (80B)
    __shared__ __align__(16) __half B_sh[2][32][136];   // pitch 136 halves (272B)
    __shared__ int src[128];

    int tid = threadIdx.x;
    int count = 0x7fffffff;
    int r0 = blockIdx.x * 128;
    if (flags & FLAG_GATHER) {
        count = g_count;
        if (r0 >= count) return;
        if (tid < 128) {
            int gidx = r0 + tid;
            src[tid] = g_rowIdx[gidx < count ? gidx : count - 1];
        }
    } else {
        if (tid < 128) src[tid] = r0 + tid;
    }
    __syncthreads();
    int n0 = blockIdx.y * 128;
    int kb0 = blockIdx.z * kChunk;
    float* Cout = C + (size_t)blockIdx.z * partStride;

    // gmem load mapping: A: thread -> (row, 16-col half); B: (k-row pair, 8-col)
    int aRow = tid & 127, aHalf = tid >> 7;
    const float* aPtr = A + (size_t)src[aRow] * K + kb0 + aHalf * 16;
    int bK = tid >> 4, bN = tid & 15;
    const float* bPtr = W + (size_t)(kb0 + bK) * N + n0 + bN * 8;

    uint32_t pa[8], pb[8];
#define LOADPACK(off)                                                            \
    do {                                                                         \
        float4 t0 = *(const float4*)(aPtr + (off));                              \
        float4 t1 = *(const float4*)(aPtr + (off) + 4);                          \
        float4 t2 = *(const float4*)(aPtr + (off) + 8);                          \
        float4 t3 = *(const float4*)(aPtr + (off) + 12);                         \
        pa[0] = packh2(t0.x, t0.y); pa[1] = packh2(t0.z, t0.w);                  \
        pa[2] = packh2(t1.x, t1.y); pa[3] = packh2(t1.z, t1.w);                  \
        pa[4] = packh2(t2.x, t2.y); pa[5] = packh2(t2.z, t2.w);                  \
        pa[6] = packh2(t3.x, t3.y); pa[7] = packh2(t3.z, t3.w);                  \
        float4 u0 = *(const float4*)(bPtr + (size_t)(off) * N);                  \
        float4 u1 = *(const float4*)(bPtr + (size_t)(off) * N + 4);              \
        float4 u2 = *(const float4*)(bPtr + (size_t)((off) + 16) * N);           \
        float4 u3 = *(const float4*)(bPtr + (size_t)((off) + 16) * N + 4);       \
        pb[0] = packh2(u0.x, u0.y); pb[1] = packh2(u0.z, u0.w);                  \
        pb[2] = packh2(u1.x, u1.y); pb[3] = packh2(u1.z, u1.w);                  \
        pb[4] = packh2(u2.x, u2.y); pb[5] = packh2(u2.z, u2.w);                  \
        pb[6] = packh2(u3.x, u3.y); pb[7] = packh2(u3.z, u3.w);                  \
    } while (0)
#define STORE_TILES(BF)                                                          \
    do {                                                                         \
        *(uint4*)&A_sh[BF][aRow][aHalf * 16]     = make_uint4(pa[0], pa[1], pa[2], pa[3]); \
        *(uint4*)&A_sh[BF][aRow][aHalf * 16 + 8] = make_uint4(pa[4], pa[5], pa[6], pa[7]); \
        *(uint4*)&B_sh[BF][bK][bN * 8]           = make_uint4(pb[0], pb[1], pb[2], pb[3]); \
        *(uint4*)&B_sh[BF][bK + 16][bN * 8]      = make_uint4(pb[4], pb[5], pb[6], pb[7]); \
    } while (0)

    float acc[2][8][4];
#pragma unroll
    for (int i = 0; i < 2; i++)
#pragma unroll
        for (int j = 0; j < 8; j++)
#pragma unroll
            for (int l = 0; l < 4; l++) acc[i][j][l] = 0.0f;

    int wid = tid >> 5, lane = tid & 31;
    int wm = wid & 3, wn = wid >> 2;
    int lrow = lane & 15, lcol = lane >> 4;
    uint32_t aLd = smemAddr(&A_sh[0][wm * 32 + lrow][lcol * 8]);
    uint32_t bLd = smemAddr(&B_sh[0][lrow][wn * 64 + lcol * 8]);
    const int A_BUF = 128 * 40 * 2;   // 10240 B
    const int B_BUF = 32 * 136 * 2;   //  8704 B

    LOADPACK(0);
    STORE_TILES(0);
    __syncthreads();

    int nIter = kChunk / 32;
    int buf = 0;
#pragma unroll 1
    for (int it = 0; it < nIter; it++) {
        if (it + 1 < nIter) LOADPACK((it + 1) * 32);
        uint32_t aB = aLd + buf * A_BUF;
        uint32_t bB = bLd + buf * B_BUF;
#pragma unroll
        for (int ks = 0; ks < 2; ks++) {
            uint32_t af[2][4];
#pragma unroll
            for (int mf = 0; mf < 2; mf++)
                LDSM4(af[mf], aB + mf * (16 * 80) + ks * 32);
            uint32_t bfm[4][4];
#pragma unroll
            for (int np = 0; np < 4; np++)
                LDSM4T(bfm[np], bB + ks * (16 * 272) + np * 32);
#pragma unroll
            for (int np = 0; np < 4; np++)
#pragma unroll
                for (int hh = 0; hh < 2; hh++) {
                    int nf = np * 2 + hh;
#pragma unroll
                    for (int mf = 0; mf < 2; mf++)
                        MMA16816(acc[mf][nf], af[mf], bfm[np][hh * 2], bfm[np][hh * 2 + 1]);
                }
        }
        if (it + 1 < nIter) STORE_TILES(buf ^ 1);
        __syncthreads();
        buf ^= 1;
    }
#undef LOADPACK
#undef STORE_TILES

    // epilogue: c0,c1 -> (gid, 2*tig / +1); c2,c3 -> (gid+8, ...)
    int gid = lane >> 2, tig = lane & 3;
#pragma unroll
    for (int mf = 0; mf < 2; mf++) {
#pragma unroll
        for (int half = 0; half < 2; half++) {
            int r = r0 + wm * 32 + mf * 16 + gid + half * 8;
            bool rok = r < count;
#pragma unroll
            for (int nf = 0; nf < 8; nf++) {
                int cb = n0 + wn * 64 + nf * 8 + tig * 2;
                float v0 = acc[mf][nf][half * 2 + 0];
                float v1 = acc[mf][nf][half * 2 + 1];
                if (!(flags & FLAG_SPLIT)) {
                    v0 += bias[cb];
                    v1 += bias[cb + 1];
                    if (flags & FLAG_RELU) { v0 = fmaxf(v0, 0.f); v1 = fmaxf(v1, 0.f); }
                }
                if (rok) {
                    if (resid) {
                        v0 += resid[(size_t)r * N + cb];
                        v1 += resid[(size_t)r * N + cb + 1];
                    }
                    Cout[(size_t)r * N + cb]     = v0;
                    Cout[(size_t)r * N + cb + 1] = v1;
                }
            }
        }
    }
}

// ---------------- split-K reduction for FFN-2 (+bias +residual) -> out ----------------
__global__ void f2red_kernel(const float* __restrict__ bias, float* __restrict__ out) {
    int i = blockIdx.x * 256 + threadIdx.x;     // 65536 elems
    int c = i & 255;
    float v = g_me2[i] + bias[c]
            + g_f2part[i] + g_f2part[65536 + i]
            + g_f2part[131072 + i] + g_f2part[196608 + i];
    out[i] = v;
}

// ---------------- attention ----------------
__global__ __launch_bounds__(256)
void attn_kernel(const float* __restrict__ machine_emb,
                 const float* __restrict__ Wo, const float* __restrict__ bo) {
    __shared__ float sc[H_][N_];
    __shared__ float ao[D_];
    __shared__ int   sn[N_];
    int row = blockIdx.x;
    int b = row >> 6;
    int tid = threadIdx.x, lane = tid & 31, h = tid >> 5;
    int cnt = g_actCnt[row];
    int start = g_rowStart[row];

    for (int i = tid; i < cnt; i += 256) sn[i] = g_actN[row * N_ + i];
    __syncthreads();

    int g = lane >> 3, d8 = lane & 7;
    const float* qkvRow = g_qkv + (size_t)row * 768;
    float4 q4  = ((const float4*)(qkvRow +       h * 32))[d8];
    float4 ks4 = ((const float4*)(qkvRow + 256 + h * 32))[d8];
    float4 vs4 = ((const float4*)(qkvRow + 512 + h * 32))[d8];

    float sSelf = q4.x * ks4.x + q4.y * ks4.y + q4.z * ks4.z + q4.w * ks4.w;
#pragma unroll
    for (int o = 1; o < 8; o <<= 1) sSelf += __shfl_xor_sync(0xffffffffu, sSelf, o);
    sSelf *= SCALE_;

    const float* Eb = g_E  + (size_t)start * D_ + h * 32;
    const float* Kb = g_kv + (size_t)b * N_ * 512 + h * 32;        // k cols 0:256
    const float* Vb = Kb + 256;                                    // v cols 256:512

    // pass 1: scores over active n only
#pragma unroll 2
    for (int j0 = 0; j0 < cnt; j0 += 4) {
        int j = j0 + g;
        bool ok = j < cnt;
        float t = 0.0f;
        if (ok) {
            float4 e4 = *(const float4*)(Eb + (size_t)j * D_ + d8 * 4);
            int n = sn[j];
            float4 k4 = *(const float4*)(Kb + (size_t)n * 512 + d8 * 4);
            t = (q4.x + e4.x) * (k4.x + e4.x) + (q4.y + e4.y) * (k4.y + e4.y)
              + (q4.z + e4.z) * (k4.z + e4.z) + (q4.w + e4.w) * (k4.w + e4.w);
        }
#pragma unroll
        for (int o = 1; o < 8; o <<= 1) t += __shfl_xor_sync(0xffffffffu, t, o);
        if (ok && d8 == 0) sc[h][j] = t * SCALE_;
    }
    __syncwarp();

    float mx = sSelf;
    for (int i = lane; i < cnt; i += 32) mx = fmaxf(mx, sc[h][i]);
    mx = warpMax(mx);
    float ps = 0.0f;
    for (int i = lane; i < cnt; i += 32) {
        float p = __expf(sc[h][i] - mx);
        sc[h][i] = p;
        ps += p;
    }
    ps = warpSum(ps);
    float pSelf = __expf(sSelf - mx);
    float inv = 1.0f / (ps + pSelf);
    __syncwarp();

    float4 acc = make_float4(0.f, 0.f, 0.f, 0.f);
    if (g == 0) {
        acc.x = pSelf * vs4.x; acc.y = pSelf * vs4.y;
        acc.z = pSelf * vs4.z; acc.w = pSelf * vs4.w;
    }
#pragma unroll 2
    for (int j0 = 0; j0 < cnt; j0 += 4) {
        int j = j0 + g;
        if (j < cnt) {
            float p = sc[h][j];
            float4 e4 = *(const float4*)(Eb + (size_t)j * D_ + d8 * 4);
            int n = sn[j];
            float4 v4 = *(const float4*)(Vb + (size_t)n * 512 + d8 * 4);
            acc.x = fmaf(p, v4.x + e4.x, acc.x);
            acc.y = fmaf(p, v4.y + e4.y, acc.y);
            acc.z = fmaf(p, v4.z + e4.z, acc.z);
            acc.w = fmaf(p, v4.w + e4.w, acc.w);
        }
    }
#pragma unroll
    for (int o = 8; o < 32; o <<= 1) {
        acc.x += __shfl_xor_sync(0xffffffffu, acc.x, o);
        acc.y += __shfl_xor_sync(0xffffffffu, acc.y, o);
        acc.z += __shfl_xor_sync(0xffffffffu, acc.z, o);
        acc.w += __shfl_xor_sync(0xffffffffu, acc.w, o);
    }
    if (g == 0) {
        float4 r = make_float4(acc.x * inv, acc.y * inv, acc.z * inv, acc.w * inv);
        *(float4*)(ao + h * 32 + d8 * 4) = r;
    }
    __syncthreads();

    float r = machine_emb[(size_t)row * D_ + tid] + bo[tid];
#pragma unroll 8
    for (int k = 0; k < D_; k++) r = fmaf(ao[k], Wo[(size_t)k * D_ + tid], r);
    g_me2[(size_t)row * D_ + tid] = r;
}

// ---------------- launch ----------------
static float* symAddr(const void* sym) {
    void* p = nullptr;
    cudaGetSymbolAddress(&p, sym);
    return (float*)p;
}

extern "C" void kernel_launch(void* const* d_in, const int* in_sizes, int n_in,
                              void* d_out, int out_size) {
    const float* machine_emb = (const float*)d_in[0];
    const float* op_emb      = (const float*)d_in[1];
    const float* edge_emb    = (const float*)d_in[2];
    const void*  mask        = d_in[3];
    const float* Wq  = (const float*)d_in[4];
    const float* bq  = (const float*)d_in[5];
    const float* Wk  = (const float*)d_in[6];
    const float* bk  = (const float*)d_in[7];
    const float* Wv  = (const float*)d_in[8];
    const float* bv  = (const float*)d_in[9];
    const float* Wo  = (const float*)d_in[10];
    const float* bo  = (const float*)d_in[11];
    const float* Wks = (const float*)d_in[12];
    const float* bks = (const float*)d_in[13];
    const float* Wvs = (const float*)d_in[14];
    const float* bvs = (const float*)d_in[15];
    const float* We  = (const float*)d_in[16];
    const float* be  = (const float*)d_in[17];
    const float* g1  = (const float*)d_in[18];
    const float* bn1 = (const float*)d_in[19];
    const float* g2  = (const float*)d_in[20];
    const float* bn2 = (const float*)d_in[21];
    const float* gop = (const float*)d_in[22];
    const float* bnop= (const float*)d_in[23];
    const float* Wf1 = (const float*)d_in[24];
    const float* bf1 = (const float*)d_in[25];
    const float* Wf2 = (const float*)d_in[26];
    const float* bf2 = (const float*)d_in[27];
    float* out = (float*)d_out;

    float* p_mnorm = symAddr(g_mnorm);
    float* p_onorm = symAddr(g_onorm);
    float* p_Wqkv  = symAddr(g_Wqkv);
    float* p_bqkv  = symAddr(g_bqkv);
    float* p_Wkv   = symAddr(g_Wkv);
    float* p_bkv   = symAddr(g_bkv);
    float* p_qkv   = symAddr(g_qkv);
    float* p_kv    = symAddr(g_kv);
    float* p_E     = symAddr(g_E);
    float* p_me2   = symAddr(g_me2);
    float* p_h     = symAddr(g_hbuf);
    float* p_f1    = symAddr(g_f1);
    float* p_f2p   = symAddr(g_f2part);

    // one-time stream/event setup (first call is the uncaptured correctness run)
    static cudaStream_t s1 = nullptr, s2 = nullptr;
    static cudaEvent_t eFork = nullptr, ePack = nullptr, eS1 = nullptr;
    if (!s1) {
        cudaStreamCreateWithFlags(&s1, cudaStreamNonBlocking);
        cudaStreamCreateWithFlags(&s2, cudaStreamNonBlocking);
        cudaEventCreateWithFlags(&eFork, cudaEventDisableTiming);
        cudaEventCreateWithFlags(&ePack, cudaEventDisableTiming);
        cudaEventCreateWithFlags(&eS1,   cudaEventDisableTiming);
    }

    // ---- fork ----
    cudaEventRecord(eFork, 0);
    cudaStreamWaitEvent(s1, eFork, 0);
    cudaStreamWaitEvent(s2, eFork, 0);

    // branch s2: weight packing
    pack_kernel<<<320, 1024, 0, s2>>>(Wq, bq, Wks, bks, Wvs, bvs, Wk, bk, Wv, bv);
    cudaEventRecord(ePack, s2);

    // branch s1: layernorms -> fused projections
    ln_kernel<<<ROWS_M, 256, 0, s1>>>(machine_emb, g1, bn1, p_mnorm);
    ln_kernel<<<ROWS_O, 256, 0, s1>>>(op_emb, gop, bnop, p_onorm);
    cudaStreamWaitEvent(s1, ePack, 0);
    {
        dim3 gQ(ROWS_M / 128, 768 / 128);
        gemm_fp16<<<gQ, 256, 0, s1>>>(p_mnorm, p_Wqkv, p_bqkv, nullptr, p_qkv,
                                      D_, 768, D_, 0, 0);
        dim3 gKV(ROWS_O / 128, 512 / 128);
        gemm_fp16<<<gKV, 256, 0, s1>>>(p_onorm, p_Wkv, p_bkv, nullptr, p_kv,
                                       D_, 512, D_, 0, 0);
    }
    cudaEventRecord(eS1, s1);

    // main branch: compaction chain -> gathered edge GEMM
    detect_kernel<<<256, 256>>>((const unsigned char*)mask, in_sizes[3]);
    actlist_kernel<<<32, 256>>>(mask);
    prefixfill_kernel<<<ROWS_M, 256>>>();
    {
        dim3 gE(NEDGE / 128, D_ / 128);
        gemm_fp16<<<gE, 256>>>(edge_emb, We, be, nullptr, p_E,
                               D_, D_, D_, 0, FLAG_GATHER);
    }

    // ---- join ----
    cudaStreamWaitEvent(0, eS1, 0);

    attn_kernel<<<ROWS_M, 256>>>(machine_emb, Wo, bo);

    ln_kernel<<<ROWS_M, 256>>>(p_me2, g2, bn2, p_h);
    {
        dim3 gF1(ROWS_M / 128, F_ / 128);
        gemm_fp16<<<gF1, 256>>>(p_h, Wf1, bf1, nullptr, p_f1,
                                D_, F_, D_, 0, FLAG_RELU);
        dim3 gF2(ROWS_M / 128, D_ / 128, 4);    // split-K, deterministic partials
        gemm_fp16<<<gF2, 256>>>(p_f1, Wf2, bf2, nullptr, p_f2p,
                                F_, D_, F_ / 4, ROWS_M * D_, FLAG_SPLIT);
    }
    f2red_kernel<<<ROWS_M, 256>>>(bf2, out);
}

// round 6
// speedup vs baseline: 4.8745x; 1.0936x over previous
#include <cuda_runtime.h>
#include <cuda_fp16.h>
#include <cstdint>

// ---------------- problem constants ----------------
#define D_      256
#define B_      4
#define M_      64
#define N_      512
#define H_      8
#define F_      1024
#define ROWS_M  256        // B*M
#define ROWS_O  2048       // B*N
#define NEDGE   131072     // B*N*M
#define SCALE_  0.17677669529663687f   // 1/sqrt(32)
#define EPS_    1e-5f

#define FLAG_RELU    1
#define FLAG_GATHER  2
#define FLAG_SPLIT   4
#define FLAG_HALFOUT 8

// ---------------- scratch (device globals; no runtime allocation) ----------------
__device__ __align__(16) __half g_mnorm16[ROWS_M * D_];
__device__ __align__(16) __half g_onorm16[ROWS_O * D_];
__device__ __align__(16) __half g_Wqkv16[D_ * 768];
__device__ __align__(16) __half g_Wkv16 [D_ * 512];
__device__ __align__(16) __half g_Wf1_16[D_ * F_];
__device__ __align__(16) __half g_Wf2_16[F_ * D_];
__device__ __align__(16) __half g_f1h   [ROWS_M * F_];
__device__ __align__(16) __half g_h16   [ROWS_M * D_];
__device__ float g_bqkv[768];
__device__ float g_bkv [512];
__device__ float g_qkv [ROWS_M * 768];        // 0:256 q | 256:512 ks | 512:768 vs
__device__ float g_kv  [ROWS_O * 512];        // 0:256 k | 256:512 v
__device__ float g_E   [(size_t)NEDGE * D_];  // compacted projected edges
__device__ float g_me2 [ROWS_M * D_];
__device__ float g_f2part[4 * ROWS_M * D_];
__device__ int   g_actN[ROWS_M * N_];
__device__ int   g_actCnt[ROWS_M];
__device__ int   g_rowStart[ROWS_M + 1];
__device__ int   g_rowIdx[NEDGE];
__device__ int   g_count;
__device__ int   g_flagGt1, g_flagNz;

// ---------------- helpers ----------------
__device__ __forceinline__ float warpSum(float v) {
#pragma unroll
    for (int o = 16; o; o >>= 1) v += __shfl_xor_sync(0xffffffffu, v, o);
    return v;
}
__device__ __forceinline__ float warpMax(float v) {
#pragma unroll
    for (int o = 16; o; o >>= 1) v = fmaxf(v, __shfl_xor_sync(0xffffffffu, v, o));
    return v;
}
__device__ __forceinline__ uint32_t packh2(float x, float y) {
    __half2 h = __floats2half2_rn(x, y);
    return *reinterpret_cast<uint32_t*>(&h);
}
__device__ __forceinline__ uint32_t smemAddr(const void* p) {
    return (uint32_t)__cvta_generic_to_shared(p);
}

#define CP16(d, s) asm volatile("cp.async.ca.shared.global [%0], [%1], 16;" :: "r"(d), "l"(s))
#define CPCOMMIT() asm volatile("cp.async.commit_group;")
#define CPWAIT0()  asm volatile("cp.async.wait_group 0;")

#define LDSM4(r, addr)                                                          \
    asm volatile("ldmatrix.sync.aligned.m8n8.x4.shared.b16 {%0,%1,%2,%3}, [%4];"\
                 : "=r"((r)[0]), "=r"((r)[1]), "=r"((r)[2]), "=r"((r)[3])       \
                 : "r"(addr))
#define LDSM4T(r, addr)                                                         \
    asm volatile("ldmatrix.sync.aligned.m8n8.x4.trans.shared.b16 {%0,%1,%2,%3}, [%4];" \
                 : "=r"((r)[0]), "=r"((r)[1]), "=r"((r)[2]), "=r"((r)[3])       \
                 : "r"(addr))
#define MMA16816(d, a, b0v, b1v)                                                \
    asm volatile("mma.sync.aligned.m16n8k16.row.col.f32.f16.f16.f32 "           \
                 "{%0,%1,%2,%3},{%4,%5,%6,%7},{%8,%9},{%0,%1,%2,%3};"           \
                 : "+f"((d)[0]), "+f"((d)[1]), "+f"((d)[2]), "+f"((d)[3])       \
                 : "r"((a)[0]), "r"((a)[1]), "r"((a)[2]), "r"((a)[3]),          \
                   "r"(b0v), "r"(b1v))

// ---------------- mask preprocessing ----------------
__global__ void detect_kernel(const unsigned char* __restrict__ p, int nbytes) {
    int i = blockIdx.x * blockDim.x + threadIdx.x;
    int stride = gridDim.x * blockDim.x;
    int gt1 = 0, nz = 0;
    for (; i < nbytes; i += stride) {
        unsigned char v = p[i];
        gt1 |= (v > 1);
        nz  |= (v != 0 && (i & 3) != 0);
    }
    if (__any_sync(0xffffffffu, gt1) && (threadIdx.x & 31) == 0) atomicOr(&g_flagGt1, 1);
    if (__any_sync(0xffffffffu, nz)  && (threadIdx.x & 31) == 0) atomicOr(&g_flagNz, 1);
}

__global__ void actlist_kernel(const void* __restrict__ mask) {
    int wid = threadIdx.x >> 5, lane = threadIdx.x & 31;
    int row = blockIdx.x * 8 + wid;
    int b = row >> 6, m = row & 63;
    int mode = g_flagGt1 ? 2 : (g_flagNz ? 1 : 0);
    int base = 0;
#pragma unroll 1
    for (int c = 0; c < 16; c++) {
        int n = c * 32 + lane;
        size_t mi = ((size_t)(b * N_ + n)) * M_ + m;
        bool a;
        if (mode == 2)      a = ((const float*)mask)[mi] != 0.0f;
        else if (mode == 1) a = ((const unsigned char*)mask)[mi] != 0;
        else                a = ((const int*)mask)[mi] != 0;
        unsigned bal = __ballot_sync(0xffffffffu, a);
        if (a) g_actN[row * N_ + base + __popc(bal & ((1u << lane) - 1u))] = n;
        base += __popc(bal);
    }
    if (lane == 0) g_actCnt[row] = base;
}

// Merged prefix + fill; resets mask flags for next replay.
__global__ void prefixfill_kernel() {
    __shared__ int ws[8];
    __shared__ int startS;
    int tid = threadIdx.x;
    int row = blockIdx.x;
    int v = g_actCnt[tid];
    int lane = tid & 31, w = tid >> 5;
    int inc = v;
#pragma unroll
    for (int o = 1; o < 32; o <<= 1) {
        int t = __shfl_up_sync(0xffffffffu, inc, o);
        if (lane >= o) inc += t;
    }
    if (lane == 31) ws[w] = inc;
    __syncthreads();
    int add = 0;
#pragma unroll
    for (int i = 0; i < 8; i++) if (i < w) add += ws[i];
    int excl = inc - v + add;
    if (row == 0) {
        g_rowStart[tid] = excl;
        if (tid == 255) { g_rowStart[256] = excl + v; g_count = excl + v; }
        if (tid == 0) { g_flagGt1 = 0; g_flagNz = 0; }
    }
    if (tid == row) startS = excl;
    __syncthreads();
    int myStart = startS;
    int myCnt = g_actCnt[row];
    int b = row >> 6, m = row & 63;
    for (int i = tid; i < myCnt; i += 256) {
        int n = g_actN[row * N_ + i];
        g_rowIdx[myStart + i] = (b * N_ + n) * M_ + m;
    }
}

// ---------------- weight packing -> fp16 ----------------
__global__ void pack_kernel(const float* __restrict__ Wq,  const float* __restrict__ bq,
                            const float* __restrict__ Wks, const float* __restrict__ bks,
                            const float* __restrict__ Wvs, const float* __restrict__ bvs,
                            const float* __restrict__ Wk,  const float* __restrict__ bk,
                            const float* __restrict__ Wv,  const float* __restrict__ bv,
                            const float* __restrict__ Wf1, const float* __restrict__ Wf2) {
    int stride = gridDim.x * blockDim.x;
    int i0 = blockIdx.x * blockDim.x + threadIdx.x;
    for (int i = i0; i < D_ * 768; i += stride) {
        int k = i / 768, c = i % 768;
        float v = (c < 256) ? Wq[k * 256 + c]
                : (c < 512) ? Wks[k * 256 + c - 256]
                            : Wvs[k * 256 + c - 512];
        g_Wqkv16[i] = __float2half(v);
    }
    for (int i = i0; i < D_ * 512; i += stride) {
        int k = i / 512, c = i % 512;
        g_Wkv16[i] = __float2half((c < 256) ? Wk[k * 256 + c] : Wv[k * 256 + c - 256]);
    }
    for (int i = i0; i < D_ * F_; i += stride) g_Wf1_16[i] = __float2half(Wf1[i]);
    for (int i = i0; i < F_ * D_; i += stride) g_Wf2_16[i] = __float2half(Wf2[i]);
    if (i0 < 768)
        g_bqkv[i0] = (i0 < 256) ? bq[i0] : (i0 < 512) ? bks[i0 - 256] : bvs[i0 - 512];
    if (i0 < 512)
        g_bkv[i0] = (i0 < 256) ? bk[i0] : bv[i0 - 256];
}

// ---------------- layernorm (fp32 in -> fp16 out) ----------------
__global__ void ln_kernel(const float* __restrict__ x, const float* __restrict__ g,
                          const float* __restrict__ beta, __half* __restrict__ y) {
    __shared__ float red[16];
    int row = blockIdx.x;
    int tid = threadIdx.x;
    float v = x[(size_t)row * D_ + tid];
    float s  = warpSum(v);
    float s2 = warpSum(v * v);
    if ((tid & 31) == 0) { red[tid >> 5] = s; red[8 + (tid >> 5)] = s2; }
    __syncthreads();
    float sum = 0.f, sum2 = 0.f;
#pragma unroll
    for (int i = 0; i < 8; i++) { sum += red[i]; sum2 += red[8 + i]; }
    float mu  = sum * (1.0f / D_);
    float var = sum2 * (1.0f / D_) - mu * mu;
    float inv = rsqrtf(var + EPS_);
    y[(size_t)row * D_ + tid] = __float2half((v - mu) * inv * g[tid] + beta[tid]);
}

// ---------------- fp16/fp16 GEMM, cp.async 2-stage: 128x128 tile, 8 warps ----------
// A half [rows,K], W half [K,N]; fp32 accum; out fp32 (C) or fp16 (Ch). K mult 32.
__global__ __launch_bounds__(256)
void gemm_h(const __half* __restrict__ A, const __half* __restrict__ W,
            const float* __restrict__ bias, float* __restrict__ C,
            __half* __restrict__ Ch,
            int K, int N, int kChunk, int partStride, int flags) {
    __shared__ __align__(16) __half A_sh[2][128][40];   // pitch 80B
    __shared__ __align__(16) __half B_sh[2][32][136];   // pitch 272B

    int tid = threadIdx.x;
    int r0 = blockIdx.x * 128, n0 = blockIdx.y * 128;
    int kb0 = blockIdx.z * kChunk;
    float* Cout = C + (size_t)blockIdx.z * partStride;

    // A: 512 chunks (128 rows x 4x16B); 2 per thread
    int a1 = tid, a2 = tid + 256;
    int aR1 = a1 >> 2, aC1 = a1 & 3, aR2 = a2 >> 2, aC2 = a2 & 3;
    const __half* aS1 = A + (size_t)(r0 + aR1) * K + kb0 + aC1 * 8;
    const __half* aS2 = A + (size_t)(r0 + aR2) * K + kb0 + aC2 * 8;
    uint32_t aD1 = smemAddr(&A_sh[0][aR1][aC1 * 8]);
    uint32_t aD2 = smemAddr(&A_sh[0][aR2][aC2 * 8]);
    // B: 512 chunks (32 rows x 16x16B); 2 per thread
    int bR1 = tid >> 4, bC = tid & 15, bR2 = bR1 + 16;
    const __half* bS1 = W + (size_t)(kb0 + bR1) * N + n0 + bC * 8;
    const __half* bS2 = W + (size_t)(kb0 + bR2) * N + n0 + bC * 8;
    uint32_t bD1 = smemAddr(&B_sh[0][bR1][bC * 8]);
    uint32_t bD2 = smemAddr(&B_sh[0][bR2][bC * 8]);
    const int ABUF = 128 * 40 * 2, BBUF = 32 * 136 * 2;

#define ISSUE(st, koff)                                                         \
    do {                                                                        \
        CP16(aD1 + (st) * ABUF, aS1 + (koff));                                  \
        CP16(aD2 + (st) * ABUF, aS2 + (koff));                                  \
        CP16(bD1 + (st) * BBUF, bS1 + (size_t)(koff) * N);                      \
        CP16(bD2 + (st) * BBUF, bS2 + (size_t)(koff) * N);                      \
    } while (0)

    float acc[2][8][4];
#pragma unroll
    for (int i = 0; i < 2; i++)
#pragma unroll
        for (int j = 0; j < 8; j++)
#pragma unroll
            for (int l = 0; l < 4; l++) acc[i][j][l] = 0.0f;

    int wid = tid >> 5, lane = tid & 31;
    int wm = wid & 3, wn = wid >> 2;
    int lrow = lane & 15, lcol = lane >> 4;
    uint32_t aLd = smemAddr(&A_sh[0][wm * 32 + lrow][lcol * 8]);
    uint32_t bLd = smemAddr(&B_sh[0][lrow][wn * 64 + lcol * 8]);

    ISSUE(0, 0);
    CPCOMMIT();

    int nIter = kChunk / 32;
#pragma unroll 1
    for (int it = 0; it < nIter; it++) {
        CPWAIT0();
        __syncthreads();
        int st = it & 1;
        if (it + 1 < nIter) ISSUE(st ^ 1, (it + 1) * 32);
        CPCOMMIT();
        uint32_t aB = aLd + st * ABUF;
        uint32_t bB = bLd + st * BBUF;
#pragma unroll
        for (int ks = 0; ks < 2; ks++) {
            uint32_t af[2][4];
#pragma unroll
            for (int mf = 0; mf < 2; mf++)
                LDSM4(af[mf], aB + mf * (16 * 80) + ks * 32);
            uint32_t bfm[4][4];
#pragma unroll
            for (int np = 0; np < 4; np++)
                LDSM4T(bfm[np], bB + ks * (16 * 272) + np * 32);
#pragma unroll
            for (int np = 0; np < 4; np++)
#pragma unroll
                for (int hh = 0; hh < 2; hh++) {
                    int nf = np * 2 + hh;
#pragma unroll
                    for (int mf = 0; mf < 2; mf++)
                        MMA16816(acc[mf][nf], af[mf], bfm[np][hh * 2], bfm[np][hh * 2 + 1]);
                }
        }
    }
#undef ISSUE

    int gid = lane >> 2, tig = lane & 3;
#pragma unroll
    for (int mf = 0; mf < 2; mf++) {
#pragma unroll
        for (int half = 0; half < 2; half++) {
            int r = r0 + wm * 32 + mf * 16 + gid + half * 8;
#pragma unroll
            for (int nf = 0; nf < 8; nf++) {
                int cb = n0 + wn * 64 + nf * 8 + tig * 2;
                float v0 = acc[mf][nf][half * 2 + 0];
                float v1 = acc[mf][nf][half * 2 + 1];
                if (!(flags & FLAG_SPLIT)) {
                    v0 += bias[cb];
                    v1 += bias[cb + 1];
                    if (flags & FLAG_RELU) { v0 = fmaxf(v0, 0.f); v1 = fmaxf(v1, 0.f); }
                }
                if (flags & FLAG_HALFOUT) {
                    *(__half2*)&Ch[(size_t)r * N + cb] = __floats2half2_rn(v0, v1);
                } else {
                    Cout[(size_t)r * N + cb]     = v0;
                    Cout[(size_t)r * N + cb + 1] = v1;
                }
            }
        }
    }
}

// ---------------- gathered edge GEMM (fp32 in, fp16 mma) — unchanged R5 path ------
__global__ __launch_bounds__(256)
void gemm_gather(const float* __restrict__ A, const float* __restrict__ W,
                 const float* __restrict__ bias, float* __restrict__ C) {
    __shared__ __align__(16) __half A_sh[2][128][40];
    __shared__ __align__(16) __half B_sh[2][32][136];
    __shared__ int src[128];

    int tid = threadIdx.x;
    int count = g_count;
    int r0 = blockIdx.x * 128;
    if (r0 >= count) return;
    if (tid < 128) {
        int gidx = r0 + tid;
        src[tid] = g_rowIdx[gidx < count ? gidx : count - 1];
    }
    __syncthreads();
    int n0 = blockIdx.y * 128;
    const int K = D_, N = D_;

    int aRow = tid & 127, aHalf = tid >> 7;
    const float* aPtr = A + (size_t)src[aRow] * K + aHalf * 16;
    int bK = tid >> 4, bN = tid & 15;
    const float* bPtr = W + (size_t)bK * N + n0 + bN * 8;

    uint32_t pa[8], pb[8];
#define LOADPACK(off)                                                            \
    do {                                                                         \
        float4 t0 = *(const float4*)(aPtr + (off));                              \
        float4 t1 = *(const float4*)(aPtr + (off) + 4);                          \
        float4 t2 = *(const float4*)(aPtr + (off) + 8);                          \
        float4 t3 = *(const float4*)(aPtr + (off) + 12);                         \
        pa[0] = packh2(t0.x, t0.y); pa[1] = packh2(t0.z, t0.w);                  \
        pa[2] = packh2(t1.x, t1.y); pa[3] = packh2(t1.z, t1.w);                  \
        pa[4] = packh2(t2.x, t2.y); pa[5] = packh2(t2.z, t2.w);                  \
        pa[6] = packh2(t3.x, t3.y); pa[7] = packh2(t3.z, t3.w);                  \
        float4 u0 = *(const float4*)(bPtr + (size_t)(off) * N);                  \
        float4 u1 = *(const float4*)(bPtr + (size_t)(off) * N + 4);              \
        float4 u2 = *(const float4*)(bPtr + (size_t)((off) + 16) * N);           \
        float4 u3 = *(const float4*)(bPtr + (size_t)((off) + 16) * N + 4);       \
        pb[0] = packh2(u0.x, u0.y); pb[1] = packh2(u0.z, u0.w);                  \
        pb[2] = packh2(u1.x, u1.y); pb[3] = packh2(u1.z, u1.w);                  \
        pb[4] = packh2(u2.x, u2.y); pb[5] = packh2(u2.z, u2.w);                  \
        pb[6] = packh2(u3.x, u3.y); pb[7] = packh2(u3.z, u3.w);                  \
    } while (0)
#define STORE_TILES(BF)                                                          \
    do {                                                                         \
        *(uint4*)&A_sh[BF][aRow][aHalf * 16]     = make_uint4(pa[0], pa[1], pa[2], pa[3]); \
        *(uint4*)&A_sh[BF][aRow][aHalf * 16 + 8] = make_uint4(pa[4], pa[5], pa[6], pa[7]); \
        *(uint4*)&B_sh[BF][bK][bN * 8]           = make_uint4(pb[0], pb[1], pb[2], pb[3]); \
        *(uint4*)&B_sh[BF][bK + 16][bN * 8]      = make_uint4(pb[4], pb[5], pb[6], pb[7]); \
    } while (0)

    float acc[2][8][4];
#pragma unroll
    for (int i = 0; i < 2; i++)
#pragma unroll
        for (int j = 0; j < 8; j++)
#pragma unroll
            for (int l = 0; l < 4; l++) acc[i][j][l] = 0.0f;

    int wid = tid >> 5, lane = tid & 31;
    int wm = wid & 3, wn = wid >> 2;
    int lrow = lane & 15, lcol = lane >> 4;
    uint32_t aLd = smemAddr(&A_sh[0][wm * 32 + lrow][lcol * 8]);
    uint32_t bLd = smemAddr(&B_sh[0][lrow][wn * 64 + lcol * 8]);
    const int A_BUF = 128 * 40 * 2;
    const int B_BUF = 32 * 136 * 2;

    LOADPACK(0);
    STORE_TILES(0);
    __syncthreads();

    int buf = 0;
#pragma unroll 1
    for (int it = 0; it < 8; it++) {
        if (it + 1 < 8) LOADPACK((it + 1) * 32);
        uint32_t aB = aLd + buf * A_BUF;
        uint32_t bB = bLd + buf * B_BUF;
#pragma unroll
        for (int ks = 0; ks < 2; ks++) {
            uint32_t af[2][4];
#pragma unroll
            for (int mf = 0; mf < 2; mf++)
                LDSM4(af[mf], aB + mf * (16 * 80) + ks * 32);
            uint32_t bfm[4][4];
#pragma unroll
            for (int np = 0; np < 4; np++)
                LDSM4T(bfm[np], bB + ks * (16 * 272) + np * 32);
#pragma unroll
            for (int np = 0; np < 4; np++)
#pragma unroll
                for (int hh = 0; hh < 2; hh++) {
                    int nf = np * 2 + hh;
#pragma unroll
                    for (int mf = 0; mf < 2; mf++)
                        MMA16816(acc[mf][nf], af[mf], bfm[np][hh * 2], bfm[np][hh * 2 + 1]);
                }
        }
        if (it + 1 < 8) STORE_TILES(buf ^ 1);
        __syncthreads();
        buf ^= 1;
    }
#undef LOADPACK
#undef STORE_TILES

    int gid = lane >> 2, tig = lane & 3;
#pragma unroll
    for (int mf = 0; mf < 2; mf++) {
#pragma unroll
        for (int half = 0; half < 2; half++) {
            int r = r0 + wm * 32 + mf * 16 + gid + half * 8;
            bool rok = r < count;
#pragma unroll
            for (int nf = 0; nf < 8; nf++) {
                int cb = n0 + wn * 64 + nf * 8 + tig * 2;
                if (rok) {
                    C[(size_t)r * N + cb]     = acc[mf][nf][half * 2 + 0] + bias[cb];
                    C[(size_t)r * N + cb + 1] = acc[mf][nf][half * 2 + 1] + bias[cb + 1];
                }
            }
        }
    }
}

// ---------------- split-K reduction for FFN-2 (+bias +residual) -> out ----------------
__global__ void f2red_kernel(const float* __restrict__ bias, float* __restrict__ out) {
    int i = blockIdx.x * 256 + threadIdx.x;
    int c = i & 255;
    out[i] = g_me2[i] + bias[c]
           + g_f2part[i] + g_f2part[65536 + i]
           + g_f2part[131072 + i] + g_f2part[196608 + i];
}

// ---------------- attention (+ fused output proj + residual + LN2) ----------------
__global__ __launch_bounds__(256)
void attn_kernel(const float* __restrict__ machine_emb,
                 const float* __restrict__ Wo, const float* __restrict__ bo,
                 const float* __restrict__ g2, const float* __restrict__ bn2) {
    __shared__ float sc[H_][N_];
    __shared__ float ao[D_];
    __shared__ int   sn[N_];
    __shared__ float red[16];
    int row = blockIdx.x;
    int b = row >> 6;
    int tid = threadIdx.x, lane = tid & 31, h = tid >> 5;
    int cnt = g_actCnt[row];
    int start = g_rowStart[row];

    for (int i = tid; i < cnt; i += 256) sn[i] = g_actN[row * N_ + i];
    __syncthreads();

    int g = lane >> 3, d8 = lane & 7;
    const float* qkvRow = g_qkv + (size_t)row * 768;
    float4 q4  = ((const float4*)(qkvRow +       h * 32))[d8];
    float4 ks4 = ((const float4*)(qkvRow + 256 + h * 32))[d8];
    float4 vs4 = ((const float4*)(qkvRow + 512 + h * 32))[d8];

    float sSelf = q4.x * ks4.x + q4.y * ks4.y + q4.z * ks4.z + q4.w * ks4.w;
#pragma unroll
    for (int o = 1; o < 8; o <<= 1) sSelf += __shfl_xor_sync(0xffffffffu, sSelf, o);
    sSelf *= SCALE_;

    const float* Eb = g_E  + (size_t)start * D_ + h * 32;
    const float* Kb = g_kv + (size_t)b * N_ * 512 + h * 32;
    const float* Vb = Kb + 256;

#pragma unroll 2
    for (int j0 = 0; j0 < cnt; j0 += 4) {
        int j = j0 + g;
        bool ok = j < cnt;
        float t = 0.0f;
        if (ok) {
            float4 e4 = *(const float4*)(Eb + (size_t)j * D_ + d8 * 4);
            int n = sn[j];
            float4 k4 = *(const float4*)(Kb + (size_t)n * 512 + d8 * 4);
            t = (q4.x + e4.x) * (k4.x + e4.x) + (q4.y + e4.y) * (k4.y + e4.y)
              + (q4.z + e4.z) * (k4.z + e4.z) + (q4.w + e4.w) * (k4.w + e4.w);
        }
#pragma unroll
        for (int o = 1; o < 8; o <<= 1) t += __shfl_xor_sync(0xffffffffu, t, o);
        if (ok && d8 == 0) sc[h][j] = t * SCALE_;
    }
    __syncwarp();

    float mx = sSelf;
    for (int i = lane; i < cnt; i += 32) mx = fmaxf(mx, sc[h][i]);
    mx = warpMax(mx);
    float ps = 0.0f;
    for (int i = lane; i < cnt; i += 32) {
        float p = __expf(sc[h][i] - mx);
        sc[h][i] = p;
        ps += p;
    }
    ps = warpSum(ps);
    float pSelf = __expf(sSelf - mx);
    float inv = 1.0f / (ps + pSelf);
    __syncwarp();

    float4 acc = make_float4(0.f, 0.f, 0.f, 0.f);
    if (g == 0) {
        acc.x = pSelf * vs4.x; acc.y = pSelf * vs4.y;
        acc.z = pSelf * vs4.z; acc.w = pSelf * vs4.w;
    }
#pragma unroll 2
    for (int j0 = 0; j0 < cnt; j0 += 4) {
        int j = j0 + g;
        if (j < cnt) {
            float p = sc[h][j];
            float4 e4 = *(const float4*)(Eb + (size_t)j * D_ + d8 * 4);
            int n = sn[j];
            float4 v4 = *(const float4*)(Vb + (size_t)n * 512 + d8 * 4);
            acc.x = fmaf(p, v4.x + e4.x, acc.x);
            acc.y = fmaf(p, v4.y + e4.y, acc.y);
            acc.z = fmaf(p, v4.z + e4.z, acc.z);
            acc.w = fmaf(p, v4.w + e4.w, acc.w);
        }
    }
#pragma unroll
    for (int o = 8; o < 32; o <<= 1) {
        acc.x += __shfl_xor_sync(0xffffffffu, acc.x, o);
        acc.y += __shfl_xor_sync(0xffffffffu, acc.y, o);
        acc.z += __shfl_xor_sync(0xffffffffu, acc.z, o);
        acc.w += __shfl_xor_sync(0xffffffffu, acc.w, o);
    }
    if (g == 0) {
        float4 r = make_float4(acc.x * inv, acc.y * inv, acc.z * inv, acc.w * inv);
        *(float4*)(ao + h * 32 + d8 * 4) = r;
    }
    __syncthreads();

    // output projection + residual
    float r = machine_emb[(size_t)row * D_ + tid] + bo[tid];
#pragma unroll 8
    for (int k = 0; k < D_; k++) r = fmaf(ao[k], Wo[(size_t)k * D_ + tid], r);
    g_me2[(size_t)row * D_ + tid] = r;

    // fused LN2 -> fp16 (row fully owned by this CTA)
    float s  = warpSum(r);
    float s2 = warpSum(r * r);
    if ((tid & 31) == 0) { red[tid >> 5] = s; red[8 + (tid >> 5)] = s2; }
    __syncthreads();
    float sum = 0.f, sum2 = 0.f;
#pragma unroll
    for (int i = 0; i < 8; i++) { sum += red[i]; sum2 += red[8 + i]; }
    float mu  = sum * (1.0f / D_);
    float var = sum2 * (1.0f / D_) - mu * mu;
    float invs = rsqrtf(var + EPS_);
    g_h16[(size_t)row * D_ + tid] = __float2half((r - mu) * invs * g2[tid] + bn2[tid]);
}

// ---------------- launch ----------------
template <typename T>
static T* symAddr(const void* sym) {
    void* p = nullptr;
    cudaGetSymbolAddress(&p, sym);
    return (T*)p;
}

extern "C" void kernel_launch(void* const* d_in, const int* in_sizes, int n_in,
                              void* d_out, int out_size) {
    const float* machine_emb = (const float*)d_in[0];
    const float* op_emb      = (const float*)d_in[1];
    const float* edge_emb    = (const float*)d_in[2];
    const void*  mask        = d_in[3];
    const float* Wq  = (const float*)d_in[4];
    const float* bq  = (const float*)d_in[5];
    const float* Wk  = (const float*)d_in[6];
    const float* bk  = (const float*)d_in[7];
    const float* Wv  = (const float*)d_in[8];
    const float* bv  = (const float*)d_in[9];
    const float* Wo  = (const float*)d_in[10];
    const float* bo  = (const float*)d_in[11];
    const float* Wks = (const float*)d_in[12];
    const float* bks = (const float*)d_in[13];
    const float* Wvs = (const float*)d_in[14];
    const float* bvs = (const float*)d_in[15];
    const float* We  = (const float*)d_in[16];
    const float* be  = (const float*)d_in[17];
    const float* g1  = (const float*)d_in[18];
    const float* bn1 = (const float*)d_in[19];
    const float* g2  = (const float*)d_in[20];
    const float* bn2 = (const float*)d_in[21];
    const float* gop = (const float*)d_in[22];
    const float* bnop= (const float*)d_in[23];
    const float* Wf1 = (const float*)d_in[24];
    const float* bf1 = (const float*)d_in[25];
    const float* Wf2 = (const float*)d_in[26];
    const float* bf2 = (const float*)d_in[27];
    float* out = (float*)d_out;

    __half* p_mnorm16 = symAddr<__half>(g_mnorm16);
    __half* p_onorm16 = symAddr<__half>(g_onorm16);
    __half* p_Wqkv16  = symAddr<__half>(g_Wqkv16);
    __half* p_Wkv16   = symAddr<__half>(g_Wkv16);
    __half* p_Wf1_16  = symAddr<__half>(g_Wf1_16);
    __half* p_Wf2_16  = symAddr<__half>(g_Wf2_16);
    __half* p_f1h     = symAddr<__half>(g_f1h);
    __half* p_h16     = symAddr<__half>(g_h16);
    float* p_bqkv = symAddr<float>(g_bqkv);
    float* p_bkv  = symAddr<float>(g_bkv);
    float* p_qkv  = symAddr<float>(g_qkv);
    float* p_kv   = symAddr<float>(g_kv);
    float* p_E    = symAddr<float>(g_E);
    float* p_f2p  = symAddr<float>(g_f2part);

    static cudaStream_t s1 = nullptr, s2 = nullptr;
    static cudaEvent_t eFork = nullptr, ePack = nullptr, eS1 = nullptr;
    if (!s1) {
        cudaStreamCreateWithFlags(&s1, cudaStreamNonBlocking);
        cudaStreamCreateWithFlags(&s2, cudaStreamNonBlocking);
        cudaEventCreateWithFlags(&eFork, cudaEventDisableTiming);
        cudaEventCreateWithFlags(&ePack, cudaEventDisableTiming);
        cudaEventCreateWithFlags(&eS1,   cudaEventDisableTiming);
    }

    // ---- fork ----
    cudaEventRecord(eFork, 0);
    cudaStreamWaitEvent(s1, eFork, 0);
    cudaStreamWaitEvent(s2, eFork, 0);

    // branch s2: weight packing (fp16)
    pack_kernel<<<320, 1024, 0, s2>>>(Wq, bq, Wks, bks, Wvs, bvs, Wk, bk, Wv, bv, Wf1, Wf2);
    cudaEventRecord(ePack, s2);

    // branch s1: layernorms -> fused projections (cp.async fp16 GEMMs)
    ln_kernel<<<ROWS_M, 256, 0, s1>>>(machine_emb, g1, bn1, p_mnorm16);
    ln_kernel<<<ROWS_O, 256, 0, s1>>>(op_emb, gop, bnop, p_onorm16);
    cudaStreamWaitEvent(s1, ePack, 0);
    {
        dim3 gQ(ROWS_M / 128, 768 / 128);
        gemm_h<<<gQ, 256, 0, s1>>>(p_mnorm16, p_Wqkv16, p_bqkv, p_qkv, nullptr,
                                   D_, 768, D_, 0, 0);
        dim3 gKV(ROWS_O / 128, 512 / 128);
        gemm_h<<<gKV, 256, 0, s1>>>(p_onorm16, p_Wkv16, p_bkv, p_kv, nullptr,
                                    D_, 512, D_, 0, 0);
    }
    cudaEventRecord(eS1, s1);

    // main branch: compaction chain -> gathered edge GEMM
    detect_kernel<<<256, 256>>>((const unsigned char*)mask, in_sizes[3]);
    actlist_kernel<<<32, 256>>>(mask);
    prefixfill_kernel<<<ROWS_M, 256>>>();
    {
        dim3 gE(NEDGE / 128, D_ / 128);
        gemm_gather<<<gE, 256>>>(edge_emb, We, be, p_E);
    }

    // ---- join ----
    cudaStreamWaitEvent(0, eS1, 0);

    attn_kernel<<<ROWS_M, 256>>>(machine_emb, Wo, bo, g2, bn2);

    {
        dim3 gF1(ROWS_M / 128, F_ / 128);
        gemm_h<<<gF1, 256>>>(p_h16, p_Wf1_16, bf1, nullptr, p_f1h,
                             D_, F_, D_, 0, FLAG_RELU | FLAG_HALFOUT);
        dim3 gF2(ROWS_M / 128, D_ / 128, 4);
        gemm_h<<<gF2, 256>>>(p_f1h, p_Wf2_16, bf2, p_f2p, nullptr,
                             F_, D_, F_ / 4, ROWS_M * D_, FLAG_SPLIT);
    }
    f2red_kernel<<<ROWS_M, 256>>>(bf2, out);
}

// round 7
// speedup vs baseline: 5.6611x; 1.1614x over previous
#include <cuda_runtime.h>
#include <cuda_fp16.h>
#include <cstdint>

// ---------------- problem constants ----------------
#define D_      256
#define B_      4
#define M_      64
#define N_      512
#define H_      8
#define F_      1024
#define ROWS_M  256        // B*M
#define ROWS_O  2048       // B*N
#define NEDGE   131072     // B*N*M
#define SCALE_  0.17677669529663687f   // 1/sqrt(32)
#define EPS_    1e-5f

#define FLAG_RELU    1
#define FLAG_SPLIT   4
#define FLAG_HALFOUT 8

// ---------------- scratch (device globals; no runtime allocation) ----------------
__device__ __align__(16) __half g_mnorm16[ROWS_M * D_];
__device__ __align__(16) __half g_onorm16[ROWS_O * D_];
__device__ __align__(16) __half g_Wqkv16[D_ * 768];
__device__ __align__(16) __half g_Wkv16 [D_ * 512];
__device__ __align__(16) __half g_We16  [D_ * D_];
__device__ __align__(16) __half g_Wf1_16[D_ * F_];
__device__ __align__(16) __half g_Wf2_16[F_ * D_];
__device__ __align__(16) __half g_f1h   [ROWS_M * F_];
__device__ __align__(16) __half g_h16   [ROWS_M * D_];
__device__ __align__(16) __half g_kvh   [ROWS_O * 512];      // 0:256 k | 256:512 v (fp16)
__device__ __align__(16) __half g_Eh    [(size_t)NEDGE * D_];// compacted projected edges fp16
__device__ float g_bqkv[768];
__device__ float g_bkv [512];
__device__ float g_qkv [ROWS_M * 768];        // 0:256 q | 256:512 ks | 512:768 vs
__device__ float g_me2 [ROWS_M * D_];
__device__ float g_f2part[4 * ROWS_M * D_];
__device__ int   g_actN[ROWS_M * N_];
__device__ int   g_actCnt[ROWS_M];
__device__ int   g_rowStart[ROWS_M + 1];
__device__ int   g_rowIdx[NEDGE];
__device__ int   g_count;
__device__ int   g_flagGt1, g_flagNz;

// ---------------- helpers ----------------
__device__ __forceinline__ float warpSum(float v) {
#pragma unroll
    for (int o = 16; o; o >>= 1) v += __shfl_xor_sync(0xffffffffu, v, o);
    return v;
}
__device__ __forceinline__ float warpMax(float v) {
#pragma unroll
    for (int o = 16; o; o >>= 1) v = fmaxf(v, __shfl_xor_sync(0xffffffffu, v, o));
    return v;
}
__device__ __forceinline__ uint32_t packh2(float x, float y) {
    __half2 h = __floats2half2_rn(x, y);
    return *reinterpret_cast<uint32_t*>(&h);
}
__device__ __forceinline__ uint32_t smemAddr(const void* p) {
    return (uint32_t)__cvta_generic_to_shared(p);
}

#define CP16(d, s) asm volatile("cp.async.ca.shared.global [%0], [%1], 16;" :: "r"(d), "l"(s))
#define CPCOMMIT() asm volatile("cp.async.commit_group;")
#define CPWAIT1()  asm volatile("cp.async.wait_group 1;")

#define LDSM4(r, addr)                                                          \
    asm volatile("ldmatrix.sync.aligned.m8n8.x4.shared.b16 {%0,%1,%2,%3}, [%4];"\
                 : "=r"((r)[0]), "=r"((r)[1]), "=r"((r)[2]), "=r"((r)[3])       \
                 : "r"(addr))
#define LDSM4T(r, addr)                                                         \
    asm volatile("ldmatrix.sync.aligned.m8n8.x4.trans.shared.b16 {%0,%1,%2,%3}, [%4];" \
                 : "=r"((r)[0]), "=r"((r)[1]), "=r"((r)[2]), "=r"((r)[3])       \
                 : "r"(addr))
#define MMA16816(d, a, b0v, b1v)                                                \
    asm volatile("mma.sync.aligned.m16n8k16.row.col.f32.f16.f16.f32 "           \
                 "{%0,%1,%2,%3},{%4,%5,%6,%7},{%8,%9},{%0,%1,%2,%3};"           \
                 : "+f"((d)[0]), "+f"((d)[1]), "+f"((d)[2]), "+f"((d)[3])       \
                 : "r"((a)[0]), "r"((a)[1]), "r"((a)[2]), "r"((a)[3]),          \
                   "r"(b0v), "r"(b1v))

// ---------------- mask preprocessing ----------------
__global__ void detect_kernel(const unsigned char* __restrict__ p, int nbytes) {
    int i = blockIdx.x * blockDim.x + threadIdx.x;
    int stride = gridDim.x * blockDim.x;
    int gt1 = 0, nz = 0;
    for (; i < nbytes; i += stride) {
        unsigned char v = p[i];
        gt1 |= (v > 1);
        nz  |= (v != 0 && (i & 3) != 0);
    }
    if (__any_sync(0xffffffffu, gt1) && (threadIdx.x & 31) == 0) atomicOr(&g_flagGt1, 1);
    if (__any_sync(0xffffffffu, nz)  && (threadIdx.x & 31) == 0) atomicOr(&g_flagNz, 1);
}

__global__ void actlist_kernel(const void* __restrict__ mask) {
    int wid = threadIdx.x >> 5, lane = threadIdx.x & 31;
    int row = blockIdx.x * 8 + wid;
    int b = row >> 6, m = row & 63;
    int mode = g_flagGt1 ? 2 : (g_flagNz ? 1 : 0);
    int base = 0;
#pragma unroll 1
    for (int c = 0; c < 16; c++) {
        int n = c * 32 + lane;
        size_t mi = ((size_t)(b * N_ + n)) * M_ + m;
        bool a;
        if (mode == 2)      a = ((const float*)mask)[mi] != 0.0f;
        else if (mode == 1) a = ((const unsigned char*)mask)[mi] != 0;
        else                a = ((const int*)mask)[mi] != 0;
        unsigned bal = __ballot_sync(0xffffffffu, a);
        if (a) g_actN[row * N_ + base + __popc(bal & ((1u << lane) - 1u))] = n;
        base += __popc(bal);
    }
    if (lane == 0) g_actCnt[row] = base;
}

// Merged prefix + fill; resets mask flags for next replay.
__global__ void prefixfill_kernel() {
    __shared__ int ws[8];
    __shared__ int startS;
    int tid = threadIdx.x;
    int row = blockIdx.x;
    int v = g_actCnt[tid];
    int lane = tid & 31, w = tid >> 5;
    int inc = v;
#pragma unroll
    for (int o = 1; o < 32; o <<= 1) {
        int t = __shfl_up_sync(0xffffffffu, inc, o);
        if (lane >= o) inc += t;
    }
    if (lane == 31) ws[w] = inc;
    __syncthreads();
    int add = 0;
#pragma unroll
    for (int i = 0; i < 8; i++) if (i < w) add += ws[i];
    int excl = inc - v + add;
    if (row == 0) {
        g_rowStart[tid] = excl;
        if (tid == 255) { g_rowStart[256] = excl + v; g_count = excl + v; }
        if (tid == 0) { g_flagGt1 = 0; g_flagNz = 0; }
    }
    if (tid == row) startS = excl;
    __syncthreads();
    int myStart = startS;
    int myCnt = g_actCnt[row];
    int b = row >> 6, m = row & 63;
    for (int i = tid; i < myCnt; i += 256) {
        int n = g_actN[row * N_ + i];
        g_rowIdx[myStart + i] = (b * N_ + n) * M_ + m;
    }
}

// ---------------- weight packing -> fp16 ----------------
__global__ void pack_kernel(const float* __restrict__ Wq,  const float* __restrict__ bq,
                            const float* __restrict__ Wks, const float* __restrict__ bks,
                            const float* __restrict__ Wvs, const float* __restrict__ bvs,
                            const float* __restrict__ Wk,  const float* __restrict__ bk,
                            const float* __restrict__ Wv,  const float* __restrict__ bv,
                            const float* __restrict__ Wf1, const float* __restrict__ Wf2,
                            const float* __restrict__ We) {
    int stride = gridDim.x * blockDim.x;
    int i0 = blockIdx.x * blockDim.x + threadIdx.x;
    for (int i = i0; i < D_ * 768; i += stride) {
        int k = i / 768, c = i % 768;
        float v = (c < 256) ? Wq[k * 256 + c]
                : (c < 512) ? Wks[k * 256 + c - 256]
                            : Wvs[k * 256 + c - 512];
        g_Wqkv16[i] = __float2half(v);
    }
    for (int i = i0; i < D_ * 512; i += stride) {
        int k = i / 512, c = i % 512;
        g_Wkv16[i] = __float2half((c < 256) ? Wk[k * 256 + c] : Wv[k * 256 + c - 256]);
    }
    for (int i = i0; i < D_ * F_; i += stride) g_Wf1_16[i] = __float2half(Wf1[i]);
    for (int i = i0; i < F_ * D_; i += stride) g_Wf2_16[i] = __float2half(Wf2[i]);
    for (int i = i0; i < D_ * D_; i += stride) g_We16[i]  = __float2half(We[i]);
    if (i0 < 768)
        g_bqkv[i0] = (i0 < 256) ? bq[i0] : (i0 < 512) ? bks[i0 - 256] : bvs[i0 - 512];
    if (i0 < 512)
        g_bkv[i0] = (i0 < 256) ? bk[i0] : bv[i0 - 256];
}

// ---------------- layernorm (fp32 in -> fp16 out) ----------------
__global__ void ln_kernel(const float* __restrict__ x, const float* __restrict__ g,
                          const float* __restrict__ beta, __half* __restrict__ y) {
    __shared__ float red[16];
    int row = blockIdx.x;
    int tid = threadIdx.x;
    float v = x[(size_t)row * D_ + tid];
    float s  = warpSum(v);
    float s2 = warpSum(v * v);
    if ((tid & 31) == 0) { red[tid >> 5] = s; red[8 + (tid >> 5)] = s2; }
    __syncthreads();
    float sum = 0.f, sum2 = 0.f;
#pragma unroll
    for (int i = 0; i < 8; i++) { sum += red[i]; sum2 += red[8 + i]; }
    float mu  = sum * (1.0f / D_);
    float var = sum2 * (1.0f / D_) - mu * mu;
    float inv = rsqrtf(var + EPS_);
    y[(size_t)row * D_ + tid] = __float2half((v - mu) * inv * g[tid] + beta[tid]);
}

// ---------------- fp16/fp16 GEMM, cp.async 3-stage: 128x128 tile, 8 warps ----------
__global__ __launch_bounds__(256)
void gemm_h(const __half* __restrict__ A, const __half* __restrict__ W,
            const float* __restrict__ bias, float* __restrict__ C,
            __half* __restrict__ Ch,
            int K, int N, int kChunk, int partStride, int flags) {
    __shared__ __align__(16) __half A_sh[3][128][40];
    __shared__ __align__(16) __half B_sh[3][32][136];

    int tid = threadIdx.x;
    int r0 = blockIdx.x * 128, n0 = blockIdx.y * 128;
    int kb0 = blockIdx.z * kChunk;
    float* Cout = C + (size_t)blockIdx.z * partStride;

    int a1 = tid, a2 = tid + 256;
    int aR1 = a1 >> 2, aC1 = a1 & 3, aR2 = a2 >> 2, aC2 = a2 & 3;
    const __half* aS1 = A + (size_t)(r0 + aR1) * K + kb0 + aC1 * 8;
    const __half* aS2 = A + (size_t)(r0 + aR2) * K + kb0 + aC2 * 8;
    uint32_t aD1 = smemAddr(&A_sh[0][aR1][aC1 * 8]);
    uint32_t aD2 = smemAddr(&A_sh[0][aR2][aC2 * 8]);
    int bR1 = tid >> 4, bC = tid & 15, bR2 = bR1 + 16;
    const __half* bS1 = W + (size_t)(kb0 + bR1) * N + n0 + bC * 8;
    const __half* bS2 = W + (size_t)(kb0 + bR2) * N + n0 + bC * 8;
    uint32_t bD1 = smemAddr(&B_sh[0][bR1][bC * 8]);
    uint32_t bD2 = smemAddr(&B_sh[0][bR2][bC * 8]);
    const int ABUF = 128 * 40 * 2, BBUF = 32 * 136 * 2;

#define ISSUE(st, koff)                                                         \
    do {                                                                        \
        CP16(aD1 + (st) * ABUF, aS1 + (koff));                                  \
        CP16(aD2 + (st) * ABUF, aS2 + (koff));                                  \
        CP16(bD1 + (st) * BBUF, bS1 + (size_t)(koff) * N);                      \
        CP16(bD2 + (st) * BBUF, bS2 + (size_t)(koff) * N);                      \
    } while (0)

    float acc[2][8][4];
#pragma unroll
    for (int i = 0; i < 2; i++)
#pragma unroll
        for (int j = 0; j < 8; j++)
#pragma unroll
            for (int l = 0; l < 4; l++) acc[i][j][l] = 0.0f;

    int wid = tid >> 5, lane = tid & 31;
    int wm = wid & 3, wn = wid >> 2;
    int lrow = lane & 15, lcol = lane >> 4;
    uint32_t aLd = smemAddr(&A_sh[0][wm * 32 + lrow][lcol * 8]);
    uint32_t bLd = smemAddr(&B_sh[0][lrow][wn * 64 + lcol * 8]);

    int nIter = kChunk / 32;
    ISSUE(0, 0);
    CPCOMMIT();
    if (nIter > 1) ISSUE(1, 32);
    CPCOMMIT();

#pragma unroll 1
    for (int it = 0; it < nIter; it++) {
        CPWAIT1();
        __syncthreads();
        int st = it % 3;
        int nx = it + 2;
        if (nx < nIter) ISSUE(nx % 3, nx * 32);
        CPCOMMIT();     // empty-group commit keeps wait_group accounting exact
        uint32_t aB = aLd + st * ABUF;
        uint32_t bB = bLd + st * BBUF;
#pragma unroll
        for (int ks = 0; ks < 2; ks++) {
            uint32_t af[2][4];
#pragma unroll
            for (int mf = 0; mf < 2; mf++)
                LDSM4(af[mf], aB + mf * (16 * 80) + ks * 32);
            uint32_t bfm[4][4];
#pragma unroll
            for (int np = 0; np < 4; np++)
                LDSM4T(bfm[np], bB + ks * (16 * 272) + np * 32);
#pragma unroll
            for (int np = 0; np < 4; np++)
#pragma unroll
                for (int hh = 0; hh < 2; hh++) {
                    int nf = np * 2 + hh;
#pragma unroll
                    for (int mf = 0; mf < 2; mf++)
                        MMA16816(acc[mf][nf], af[mf], bfm[np][hh * 2], bfm[np][hh * 2 + 1]);
                }
        }
        __syncthreads();
    }
#undef ISSUE

    int gid = lane >> 2, tig = lane & 3;
#pragma unroll
    for (int mf = 0; mf < 2; mf++) {
#pragma unroll
        for (int half = 0; half < 2; half++) {
            int r = r0 + wm * 32 + mf * 16 + gid + half * 8;
#pragma unroll
            for (int nf = 0; nf < 8; nf++) {
                int cb = n0 + wn * 64 + nf * 8 + tig * 2;
                float v0 = acc[mf][nf][half * 2 + 0];
                float v1 = acc[mf][nf][half * 2 + 1];
                if (!(flags & FLAG_SPLIT)) {
                    v0 += bias[cb];
                    v1 += bias[cb + 1];
                    if (flags & FLAG_RELU) { v0 = fmaxf(v0, 0.f); v1 = fmaxf(v1, 0.f); }
                }
                if (flags & FLAG_HALFOUT) {
                    *(__half2*)&Ch[(size_t)r * N + cb] = __floats2half2_rn(v0, v1);
                } else {
                    Cout[(size_t)r * N + cb]     = v0;
                    Cout[(size_t)r * N + cb + 1] = v1;
                }
            }
        }
    }
}

// ---------------- gathered edge GEMM (A fp32 gathered, B fp16 packed, out fp16) ----
__global__ __launch_bounds__(256)
void gemm_gather(const float* __restrict__ A, const __half* __restrict__ W16,
                 const float* __restrict__ bias, __half* __restrict__ C) {
    __shared__ __align__(16) __half A_sh[2][128][40];
    __shared__ __align__(16) __half B_sh[2][32][136];
    __shared__ int src[128];

    int tid = threadIdx.x;
    int count = g_count;
    int r0 = blockIdx.x * 128;
    if (r0 >= count) return;
    if (tid < 128) {
        int gidx = r0 + tid;
        src[tid] = g_rowIdx[gidx < count ? gidx : count - 1];
    }
    __syncthreads();
    int n0 = blockIdx.y * 128;
    const int K = D_, N = D_;

    int aRow = tid & 127, aHalf = tid >> 7;
    const float* aPtr = A + (size_t)src[aRow] * K + aHalf * 16;
    int bR1 = tid >> 4, bC = tid & 15;
    const __half* bPtr = W16 + (size_t)bR1 * N + n0 + bC * 8;

    uint32_t pa[8];
    uint4 ub0, ub1;
#define LOADPACK(off)                                                            \
    do {                                                                         \
        float4 t0 = *(const float4*)(aPtr + (off));                              \
        float4 t1 = *(const float4*)(aPtr + (off) + 4);                          \
        float4 t2 = *(const float4*)(aPtr + (off) + 8);                          \
        float4 t3 = *(const float4*)(aPtr + (off) + 12);                         \
        pa[0] = packh2(t0.x, t0.y); pa[1] = packh2(t0.z, t0.w);                  \
        pa[2] = packh2(t1.x, t1.y); pa[3] = packh2(t1.z, t1.w);                  \
        pa[4] = packh2(t2.x, t2.y); pa[5] = packh2(t2.z, t2.w);                  \
        pa[6] = packh2(t3.x, t3.y); pa[7] = packh2(t3.z, t3.w);                  \
        ub0 = *(const uint4*)(bPtr + (size_t)(off) * N);                         \
        ub1 = *(const uint4*)(bPtr + (size_t)((off) + 16) * N);                  \
    } while (0)
#define STORE_TILES(BF)                                                          \
    do {                                                                         \
        *(uint4*)&A_sh[BF][aRow][aHalf * 16]     = make_uint4(pa[0], pa[1], pa[2], pa[3]); \
        *(uint4*)&A_sh[BF][aRow][aHalf * 16 + 8] = make_uint4(pa[4], pa[5], pa[6], pa[7]); \
        *(uint4*)&B_sh[BF][bR1][bC * 8]          = ub0;                          \
        *(uint4*)&B_sh[BF][bR1 + 16][bC * 8]     = ub1;                          \
    } while (0)

    float acc[2][8][4];
#pragma unroll
    for (int i = 0; i < 2; i++)
#pragma unroll
        for (int j = 0; j < 8; j++)
#pragma unroll
            for (int l = 0; l < 4; l++) acc[i][j][l] = 0.0f;

    int wid = tid >> 5, lane = tid & 31;
    int wm = wid & 3, wn = wid >> 2;
    int lrow = lane & 15, lcol = lane >> 4;
    uint32_t aLd = smemAddr(&A_sh[0][wm * 32 + lrow][lcol * 8]);
    uint32_t bLd = smemAddr(&B_sh[0][lrow][wn * 64 + lcol * 8]);
    const int A_BUF = 128 * 40 * 2;
    const int B_BUF = 32 * 136 * 2;

    LOADPACK(0);
    STORE_TILES(0);
    __syncthreads();

    int buf = 0;
#pragma unroll 1
    for (int it = 0; it < 8; it++) {
        if (it + 1 < 8) LOADPACK((it + 1) * 32);
        uint32_t aB = aLd + buf * A_BUF;
        uint32_t bB = bLd + buf * B_BUF;
#pragma unroll
        for (int ks = 0; ks < 2; ks++) {
            uint32_t af[2][4];
#pragma unroll
            for (int mf = 0; mf < 2; mf++)
                LDSM4(af[mf], aB + mf * (16 * 80) + ks * 32);
            uint32_t bfm[4][4];
#pragma unroll
            for (int np = 0; np < 4; np++)
                LDSM4T(bfm[np], bB + ks * (16 * 272) + np * 32);
#pragma unroll
            for (int np = 0; np < 4; np++)
#pragma unroll
                for (int hh = 0; hh < 2; hh++) {
                    int nf = np * 2 + hh;
#pragma unroll
                    for (int mf = 0; mf < 2; mf++)
                        MMA16816(acc[mf][nf], af[mf], bfm[np][hh * 2], bfm[np][hh * 2 + 1]);
                }
        }
        if (it + 1 < 8) STORE_TILES(buf ^ 1);
        __syncthreads();
        buf ^= 1;
    }
#undef LOADPACK
#undef STORE_TILES

    int gid = lane >> 2, tig = lane & 3;
#pragma unroll
    for (int mf = 0; mf < 2; mf++) {
#pragma unroll
        for (int half = 0; half < 2; half++) {
            int r = r0 + wm * 32 + mf * 16 + gid + half * 8;
            bool rok = r < count;
#pragma unroll
            for (int nf = 0; nf < 8; nf++) {
                int cb = n0 + wn * 64 + nf * 8 + tig * 2;
                if (rok) {
                    float v0 = acc[mf][nf][half * 2 + 0] + bias[cb];
                    float v1 = acc[mf][nf][half * 2 + 1] + bias[cb + 1];
                    *(__half2*)&C[(size_t)r * N + cb] = __floats2half2_rn(v0, v1);
                }
            }
        }
    }
}

// ---------------- split-K reduction for FFN-2 (+bias +residual) -> out ----------------
__global__ void f2red_kernel(const float* __restrict__ bias, float* __restrict__ out) {
    int i = blockIdx.x * 256 + threadIdx.x;
    int c = i & 255;
    out[i] = g_me2[i] + bias[c]
           + g_f2part[i] + g_f2part[65536 + i]
           + g_f2part[131072 + i] + g_f2part[196608 + i];
}

// ---------------- attention (+ fused output proj + residual + LN2) ----------------
__global__ __launch_bounds__(256)
void attn_kernel(const float* __restrict__ machine_emb,
                 const float* __restrict__ Wo, const float* __restrict__ bo,
                 const float* __restrict__ g2, const float* __restrict__ bn2) {
    __shared__ float sc[H_][N_];
    __shared__ float ao[D_];
    __shared__ int   sn[N_];
    __shared__ float red[16];
    int row = blockIdx.x;
    int b = row >> 6;
    int tid = threadIdx.x, lane = tid & 31, h = tid >> 5;
    int cnt = g_actCnt[row];
    int start = g_rowStart[row];

    for (int i = tid; i < cnt; i += 256) sn[i] = g_actN[row * N_ + i];
    __syncthreads();

    int g = lane >> 3, d8 = lane & 7;
    const float* qkvRow = g_qkv + (size_t)row * 768;
    float4 q4  = ((const float4*)(qkvRow +       h * 32))[d8];
    float4 ks4 = ((const float4*)(qkvRow + 256 + h * 32))[d8];
    float4 vs4 = ((const float4*)(qkvRow + 512 + h * 32))[d8];

    float sSelf = q4.x * ks4.x + q4.y * ks4.y + q4.z * ks4.z + q4.w * ks4.w;
#pragma unroll
    for (int o = 1; o < 8; o <<= 1) sSelf += __shfl_xor_sync(0xffffffffu, sSelf, o);
    sSelf *= SCALE_;

    const __half* Eb = g_Eh  + (size_t)start * D_ + h * 32 + d8 * 4;
    const __half* Kb = g_kvh + (size_t)b * N_ * 512 + h * 32 + d8 * 4;
    const __half* Vb = Kb + 256;

#pragma unroll 2
    for (int j0 = 0; j0 < cnt; j0 += 4) {
        int j = j0 + g;
        bool ok = j < cnt;
        float t = 0.0f;
        if (ok) {
            uint2 eu = *(const uint2*)(Eb + (size_t)j * D_);
            uint2 ku = *(const uint2*)(Kb + (size_t)sn[j] * 512);
            float2 e01 = __half22float2(*(__half2*)&eu.x);
            float2 e23 = __half22float2(*(__half2*)&eu.y);
            float2 k01 = __half22float2(*(__half2*)&ku.x);
            float2 k23 = __half22float2(*(__half2*)&ku.y);
            t = (q4.x + e01.x) * (k01.x + e01.x) + (q4.y + e01.y) * (k01.y + e01.y)
              + (q4.z + e23.x) * (k23.x + e23.x) + (q4.w + e23.y) * (k23.y + e23.y);
        }
#pragma unroll
        for (int o = 1; o < 8; o <<= 1) t += __shfl_xor_sync(0xffffffffu, t, o);
        if (ok && d8 == 0) sc[h][j] = t * SCALE_;
    }
    __syncwarp();

    float mx = sSelf;
    for (int i = lane; i < cnt; i += 32) mx = fmaxf(mx, sc[h][i]);
    mx = warpMax(mx);
    float ps = 0.0f;
    for (int i = lane; i < cnt; i += 32) {
        float p = __expf(sc[h][i] - mx);
        sc[h][i] = p;
        ps += p;
    }
    ps = warpSum(ps);
    float pSelf = __expf(sSelf - mx);
    float inv = 1.0f / (ps + pSelf);
    __syncwarp();

    float4 acc = make_float4(0.f, 0.f, 0.f, 0.f);
    if (g == 0) {
        acc.x = pSelf * vs4.x; acc.y = pSelf * vs4.y;
        acc.z = pSelf * vs4.z; acc.w = pSelf * vs4.w;
    }
#pragma unroll 2
    for (int j0 = 0; j0 < cnt; j0 += 4) {
        int j = j0 + g;
        if (j < cnt) {
            float p = sc[h][j];
            uint2 eu = *(const uint2*)(Eb + (size_t)j * D_);
            uint2 vu = *(const uint2*)(Vb + (size_t)sn[j] * 512);
            float2 e01 = __half22float2(*(__half2*)&eu.x);
            float2 e23 = __half22float2(*(__half2*)&eu.y);
            float2 v01 = __half22float2(*(__half2*)&vu.x);
            float2 v23 = __half22float2(*(__half2*)&vu.y);
            acc.x = fmaf(p, v01.x + e01.x, acc.x);
            acc.y = fmaf(p, v01.y + e01.y, acc.y);
            acc.z = fmaf(p, v23.x + e23.x, acc.z);
            acc.w = fmaf(p, v23.y + e23.y, acc.w);
        }
    }
#pragma unroll
    for (int o = 8; o < 32; o <<= 1) {
        acc.x += __shfl_xor_sync(0xffffffffu, acc.x, o);
        acc.y += __shfl_xor_sync(0xffffffffu, acc.y, o);
        acc.z += __shfl_xor_sync(0xffffffffu, acc.z, o);
        acc.w += __shfl_xor_sync(0xffffffffu, acc.w, o);
    }
    if (g == 0) {
        float4 r = make_float4(acc.x * inv, acc.y * inv, acc.z * inv, acc.w * inv);
        *(float4*)(ao + h * 32 + d8 * 4) = r;
    }
    __syncthreads();

    // output projection + residual
    float r = machine_emb[(size_t)row * D_ + tid] + bo[tid];
#pragma unroll 8
    for (int k = 0; k < D_; k++) r = fmaf(ao[k], Wo[(size_t)k * D_ + tid], r);
    g_me2[(size_t)row * D_ + tid] = r;

    // fused LN2 -> fp16
    float s  = warpSum(r);
    float s2 = warpSum(r * r);
    if ((tid & 31) == 0) { red[tid >> 5] = s; red[8 + (tid >> 5)] = s2; }
    __syncthreads();
    float sum = 0.f, sum2 = 0.f;
#pragma unroll
    for (int i = 0; i < 8; i++) { sum += red[i]; sum2 += red[8 + i]; }
    float mu  = sum * (1.0f / D_);
    float var = sum2 * (1.0f / D_) - mu * mu;
    float invs = rsqrtf(var + EPS_);
    g_h16[(size_t)row * D_ + tid] = __float2half((r - mu) * invs * g2[tid] + bn2[tid]);
}

// ---------------- launch ----------------
template <typename T>
static T* symAddr(const void* sym) {
    void* p = nullptr;
    cudaGetSymbolAddress(&p, sym);
    return (T*)p;
}

extern "C" void kernel_launch(void* const* d_in, const int* in_sizes, int n_in,
                              void* d_out, int out_size) {
    const float* machine_emb = (const float*)d_in[0];
    const float* op_emb      = (const float*)d_in[1];
    const float* edge_emb    = (const float*)d_in[2];
    const void*  mask        = d_in[3];
    const float* Wq  = (const float*)d_in[4];
    const float* bq  = (const float*)d_in[5];
    const float* Wk  = (const float*)d_in[6];
    const float* bk  = (const float*)d_in[7];
    const float* Wv  = (const float*)d_in[8];
    const float* bv  = (const float*)d_in[9];
    const float* Wo  = (const float*)d_in[10];
    const float* bo  = (const float*)d_in[11];
    const float* Wks = (const float*)d_in[12];
    const float* bks = (const float*)d_in[13];
    const float* Wvs = (const float*)d_in[14];
    const float* bvs = (const float*)d_in[15];
    const float* We  = (const float*)d_in[16];
    const float* be  = (const float*)d_in[17];
    const float* g1  = (const float*)d_in[18];
    const float* bn1 = (const float*)d_in[19];
    const float* g2  = (const float*)d_in[20];
    const float* bn2 = (const float*)d_in[21];
    const float* gop = (const float*)d_in[22];
    const float* bnop= (const float*)d_in[23];
    const float* Wf1 = (const float*)d_in[24];
    const float* bf1 = (const float*)d_in[25];
    const float* Wf2 = (const float*)d_in[26];
    const float* bf2 = (const float*)d_in[27];
    float* out = (float*)d_out;

    __half* p_mnorm16 = symAddr<__half>(g_mnorm16);
    __half* p_onorm16 = symAddr<__half>(g_onorm16);
    __half* p_Wqkv16  = symAddr<__half>(g_Wqkv16);
    __half* p_Wkv16   = symAddr<__half>(g_Wkv16);
    __half* p_We16    = symAddr<__half>(g_We16);
    __half* p_Wf1_16  = symAddr<__half>(g_Wf1_16);
    __half* p_Wf2_16  = symAddr<__half>(g_Wf2_16);
    __half* p_f1h     = symAddr<__half>(g_f1h);
    __half* p_h16     = symAddr<__half>(g_h16);
    __half* p_kvh     = symAddr<__half>(g_kvh);
    __half* p_Eh      = symAddr<__half>(g_Eh);
    float* p_bqkv = symAddr<float>(g_bqkv);
    float* p_bkv  = symAddr<float>(g_bkv);
    float* p_qkv  = symAddr<float>(g_qkv);
    float* p_f2p  = symAddr<float>(g_f2part);

    static cudaStream_t s1 = nullptr, s2 = nullptr;
    static cudaEvent_t eFork = nullptr, ePack = nullptr, eS1 = nullptr;
    if (!s1) {
        cudaStreamCreateWithFlags(&s1, cudaStreamNonBlocking);
        cudaStreamCreateWithFlags(&s2, cudaStreamNonBlocking);
        cudaEventCreateWithFlags(&eFork, cudaEventDisableTiming);
        cudaEventCreateWithFlags(&ePack, cudaEventDisableTiming);
        cudaEventCreateWithFlags(&eS1,   cudaEventDisableTiming);
    }

    // ---- fork ----
    cudaEventRecord(eFork, 0);
    cudaStreamWaitEvent(s1, eFork, 0);
    cudaStreamWaitEvent(s2, eFork, 0);

    // branch s2: weight packing (fp16)
    pack_kernel<<<320, 1024, 0, s2>>>(Wq, bq, Wks, bks, Wvs, bvs, Wk, bk, Wv, bv,
                                      Wf1, Wf2, We);
    cudaEventRecord(ePack, s2);

    // branch s1: layernorms -> fused projections
    ln_kernel<<<ROWS_M, 256, 0, s1>>>(machine_emb, g1, bn1, p_mnorm16);
    ln_kernel<<<ROWS_O, 256, 0, s1>>>(op_emb, gop, bnop, p_onorm16);
    cudaStreamWaitEvent(s1, ePack, 0);
    {
        dim3 gQ(ROWS_M / 128, 768 / 128);
        gemm_h<<<gQ, 256, 0, s1>>>(p_mnorm16, p_Wqkv16, p_bqkv, p_qkv, nullptr,
                                   D_, 768, D_, 0, 0);
        dim3 gKV(ROWS_O / 128, 512 / 128);
        gemm_h<<<gKV, 256, 0, s1>>>(p_onorm16, p_Wkv16, p_bkv, nullptr, p_kvh,
                                    D_, 512, D_, 0, FLAG_HALFOUT);
    }
    cudaEventRecord(eS1, s1);

    // main branch: compaction chain -> gathered edge GEMM
    detect_kernel<<<256, 256>>>((const unsigned char*)mask, in_sizes[3]);
    actlist_kernel<<<32, 256>>>(mask);
    prefixfill_kernel<<<ROWS_M, 256>>>();
    cudaStreamWaitEvent(0, ePack, 0);   // gather needs fp16 We
    {
        dim3 gE(NEDGE / 128, D_ / 128);
        gemm_gather<<<gE, 256>>>(edge_emb, p_We16, be, p_Eh);
    }

    // ---- join ----
    cudaStreamWaitEvent(0, eS1, 0);

    attn_kernel<<<ROWS_M, 256>>>(machine_emb, Wo, bo, g2, bn2);

    {
        dim3 gF1(ROWS_M / 128, F_ / 128);
        gemm_h<<<gF1, 256>>>(p_h16, p_Wf1_16, bf1, nullptr, p_f1h,
                             D_, F_, D_, 0, FLAG_RELU | FLAG_HALFOUT);
        dim3 gF2(ROWS_M / 128, D_ / 128, 4);
        gemm_h<<<gF2, 256>>>(p_f1h, p_Wf2_16, bf2, p_f2p, nullptr,
                             F_, D_, F_ / 4, ROWS_M * D_, FLAG_SPLIT);
    }
    f2red_kernel<<<ROWS_M, 256>>>(bf2, out);
}

// round 8
// speedup vs baseline: 6.1437x; 1.0852x over previous
#include <cuda_runtime.h>
#include <cuda_fp16.h>
#include <cstdint>

// ---------------- problem constants ----------------
#define D_      256
#define B_      4
#define M_      64
#define N_      512
#define H_      8
#define F_      1024
#define ROWS_M  256        // B*M
#define ROWS_O  2048       // B*N
#define NEDGE   131072     // B*N*M
#define SCALE_  0.17677669529663687f   // 1/sqrt(32)
#define EPS_    1e-5f

#define FLAG_RELU    1
#define FLAG_SPLIT   4
#define FLAG_HALFOUT 8

// ---------------- scratch (device globals; no runtime allocation) ----------------
__device__ __align__(16) __half g_mnorm16[ROWS_M * D_];
__device__ __align__(16) __half g_onorm16[ROWS_O * D_];
__device__ __align__(16) __half g_Wqkv16[D_ * 768];
__device__ __align__(16) __half g_Wkv16 [D_ * 512];
__device__ __align__(16) __half g_We16  [D_ * D_];
__device__ __align__(16) __half g_Wf1_16[D_ * F_];
__device__ __align__(16) __half g_Wf2_16[F_ * D_];
__device__ __align__(16) __half g_f1h   [ROWS_M * F_];
__device__ __align__(16) __half g_h16   [ROWS_M * D_];
__device__ __align__(16) __half g_kvh   [ROWS_O * 512];      // 0:256 k | 256:512 v (fp16)
__device__ __align__(16) __half g_Eh    [(size_t)NEDGE * D_];// compacted projected edges fp16
__device__ float g_bqkv[768];
__device__ float g_bkv [512];
__device__ float g_qkv [ROWS_M * 768];        // 0:256 q | 256:512 ks | 512:768 vs
__device__ float g_me2 [ROWS_M * D_];
__device__ float g_f2part[4 * ROWS_M * D_];
__device__ int   g_actN[ROWS_M * N_];
__device__ int   g_actCnt[ROWS_M];
__device__ int   g_rowStart[ROWS_M + 1];
__device__ int   g_rowIdx[NEDGE];
__device__ int   g_count;
__device__ int   g_flagGt1, g_flagNz;

// ---------------- helpers ----------------
__device__ __forceinline__ float warpSum(float v) {
#pragma unroll
    for (int o = 16; o; o >>= 1) v += __shfl_xor_sync(0xffffffffu, v, o);
    return v;
}
__device__ __forceinline__ float warpMax(float v) {
#pragma unroll
    for (int o = 16; o; o >>= 1) v = fmaxf(v, __shfl_xor_sync(0xffffffffu, v, o));
    return v;
}
__device__ __forceinline__ uint32_t packh2(float x, float y) {
    __half2 h = __floats2half2_rn(x, y);
    return *reinterpret_cast<uint32_t*>(&h);
}
__device__ __forceinline__ uint32_t smemAddr(const void* p) {
    return (uint32_t)__cvta_generic_to_shared(p);
}

#define CP16(d, s) asm volatile("cp.async.ca.shared.global [%0], [%1], 16;" :: "r"(d), "l"(s))
#define CPCOMMIT() asm volatile("cp.async.commit_group;")
#define CPWAIT0()  asm volatile("cp.async.wait_group 0;")
#define CPWAIT1()  asm volatile("cp.async.wait_group 1;")

#define LDSM4(r, addr)                                                          \
    asm volatile("ldmatrix.sync.aligned.m8n8.x4.shared.b16 {%0,%1,%2,%3}, [%4];"\
                 : "=r"((r)[0]), "=r"((r)[1]), "=r"((r)[2]), "=r"((r)[3])       \
                 : "r"(addr))
#define LDSM4T(r, addr)                                                         \
    asm volatile("ldmatrix.sync.aligned.m8n8.x4.trans.shared.b16 {%0,%1,%2,%3}, [%4];" \
                 : "=r"((r)[0]), "=r"((r)[1]), "=r"((r)[2]), "=r"((r)[3])       \
                 : "r"(addr))
#define MMA16816(d, a, b0v, b1v)                                                \
    asm volatile("mma.sync.aligned.m16n8k16.row.col.f32.f16.f16.f32 "           \
                 "{%0,%1,%2,%3},{%4,%5,%6,%7},{%8,%9},{%0,%1,%2,%3};"           \
                 : "+f"((d)[0]), "+f"((d)[1]), "+f"((d)[2]), "+f"((d)[3])       \
                 : "r"((a)[0]), "r"((a)[1]), "r"((a)[2]), "r"((a)[3]),          \
                   "r"(b0v), "r"(b1v))

// ---------------- mask preprocessing ----------------
__global__ void detect_kernel(const unsigned char* __restrict__ p, int nbytes) {
    int i = blockIdx.x * blockDim.x + threadIdx.x;
    int stride = gridDim.x * blockDim.x;
    int gt1 = 0, nz = 0;
    for (; i < nbytes; i += stride) {
        unsigned char v = p[i];
        gt1 |= (v > 1);
        nz  |= (v != 0 && (i & 3) != 0);
    }
    if (__any_sync(0xffffffffu, gt1) && (threadIdx.x & 31) == 0) atomicOr(&g_flagGt1, 1);
    if (__any_sync(0xffffffffu, nz)  && (threadIdx.x & 31) == 0) atomicOr(&g_flagNz, 1);
}

__global__ void actlist_kernel(const void* __restrict__ mask) {
    int wid = threadIdx.x >> 5, lane = threadIdx.x & 31;
    int row = blockIdx.x * 8 + wid;
    int b = row >> 6, m = row & 63;
    int mode = g_flagGt1 ? 2 : (g_flagNz ? 1 : 0);
    int base = 0;
#pragma unroll 1
    for (int c = 0; c < 16; c++) {
        int n = c * 32 + lane;
        size_t mi = ((size_t)(b * N_ + n)) * M_ + m;
        bool a;
        if (mode == 2)      a = ((const float*)mask)[mi] != 0.0f;
        else if (mode == 1) a = ((const unsigned char*)mask)[mi] != 0;
        else                a = ((const int*)mask)[mi] != 0;
        unsigned bal = __ballot_sync(0xffffffffu, a);
        if (a) g_actN[row * N_ + base + __popc(bal & ((1u << lane) - 1u))] = n;
        base += __popc(bal);
    }
    if (lane == 0) g_actCnt[row] = base;
}

// Merged prefix + fill; resets mask flags for next replay.
__global__ void prefixfill_kernel() {
    __shared__ int ws[8];
    __shared__ int startS;
    int tid = threadIdx.x;
    int row = blockIdx.x;
    int v = g_actCnt[tid];
    int lane = tid & 31, w = tid >> 5;
    int inc = v;
#pragma unroll
    for (int o = 1; o < 32; o <<= 1) {
        int t = __shfl_up_sync(0xffffffffu, inc, o);
        if (lane >= o) inc += t;
    }
    if (lane == 31) ws[w] = inc;
    __syncthreads();
    int add = 0;
#pragma unroll
    for (int i = 0; i < 8; i++) if (i < w) add += ws[i];
    int excl = inc - v + add;
    if (row == 0) {
        g_rowStart[tid] = excl;
        if (tid == 255) { g_rowStart[256] = excl + v; g_count = excl + v; }
        if (tid == 0) { g_flagGt1 = 0; g_flagNz = 0; }
    }
    if (tid == row) startS = excl;
    __syncthreads();
    int myStart = startS;
    int myCnt = g_actCnt[row];
    int b = row >> 6, m = row & 63;
    for (int i = tid; i < myCnt; i += 256) {
        int n = g_actN[row * N_ + i];
        g_rowIdx[myStart + i] = (b * N_ + n) * M_ + m;
    }
}

// ---------------- weight packing -> fp16 ----------------
__global__ void pack_kernel(const float* __restrict__ Wq,  const float* __restrict__ bq,
                            const float* __restrict__ Wks, const float* __restrict__ bks,
                            const float* __restrict__ Wvs, const float* __restrict__ bvs,
                            const float* __restrict__ Wk,  const float* __restrict__ bk,
                            const float* __restrict__ Wv,  const float* __restrict__ bv,
                            const float* __restrict__ Wf1, const float* __restrict__ Wf2,
                            const float* __restrict__ We) {
    int stride = gridDim.x * blockDim.x;
    int i0 = blockIdx.x * blockDim.x + threadIdx.x;
    for (int i = i0; i < D_ * 768; i += stride) {
        int k = i / 768, c = i % 768;
        float v = (c < 256) ? Wq[k * 256 + c]
                : (c < 512) ? Wks[k * 256 + c - 256]
                            : Wvs[k * 256 + c - 512];
        g_Wqkv16[i] = __float2half(v);
    }
    for (int i = i0; i < D_ * 512; i += stride) {
        int k = i / 512, c = i % 512;
        g_Wkv16[i] = __float2half((c < 256) ? Wk[k * 256 + c] : Wv[k * 256 + c - 256]);
    }
    for (int i = i0; i < D_ * F_; i += stride) g_Wf1_16[i] = __float2half(Wf1[i]);
    for (int i = i0; i < F_ * D_; i += stride) g_Wf2_16[i] = __float2half(Wf2[i]);
    for (int i = i0; i < D_ * D_; i += stride) g_We16[i]  = __float2half(We[i]);
    if (i0 < 768)
        g_bqkv[i0] = (i0 < 256) ? bq[i0] : (i0 < 512) ? bks[i0 - 256] : bvs[i0 - 512];
    if (i0 < 512)
        g_bkv[i0] = (i0 < 256) ? bk[i0] : bv[i0 - 256];
}

// ---------------- layernorm (fp32 in -> fp16 out) ----------------
__global__ void ln_kernel(const float* __restrict__ x, const float* __restrict__ g,
                          const float* __restrict__ beta, __half* __restrict__ y) {
    __shared__ float red[16];
    int row = blockIdx.x;
    int tid = threadIdx.x;
    float v = x[(size_t)row * D_ + tid];
    float s  = warpSum(v);
    float s2 = warpSum(v * v);
    if ((tid & 31) == 0) { red[tid >> 5] = s; red[8 + (tid >> 5)] = s2; }
    __syncthreads();
    float sum = 0.f, sum2 = 0.f;
#pragma unroll
    for (int i = 0; i < 8; i++) { sum += red[i]; sum2 += red[8 + i]; }
    float mu  = sum * (1.0f / D_);
    float var = sum2 * (1.0f / D_) - mu * mu;
    float inv = rsqrtf(var + EPS_);
    y[(size_t)row * D_ + tid] = __float2half((v - mu) * inv * g[tid] + beta[tid]);
}

// ---------------- fp16/fp16 GEMM, cp.async 3-stage: 128x128 tile, 8 warps ----------
__global__ __launch_bounds__(256)
void gemm_h(const __half* __restrict__ A, const __half* __restrict__ W,
            const float* __restrict__ bias, float* __restrict__ C,
            __half* __restrict__ Ch,
            int K, int N, int kChunk, int partStride, int flags) {
    __shared__ __align__(16) __half A_sh[3][128][40];
    __shared__ __align__(16) __half B_sh[3][32][136];

    int tid = threadIdx.x;
    int r0 = blockIdx.x * 128, n0 = blockIdx.y * 128;
    int kb0 = blockIdx.z * kChunk;
    float* Cout = C + (size_t)blockIdx.z * partStride;

    int a1 = tid, a2 = tid + 256;
    int aR1 = a1 >> 2, aC1 = a1 & 3, aR2 = a2 >> 2, aC2 = a2 & 3;
    const __half* aS1 = A + (size_t)(r0 + aR1) * K + kb0 + aC1 * 8;
    const __half* aS2 = A + (size_t)(r0 + aR2) * K + kb0 + aC2 * 8;
    uint32_t aD1 = smemAddr(&A_sh[0][aR1][aC1 * 8]);
    uint32_t aD2 = smemAddr(&A_sh[0][aR2][aC2 * 8]);
    int bR1 = tid >> 4, bC = tid & 15, bR2 = bR1 + 16;
    const __half* bS1 = W + (size_t)(kb0 + bR1) * N + n0 + bC * 8;
    const __half* bS2 = W + (size_t)(kb0 + bR2) * N + n0 + bC * 8;
    uint32_t bD1 = smemAddr(&B_sh[0][bR1][bC * 8]);
    uint32_t bD2 = smemAddr(&B_sh[0][bR2][bC * 8]);
    const int ABUF = 128 * 40 * 2, BBUF = 32 * 136 * 2;

#define ISSUE(st, koff)                                                         \
    do {                                                                        \
        CP16(aD1 + (st) * ABUF, aS1 + (koff));                                  \
        CP16(aD2 + (st) * ABUF, aS2 + (koff));                                  \
        CP16(bD1 + (st) * BBUF, bS1 + (size_t)(koff) * N);                      \
        CP16(bD2 + (st) * BBUF, bS2 + (size_t)(koff) * N);                      \
    } while (0)

    float acc[2][8][4];
#pragma unroll
    for (int i = 0; i < 2; i++)
#pragma unroll
        for (int j = 0; j < 8; j++)
#pragma unroll
            for (int l = 0; l < 4; l++) acc[i][j][l] = 0.0f;

    int wid = tid >> 5, lane = tid & 31;
    int wm = wid & 3, wn = wid >> 2;
    int lrow = lane & 15, lcol = lane >> 4;
    uint32_t aLd = smemAddr(&A_sh[0][wm * 32 + lrow][lcol * 8]);
    uint32_t bLd = smemAddr(&B_sh[0][lrow][wn * 64 + lcol * 8]);

    int nIter = kChunk / 32;
    ISSUE(0, 0);
    CPCOMMIT();
    if (nIter > 1) ISSUE(1, 32);
    CPCOMMIT();

#pragma unroll 1
    for (int it = 0; it < nIter; it++) {
        CPWAIT1();
        __syncthreads();
        int st = it % 3;
        int nx = it + 2;
        if (nx < nIter) ISSUE(nx % 3, nx * 32);
        CPCOMMIT();
        uint32_t aB = aLd + st * ABUF;
        uint32_t bB = bLd + st * BBUF;
#pragma unroll
        for (int ks = 0; ks < 2; ks++) {
            uint32_t af[2][4];
#pragma unroll
            for (int mf = 0; mf < 2; mf++)
                LDSM4(af[mf], aB + mf * (16 * 80) + ks * 32);
            uint32_t bfm[4][4];
#pragma unroll
            for (int np = 0; np < 4; np++)
                LDSM4T(bfm[np], bB + ks * (16 * 272) + np * 32);
#pragma unroll
            for (int np = 0; np < 4; np++)
#pragma unroll
                for (int hh = 0; hh < 2; hh++) {
                    int nf = np * 2 + hh;
#pragma unroll
                    for (int mf = 0; mf < 2; mf++)
                        MMA16816(acc[mf][nf], af[mf], bfm[np][hh * 2], bfm[np][hh * 2 + 1]);
                }
        }
        __syncthreads();
    }
#undef ISSUE

    int gid = lane >> 2, tig = lane & 3;
#pragma unroll
    for (int mf = 0; mf < 2; mf++) {
#pragma unroll
        for (int half = 0; half < 2; half++) {
            int r = r0 + wm * 32 + mf * 16 + gid + half * 8;
#pragma unroll
            for (int nf = 0; nf < 8; nf++) {
                int cb = n0 + wn * 64 + nf * 8 + tig * 2;
                float v0 = acc[mf][nf][half * 2 + 0];
                float v1 = acc[mf][nf][half * 2 + 1];
                if (!(flags & FLAG_SPLIT)) {
                    v0 += bias[cb];
                    v1 += bias[cb + 1];
                    if (flags & FLAG_RELU) { v0 = fmaxf(v0, 0.f); v1 = fmaxf(v1, 0.f); }
                }
                if (flags & FLAG_HALFOUT) {
                    *(__half2*)&Ch[(size_t)r * N + cb] = __floats2half2_rn(v0, v1);
                } else {
                    Cout[(size_t)r * N + cb]     = v0;
                    Cout[(size_t)r * N + cb + 1] = v1;
                }
            }
        }
    }
}

// ---------------- gathered edge GEMM: 128x256 tile, 512 threads (16 warps) ----------
// A fp32 gathered (LDG+pack, loaded ONCE), B fp16 via cp.async, out fp16.
__global__ __launch_bounds__(512)
void gemm_gather(const float* __restrict__ A, const __half* __restrict__ W16,
                 const float* __restrict__ bias, __half* __restrict__ C) {
    __shared__ __align__(16) __half A_sh[2][128][40];    // 20.0 KB
    __shared__ __align__(16) __half B_sh[2][32][264];    // 33.0 KB
    __shared__ int src[128];

    int tid = threadIdx.x;
    int count = g_count;
    int r0 = blockIdx.x * 128;
    if (r0 >= count) return;
    if (tid < 128) {
        int gidx = r0 + tid;
        src[tid] = g_rowIdx[gidx < count ? gidx : count - 1];
    }
    __syncthreads();
    const int K = D_, N = D_;

    // A: 128 rows x 32 fp32 per iter; thread -> (row = tid>>2, 8-float group tid&3)
    int aR = tid >> 2, aC = tid & 3;
    const float* aPtr = A + (size_t)src[aR] * K + aC * 8;
    uint32_t aDst = smemAddr(&A_sh[0][aR][aC * 8]);
    // B: 32 rows x 256 fp16 per iter via cp.async; thread -> 2 chunks of 16B
    int bR = tid >> 5, bC = tid & 31;
    const __half* bS1 = W16 + (size_t)bR * N + bC * 8;
    const __half* bS2 = W16 + (size_t)(bR + 16) * N + bC * 8;
    uint32_t bD1 = smemAddr(&B_sh[0][bR][bC * 8]);
    uint32_t bD2 = smemAddr(&B_sh[0][bR + 16][bC * 8]);
    const int A_BUF = 128 * 40 * 2;     // 10240 B
    const int B_BUF = 32 * 264 * 2;     // 16896 B

    uint32_t pa[4];
#define LOADA(off)                                                               \
    do {                                                                         \
        float4 t0 = *(const float4*)(aPtr + (off));                              \
        float4 t1 = *(const float4*)(aPtr + (off) + 4);                          \
        pa[0] = packh2(t0.x, t0.y); pa[1] = packh2(t0.z, t0.w);                  \
        pa[2] = packh2(t1.x, t1.y); pa[3] = packh2(t1.z, t1.w);                  \
    } while (0)
#define STOREA(BF)                                                               \
    *(uint4*)((char*)0 + 0, &A_sh[BF][aR][aC * 8]) = make_uint4(pa[0], pa[1], pa[2], pa[3])
#undef STOREA
#define STOREA(BF) \
    *(uint4*)&A_sh[BF][aR][aC * 8] = make_uint4(pa[0], pa[1], pa[2], pa[3])
#define ISSUEB(st, koff)                                                         \
    do {                                                                         \
        CP16(bD1 + (st) * B_BUF, bS1 + (size_t)(koff) * N);                      \
        CP16(bD2 + (st) * B_BUF, bS2 + (size_t)(koff) * N);                      \
    } while (0)

    float acc[2][8][4];
#pragma unroll
    for (int i = 0; i < 2; i++)
#pragma unroll
        for (int j = 0; j < 8; j++)
#pragma unroll
            for (int l = 0; l < 4; l++) acc[i][j][l] = 0.0f;

    int wid = tid >> 5, lane = tid & 31;
    int wm = wid & 3, wn = wid >> 2;     // wn 0..3 over 256 cols
    int lrow = lane & 15, lcol = lane >> 4;
    uint32_t aLd = smemAddr(&A_sh[0][wm * 32 + lrow][lcol * 8]);
    uint32_t bLd = smemAddr(&B_sh[0][lrow][wn * 64 + lcol * 8]);

    LOADA(0);
    ISSUEB(0, 0);
    CPCOMMIT();
    STOREA(0);
    CPWAIT0();
    __syncthreads();

    int buf = 0;
#pragma unroll 1
    for (int it = 0; it < 8; it++) {
        if (it + 1 < 8) {
            LOADA((it + 1) * 32);
            ISSUEB(buf ^ 1, (it + 1) * 32);
        }
        CPCOMMIT();
        uint32_t aB = aLd + buf * A_BUF;
        uint32_t bB = bLd + buf * B_BUF;
#pragma unroll
        for (int ks = 0; ks < 2; ks++) {
            uint32_t af[2][4];
#pragma unroll
            for (int mf = 0; mf < 2; mf++)
                LDSM4(af[mf], aB + mf * (16 * 80) + ks * 32);
            uint32_t bfm[4][4];
#pragma unroll
            for (int np = 0; np < 4; np++)
                LDSM4T(bfm[np], bB + ks * (16 * 528) + np * 32);
#pragma unroll
            for (int np = 0; np < 4; np++)
#pragma unroll
                for (int hh = 0; hh < 2; hh++) {
                    int nf = np * 2 + hh;
#pragma unroll
                    for (int mf = 0; mf < 2; mf++)
                        MMA16816(acc[mf][nf], af[mf], bfm[np][hh * 2], bfm[np][hh * 2 + 1]);
                }
        }
        if (it + 1 < 8) STOREA(buf ^ 1);
        CPWAIT0();
        __syncthreads();
        buf ^= 1;
    }
#undef LOADA
#undef STOREA
#undef ISSUEB

    int gid = lane >> 2, tig = lane & 3;
#pragma unroll
    for (int mf = 0; mf < 2; mf++) {
#pragma unroll
        for (int half = 0; half < 2; half++) {
            int r = r0 + wm * 32 + mf * 16 + gid + half * 8;
            bool rok = r < count;
#pragma unroll
            for (int nf = 0; nf < 8; nf++) {
                int cb = wn * 64 + nf * 8 + tig * 2;
                if (rok) {
                    float v0 = acc[mf][nf][half * 2 + 0] + bias[cb];
                    float v1 = acc[mf][nf][half * 2 + 1] + bias[cb + 1];
                    *(__half2*)&C[(size_t)r * N + cb] = __floats2half2_rn(v0, v1);
                }
            }
        }
    }
}

// ---------------- split-K reduction for FFN-2 (+bias +residual) -> out ----------------
__global__ void f2red_kernel(const float* __restrict__ bias, float* __restrict__ out) {
    int i = blockIdx.x * 256 + threadIdx.x;
    int c = i & 255;
    out[i] = g_me2[i] + bias[c]
           + g_f2part[i] + g_f2part[65536 + i]
           + g_f2part[131072 + i] + g_f2part[196608 + i];
}

// ---------------- attention (+ fused output proj + residual + LN2) ----------------
__global__ __launch_bounds__(256)
void attn_kernel(const float* __restrict__ machine_emb,
                 const float* __restrict__ Wo, const float* __restrict__ bo,
                 const float* __restrict__ g2, const float* __restrict__ bn2) {
    __shared__ float sc[H_][N_];
    __shared__ float ao[D_];
    __shared__ int   sn[N_];
    __shared__ float red[16];
    int row = blockIdx.x;
    int b = row >> 6;
    int tid = threadIdx.x, lane = tid & 31, h = tid >> 5;
    int cnt = g_actCnt[row];
    int start = g_rowStart[row];

    for (int i = tid; i < cnt; i += 256) sn[i] = g_actN[row * N_ + i];
    __syncthreads();

    int g = lane >> 3, d8 = lane & 7;
    const float* qkvRow = g_qkv + (size_t)row * 768;
    float4 q4  = ((const float4*)(qkvRow +       h * 32))[d8];
    float4 ks4 = ((const float4*)(qkvRow + 256 + h * 32))[d8];
    float4 vs4 = ((const float4*)(qkvRow + 512 + h * 32))[d8];

    float sSelf = q4.x * ks4.x + q4.y * ks4.y + q4.z * ks4.z + q4.w * ks4.w;
#pragma unroll
    for (int o = 1; o < 8; o <<= 1) sSelf += __shfl_xor_sync(0xffffffffu, sSelf, o);
    sSelf *= SCALE_;

    const __half* Eb = g_Eh  + (size_t)start * D_ + h * 32 + d8 * 4;
    const __half* Kb = g_kvh + (size_t)b * N_ * 512 + h * 32 + d8 * 4;
    const __half* Vb = Kb + 256;

#pragma unroll 2
    for (int j0 = 0; j0 < cnt; j0 += 4) {
        int j = j0 + g;
        bool ok = j < cnt;
        float t = 0.0f;
        if (ok) {
            uint2 eu = *(const uint2*)(Eb + (size_t)j * D_);
            uint2 ku = *(const uint2*)(Kb + (size_t)sn[j] * 512);
            float2 e01 = __half22float2(*(__half2*)&eu.x);
            float2 e23 = __half22float2(*(__half2*)&eu.y);
            float2 k01 = __half22float2(*(__half2*)&ku.x);
            float2 k23 = __half22float2(*(__half2*)&ku.y);
            t = (q4.x + e01.x) * (k01.x + e01.x) + (q4.y + e01.y) * (k01.y + e01.y)
              + (q4.z + e23.x) * (k23.x + e23.x) + (q4.w + e23.y) * (k23.y + e23.y);
        }
#pragma unroll
        for (int o = 1; o < 8; o <<= 1) t += __shfl_xor_sync(0xffffffffu, t, o);
        if (ok && d8 == 0) sc[h][j] = t * SCALE_;
    }
    __syncwarp();

    float mx = sSelf;
    for (int i = lane; i < cnt; i += 32) mx = fmaxf(mx, sc[h][i]);
    mx = warpMax(mx);
    float ps = 0.0f;
    for (int i = lane; i < cnt; i += 32) {
        float p = __expf(sc[h][i] - mx);
        sc[h][i] = p;
        ps += p;
    }
    ps = warpSum(ps);
    float pSelf = __expf(sSelf - mx);
    float inv = 1.0f / (ps + pSelf);
    __syncwarp();

    float4 acc = make_float4(0.f, 0.f, 0.f, 0.f);
    if (g == 0) {
        acc.x = pSelf * vs4.x; acc.y = pSelf * vs4.y;
        acc.z = pSelf * vs4.z; acc.w = pSelf * vs4.w;
    }
#pragma unroll 2
    for (int j0 = 0; j0 < cnt; j0 += 4) {
        int j = j0 + g;
        if (j < cnt) {
            float p = sc[h][j];
            uint2 eu = *(const uint2*)(Eb + (size_t)j * D_);
            uint2 vu = *(const uint2*)(Vb + (size_t)sn[j] * 512);
            float2 e01 = __half22float2(*(__half2*)&eu.x);
            float2 e23 = __half22float2(*(__half2*)&eu.y);
            float2 v01 = __half22float2(*(__half2*)&vu.x);
            float2 v23 = __half22float2(*(__half2*)&vu.y);
            acc.x = fmaf(p, v01.x + e01.x, acc.x);
            acc.y = fmaf(p, v01.y + e01.y, acc.y);
            acc.z = fmaf(p, v23.x + e23.x, acc.z);
            acc.w = fmaf(p, v23.y + e23.y, acc.w);
        }
    }
#pragma unroll
    for (int o = 8; o < 32; o <<= 1) {
        acc.x += __shfl_xor_sync(0xffffffffu, acc.x, o);
        acc.y += __shfl_xor_sync(0xffffffffu, acc.y, o);
        acc.z += __shfl_xor_sync(0xffffffffu, acc.z, o);
        acc.w += __shfl_xor_sync(0xffffffffu, acc.w, o);
    }
    if (g == 0) {
        float4 r = make_float4(acc.x * inv, acc.y * inv, acc.z * inv, acc.w * inv);
        *(float4*)(ao + h * 32 + d8 * 4) = r;
    }
    __syncthreads();

    // output projection + residual
    float r = machine_emb[(size_t)row * D_ + tid] + bo[tid];
#pragma unroll 8
    for (int k = 0; k < D_; k++) r = fmaf(ao[k], Wo[(size_t)k * D_ + tid], r);
    g_me2[(size_t)row * D_ + tid] = r;

    // fused LN2 -> fp16
    float s  = warpSum(r);
    float s2 = warpSum(r * r);
    if ((tid & 31) == 0) { red[tid >> 5] = s; red[8 + (tid >> 5)] = s2; }
    __syncthreads();
    float sum = 0.f, sum2 = 0.f;
#pragma unroll
    for (int i = 0; i < 8; i++) { sum += red[i]; sum2 += red[8 + i]; }
    float mu  = sum * (1.0f / D_);
    float var = sum2 * (1.0f / D_) - mu * mu;
    float invs = rsqrtf(var + EPS_);
    g_h16[(size_t)row * D_ + tid] = __float2half((r - mu) * invs * g2[tid] + bn2[tid]);
}

// ---------------- launch ----------------
template <typename T>
static T* symAddr(const void* sym) {
    void* p = nullptr;
    cudaGetSymbolAddress(&p, sym);
    return (T*)p;
}

extern "C" void kernel_launch(void* const* d_in, const int* in_sizes, int n_in,
                              void* d_out, int out_size) {
    const float* machine_emb = (const float*)d_in[0];
    const float* op_emb      = (const float*)d_in[1];
    const float* edge_emb    = (const float*)d_in[2];
    const void*  mask        = d_in[3];
    const float* Wq  = (const float*)d_in[4];
    const float* bq  = (const float*)d_in[5];
    const float* Wk  = (const float*)d_in[6];
    const float* bk  = (const float*)d_in[7];
    const float* Wv  = (const float*)d_in[8];
    const float* bv  = (const float*)d_in[9];
    const float* Wo  = (const float*)d_in[10];
    const float* bo  = (const float*)d_in[11];
    const float* Wks = (const float*)d_in[12];
    const float* bks = (const float*)d_in[13];
    const float* Wvs = (const float*)d_in[14];
    const float* bvs = (const float*)d_in[15];
    const float* We  = (const float*)d_in[16];
    const float* be  = (const float*)d_in[17];
    const float* g1  = (const float*)d_in[18];
    const float* bn1 = (const float*)d_in[19];
    const float* g2  = (const float*)d_in[20];
    const float* bn2 = (const float*)d_in[21];
    const float* gop = (const float*)d_in[22];
    const float* bnop= (const float*)d_in[23];
    const float* Wf1 = (const float*)d_in[24];
    const float* bf1 = (const float*)d_in[25];
    const float* Wf2 = (const float*)d_in[26];
    const float* bf2 = (const float*)d_in[27];
    float* out = (float*)d_out;

    __half* p_mnorm16 = symAddr<__half>(g_mnorm16);
    __half* p_onorm16 = symAddr<__half>(g_onorm16);
    __half* p_Wqkv16  = symAddr<__half>(g_Wqkv16);
    __half* p_Wkv16   = symAddr<__half>(g_Wkv16);
    __half* p_We16    = symAddr<__half>(g_We16);
    __half* p_Wf1_16  = symAddr<__half>(g_Wf1_16);
    __half* p_Wf2_16  = symAddr<__half>(g_Wf2_16);
    __half* p_f1h     = symAddr<__half>(g_f1h);
    __half* p_h16     = symAddr<__half>(g_h16);
    __half* p_kvh     = symAddr<__half>(g_kvh);
    __half* p_Eh      = symAddr<__half>(g_Eh);
    float* p_bqkv = symAddr<float>(g_bqkv);
    float* p_bkv  = symAddr<float>(g_bkv);
    float* p_qkv  = symAddr<float>(g_qkv);
    float* p_f2p  = symAddr<float>(g_f2part);

    static cudaStream_t s1 = nullptr, s2 = nullptr;
    static cudaEvent_t eFork = nullptr, ePack = nullptr, eS1 = nullptr;
    if (!s1) {
        cudaStreamCreateWithFlags(&s1, cudaStreamNonBlocking);
        cudaStreamCreateWithFlags(&s2, cudaStreamNonBlocking);
        cudaEventCreateWithFlags(&eFork, cudaEventDisableTiming);
        cudaEventCreateWithFlags(&ePack, cudaEventDisableTiming);
        cudaEventCreateWithFlags(&eS1,   cudaEventDisableTiming);
    }

    // ---- fork ----
    cudaEventRecord(eFork, 0);
    cudaStreamWaitEvent(s1, eFork, 0);
    cudaStreamWaitEvent(s2, eFork, 0);

    // branch s2: weight packing (fp16)
    pack_kernel<<<320, 1024, 0, s2>>>(Wq, bq, Wks, bks, Wvs, bvs, Wk, bk, Wv, bv,
                                      Wf1, Wf2, We);
    cudaEventRecord(ePack, s2);

    // branch s1: layernorms -> fused projections
    ln_kernel<<<ROWS_M, 256, 0, s1>>>(machine_emb, g1, bn1, p_mnorm16);
    ln_kernel<<<ROWS_O, 256, 0, s1>>>(op_emb, gop, bnop, p_onorm16);
    cudaStreamWaitEvent(s1, ePack, 0);
    {
        dim3 gQ(ROWS_M / 128, 768 / 128);
        gemm_h<<<gQ, 256, 0, s1>>>(p_mnorm16, p_Wqkv16, p_bqkv, p_qkv, nullptr,
                                   D_, 768, D_, 0, 0);
        dim3 gKV(ROWS_O / 128, 512 / 128);
        gemm_h<<<gKV, 256, 0, s1>>>(p_onorm16, p_Wkv16, p_bkv, nullptr, p_kvh,
                                    D_, 512, D_, 0, FLAG_HALFOUT);
    }
    cudaEventRecord(eS1, s1);

    // main branch: compaction chain -> gathered edge GEMM
    detect_kernel<<<256, 256>>>((const unsigned char*)mask, in_sizes[3]);
    actlist_kernel<<<32, 256>>>(mask);
    prefixfill_kernel<<<ROWS_M, 256>>>();
    cudaStreamWaitEvent(0, ePack, 0);   // gather needs fp16 We
    {
        dim3 gE(NEDGE / 128, 1);
        gemm_gather<<<gE, 512>>>(edge_emb, p_We16, be, p_Eh);
    }

    // ---- join ----
    cudaStreamWaitEvent(0, eS1, 0);

    attn_kernel<<<ROWS_M, 256>>>(machine_emb, Wo, bo, g2, bn2);

    {
        dim3 gF1(ROWS_M / 128, F_ / 128);
        gemm_h<<<gF1, 256>>>(p_h16, p_Wf1_16, bf1, nullptr, p_f1h,
                             D_, F_, D_, 0, FLAG_RELU | FLAG_HALFOUT);
        dim3 gF2(ROWS_M / 128, D_ / 128, 4);
        gemm_h<<<gF2, 256>>>(p_f1h, p_Wf2_16, bf2, p_f2p, nullptr,
                             F_, D_, F_ / 4, ROWS_M * D_, FLAG_SPLIT);
    }
    f2red_kernel<<<ROWS_M, 256>>>(bf2, out);
}

// round 10
// speedup vs baseline: 6.8807x; 1.1200x over previous
#include <cuda_runtime.h>
#include <cuda_fp16.h>
#include <cstdint>

// ---------------- problem constants ----------------
#define D_      256
#define B_      4
#define M_      64
#define N_      512
#define H_      8
#define F_      1024
#define ROWS_M  256        // B*M
#define ROWS_O  2048       // B*N
#define NEDGE   131072     // B*N*M
#define SCALE_  0.17677669529663687f   // 1/sqrt(32)
#define EPS_    1e-5f
#define BIG_NEG (-1e30f)

#define FLAG_RELU    1
#define FLAG_SPLIT   4
#define FLAG_HALFOUT 8

// ---------------- scratch (device globals; no runtime allocation) ----------------
__device__ __align__(16) __half g_mnorm16[ROWS_M * D_];
__device__ __align__(16) __half g_onorm16[ROWS_O * D_];
__device__ __align__(16) __half g_Wqkv16[D_ * 768];
__device__ __align__(16) __half g_Wkv16 [ROWS_O ? D_ * 512 : 0];
__device__ __align__(16) __half g_We16  [D_ * D_];
__device__ __align__(16) __half g_Wf1_16[D_ * F_];
__device__ __align__(16) __half g_Wf2_16[F_ * D_];
__device__ __align__(16) __half g_f1h   [ROWS_M * F_];
__device__ __align__(16) __half g_h16   [ROWS_M * D_];
__device__ __align__(16) __half g_kvh   [ROWS_O * 512];      // 0:256 k | 256:512 v (fp16)
__device__ __align__(16) __half g_Eh    [(size_t)NEDGE * D_];// compacted projected edges fp16
__device__ float g_bqkv[768];
__device__ float g_bkv [512];
__device__ float g_qkv [ROWS_M * 768];        // 0:256 q | 256:512 ks | 512:768 vs
__device__ float g_me2 [ROWS_M * D_];
__device__ float g_f2part[4 * ROWS_M * D_];
__device__ int   g_actN[ROWS_M * N_];
__device__ int   g_actCnt[ROWS_M];
__device__ int   g_rowStart[ROWS_M + 1];
__device__ int   g_rowIdx[NEDGE];
__device__ int   g_count;
__device__ int   g_flagGt1, g_flagNz;

// ---------------- helpers ----------------
__device__ __forceinline__ float warpSum(float v) {
#pragma unroll
    for (int o = 16; o; o >>= 1) v += __shfl_xor_sync(0xffffffffu, v, o);
    return v;
}
__device__ __forceinline__ uint32_t packh2(float x, float y) {
    __half2 h = __floats2half2_rn(x, y);
    return *reinterpret_cast<uint32_t*>(&h);
}
__device__ __forceinline__ uint32_t smemAddr(const void* p) {
    return (uint32_t)__cvta_generic_to_shared(p);
}

#define CP16(d, s) asm volatile("cp.async.ca.shared.global [%0], [%1], 16;" :: "r"(d), "l"(s))
#define CPCOMMIT() asm volatile("cp.async.commit_group;")
#define CPWAIT0()  asm volatile("cp.async.wait_group 0;")
#define CPWAIT1()  asm volatile("cp.async.wait_group 1;")

#define LDSM4(r, addr)                                                          \
    asm volatile("ldmatrix.sync.aligned.m8n8.x4.shared.b16 {%0,%1,%2,%3}, [%4];"\
                 : "=r"((r)[0]), "=r"((r)[1]), "=r"((r)[2]), "=r"((r)[3])       \
                 : "r"(addr))
#define LDSM4T(r, addr)                                                         \
    asm volatile("ldmatrix.sync.aligned.m8n8.x4.trans.shared.b16 {%0,%1,%2,%3}, [%4];" \
                 : "=r"((r)[0]), "=r"((r)[1]), "=r"((r)[2]), "=r"((r)[3])       \
                 : "r"(addr))
#define MMA16816(d, a, b0v, b1v)                                                \
    asm volatile("mma.sync.aligned.m16n8k16.row.col.f32.f16.f16.f32 "           \
                 "{%0,%1,%2,%3},{%4,%5,%6,%7},{%8,%9},{%0,%1,%2,%3};"           \
                 : "+f"((d)[0]), "+f"((d)[1]), "+f"((d)[2]), "+f"((d)[3])       \
                 : "r"((a)[0]), "r"((a)[1]), "r"((a)[2]), "r"((a)[3]),          \
                   "r"(b0v), "r"(b1v))

// ---------------- mask preprocessing ----------------
__global__ void detect_kernel(const unsigned char* __restrict__ p, int nbytes) {
    int i = blockIdx.x * blockDim.x + threadIdx.x;
    int stride = gridDim.x * blockDim.x;
    int gt1 = 0, nz = 0;
    for (; i < nbytes; i += stride) {
        unsigned char v = p[i];
        gt1 |= (v > 1);
        nz  |= (v != 0 && (i & 3) != 0);
    }
    if (__any_sync(0xffffffffu, gt1) && (threadIdx.x & 31) == 0) atomicOr(&g_flagGt1, 1);
    if (__any_sync(0xffffffffu, nz)  && (threadIdx.x & 31) == 0) atomicOr(&g_flagNz, 1);
}

__global__ void actlist_kernel(const void* __restrict__ mask) {
    int wid = threadIdx.x >> 5, lane = threadIdx.x & 31;
    int row = blockIdx.x * 8 + wid;
    int b = row >> 6, m = row & 63;
    int mode = g_flagGt1 ? 2 : (g_flagNz ? 1 : 0);
    int base = 0;
#pragma unroll 1
    for (int c = 0; c < 16; c++) {
        int n = c * 32 + lane;
        size_t mi = ((size_t)(b * N_ + n)) * M_ + m;
        bool a;
        if (mode == 2)      a = ((const float*)mask)[mi] != 0.0f;
        else if (mode == 1) a = ((const unsigned char*)mask)[mi] != 0;
        else                a = ((const int*)mask)[mi] != 0;
        unsigned bal = __ballot_sync(0xffffffffu, a);
        if (a) g_actN[row * N_ + base + __popc(bal & ((1u << lane) - 1u))] = n;
        base += __popc(bal);
    }
    if (lane == 0) g_actCnt[row] = base;
}

// Merged prefix + fill; resets mask flags for next replay.
__global__ void prefixfill_kernel() {
    __shared__ int ws[8];
    __shared__ int startS;
    int tid = threadIdx.x;
    int row = blockIdx.x;
    int v = g_actCnt[tid];
    int lane = tid & 31, w = tid >> 5;
    int inc = v;
#pragma unroll
    for (int o = 1; o < 32; o <<= 1) {
        int t = __shfl_up_sync(0xffffffffu, inc, o);
        if (lane >= o) inc += t;
    }
    if (lane == 31) ws[w] = inc;
    __syncthreads();
    int add = 0;
#pragma unroll
    for (int i = 0; i < 8; i++) if (i < w) add += ws[i];
    int excl = inc - v + add;
    if (row == 0) {
        g_rowStart[tid] = excl;
        if (tid == 255) { g_rowStart[256] = excl + v; g_count = excl + v; }
        if (tid == 0) { g_flagGt1 = 0; g_flagNz = 0; }
    }
    if (tid == row) startS = excl;
    __syncthreads();
    int myStart = startS;
    int myCnt = g_actCnt[row];
    int b = row >> 6, m = row & 63;
    for (int i = tid; i < myCnt; i += 256) {
        int n = g_actN[row * N_ + i];
        g_rowIdx[myStart + i] = (b * N_ + n) * M_ + m;
    }
}

// ---------------- weight packing -> fp16 ----------------
__global__ void pack_kernel(const float* __restrict__ Wq,  const float* __restrict__ bq,
                            const float* __restrict__ Wks, const float* __restrict__ bks,
                            const float* __restrict__ Wvs, const float* __restrict__ bvs,
                            const float* __restrict__ Wk,  const float* __restrict__ bk,
                            const float* __restrict__ Wv,  const float* __restrict__ bv,
                            const float* __restrict__ Wf1, const float* __restrict__ Wf2,
                            const float* __restrict__ We) {
    int stride = gridDim.x * blockDim.x;
    int i0 = blockIdx.x * blockDim.x + threadIdx.x;
    for (int i = i0; i < D_ * 768; i += stride) {
        int k = i / 768, c = i % 768;
        float v = (c < 256) ? Wq[k * 256 + c]
                : (c < 512) ? Wks[k * 256 + c - 256]
                            : Wvs[k * 256 + c - 512];
        g_Wqkv16[i] = __float2half(v);
    }
    for (int i = i0; i < D_ * 512; i += stride) {
        int k = i / 512, c = i % 512;
        g_Wkv16[i] = __float2half((c < 256) ? Wk[k * 256 + c] : Wv[k * 256 + c - 256]);
    }
    for (int i = i0; i < D_ * F_; i += stride) g_Wf1_16[i] = __float2half(Wf1[i]);
    for (int i = i0; i < F_ * D_; i += stride) g_Wf2_16[i] = __float2half(Wf2[i]);
    for (int i = i0; i < D_ * D_; i += stride) g_We16[i]  = __float2half(We[i]);
    if (i0 < 768)
        g_bqkv[i0] = (i0 < 256) ? bq[i0] : (i0 < 512) ? bks[i0 - 256] : bvs[i0 - 512];
    if (i0 < 512)
        g_bkv[i0] = (i0 < 256) ? bk[i0] : bv[i0 - 256];
}

// ---------------- layernorm (fp32 in -> fp16 out) ----------------
__global__ void ln_kernel(const float* __restrict__ x, const float* __restrict__ g,
                          const float* __restrict__ beta, __half* __restrict__ y) {
    __shared__ float red[16];
    int row = blockIdx.x;
    int tid = threadIdx.x;
    float v = x[(size_t)row * D_ + tid];
    float s  = warpSum(v);
    float s2 = warpSum(v * v);
    if ((tid & 31) == 0) { red[tid >> 5] = s; red[8 + (tid >> 5)] = s2; }
    __syncthreads();
    float sum = 0.f, sum2 = 0.f;
#pragma unroll
    for (int i = 0; i < 8; i++) { sum += red[i]; sum2 += red[8 + i]; }
    float mu  = sum * (1.0f / D_);
    float var = sum2 * (1.0f / D_) - mu * mu;
    float inv = rsqrtf(var + EPS_);
    y[(size_t)row * D_ + tid] = __float2half((v - mu) * inv * g[tid] + beta[tid]);
}

// ---------------- fp16/fp16 GEMM, cp.async 3-stage: 128x128 tile, 8 warps ----------
__global__ __launch_bounds__(256)
void gemm_h(const __half* __restrict__ A, const __half* __restrict__ W,
            const float* __restrict__ bias, float* __restrict__ C,
            __half* __restrict__ Ch,
            int K, int N, int kChunk, int partStride, int flags) {
    __shared__ __align__(16) __half A_sh[3][128][40];
    __shared__ __align__(16) __half B_sh[3][32][136];

    int tid = threadIdx.x;
    int r0 = blockIdx.x * 128, n0 = blockIdx.y * 128;
    int kb0 = blockIdx.z * kChunk;
    float* Cout = C + (size_t)blockIdx.z * partStride;

    int a1 = tid, a2 = tid + 256;
    int aR1 = a1 >> 2, aC1 = a1 & 3, aR2 = a2 >> 2, aC2 = a2 & 3;
    const __half* aS1 = A + (size_t)(r0 + aR1) * K + kb0 + aC1 * 8;
    const __half* aS2 = A + (size_t)(r0 + aR2) * K + kb0 + aC2 * 8;
    uint32_t aD1 = smemAddr(&A_sh[0][aR1][aC1 * 8]);
    uint32_t aD2 = smemAddr(&A_sh[0][aR2][aC2 * 8]);
    int bR1 = tid >> 4, bC = tid & 15, bR2 = bR1 + 16;
    const __half* bS1 = W + (size_t)(kb0 + bR1) * N + n0 + bC * 8;
    const __half* bS2 = W + (size_t)(kb0 + bR2) * N + n0 + bC * 8;
    uint32_t bD1 = smemAddr(&B_sh[0][bR1][bC * 8]);
    uint32_t bD2 = smemAddr(&B_sh[0][bR2][bC * 8]);
    const int ABUF = 128 * 40 * 2, BBUF = 32 * 136 * 2;

#define ISSUE(st, koff)                                                         \
    do {                                                                        \
        CP16(aD1 + (st) * ABUF, aS1 + (koff));                                  \
        CP16(aD2 + (st) * ABUF, aS2 + (koff));                                  \
        CP16(bD1 + (st) * BBUF, bS1 + (size_t)(koff) * N);                      \
        CP16(bD2 + (st) * BBUF, bS2 + (size_t)(koff) * N);                      \
    } while (0)

    float acc[2][8][4];
#pragma unroll
    for (int i = 0; i < 2; i++)
#pragma unroll
        for (int j = 0; j < 8; j++)
#pragma unroll
            for (int l = 0; l < 4; l++) acc[i][j][l] = 0.0f;

    int wid = tid >> 5, lane = tid & 31;
    int wm = wid & 3, wn = wid >> 2;
    int lrow = lane & 15, lcol = lane >> 4;
    uint32_t aLd = smemAddr(&A_sh[0][wm * 32 + lrow][lcol * 8]);
    uint32_t bLd = smemAddr(&B_sh[0][lrow][wn * 64 + lcol * 8]);

    int nIter = kChunk / 32;
    ISSUE(0, 0);
    CPCOMMIT();
    if (nIter > 1) ISSUE(1, 32);
    CPCOMMIT();

#pragma unroll 1
    for (int it = 0; it < nIter; it++) {
        CPWAIT1();
        __syncthreads();
        int st = it % 3;
        int nx = it + 2;
        if (nx < nIter) ISSUE(nx % 3, nx * 32);
        CPCOMMIT();
        uint32_t aB = aLd + st * ABUF;
        uint32_t bB = bLd + st * BBUF;
#pragma unroll
        for (int ks = 0; ks < 2; ks++) {
            uint32_t af[2][4];
#pragma unroll
            for (int mf = 0; mf < 2; mf++)
                LDSM4(af[mf], aB + mf * (16 * 80) + ks * 32);
            uint32_t bfm[4][4];
#pragma unroll
            for (int np = 0; np < 4; np++)
                LDSM4T(bfm[np], bB + ks * (16 * 272) + np * 32);
#pragma unroll
            for (int np = 0; np < 4; np++)
#pragma unroll
                for (int hh = 0; hh < 2; hh++) {
                    int nf = np * 2 + hh;
#pragma unroll
                    for (int mf = 0; mf < 2; mf++)
                        MMA16816(acc[mf][nf], af[mf], bfm[np][hh * 2], bfm[np][hh * 2 + 1]);
                }
        }
        __syncthreads();
    }
#undef ISSUE

    int gid = lane >> 2, tig = lane & 3;
#pragma unroll
    for (int mf = 0; mf < 2; mf++) {
#pragma unroll
        for (int half = 0; half < 2; half++) {
            int r = r0 + wm * 32 + mf * 16 + gid + half * 8;
#pragma unroll
            for (int nf = 0; nf < 8; nf++) {
                int cb = n0 + wn * 64 + nf * 8 + tig * 2;
                float v0 = acc[mf][nf][half * 2 + 0];
                float v1 = acc[mf][nf][half * 2 + 1];
                if (!(flags & FLAG_SPLIT)) {
                    v0 += bias[cb];
                    v1 += bias[cb + 1];
                    if (flags & FLAG_RELU) { v0 = fmaxf(v0, 0.f); v1 = fmaxf(v1, 0.f); }
                }
                if (flags & FLAG_HALFOUT) {
                    *(__half2*)&Ch[(size_t)r * N + cb] = __floats2half2_rn(v0, v1);
                } else {
                    Cout[(size_t)r * N + cb]     = v0;
                    Cout[(size_t)r * N + cb + 1] = v1;
                }
            }
        }
    }
}

// ---------------- gathered edge GEMM: 128x256 tile, 512 threads (16 warps) ----------
// A fp32 gathered (LDG+pack, loaded ONCE), B fp16 via cp.async, out fp16.
__global__ __launch_bounds__(512)
void gemm_gather(const float* __restrict__ A, const __half* __restrict__ W16,
                 const float* __restrict__ bias, __half* __restrict__ C) {
    __shared__ __align__(16) __half A_sh[2][128][40];    // 20.0 KB
    __shared__ __align__(16) __half B_sh[2][32][264];    // 33.0 KB
    __shared__ int src[128];

    int tid = threadIdx.x;
    int count = g_count;
    int r0 = blockIdx.x * 128;
    if (r0 >= count) return;
    if (tid < 128) {
        int gidx = r0 + tid;
        src[tid] = g_rowIdx[gidx < count ? gidx : count - 1];
    }
    __syncthreads();
    const int K = D_, N = D_;

    int aR = tid >> 2, aC = tid & 3;
    const float* aPtr = A + (size_t)src[aR] * K + aC * 8;
    int bR = tid >> 5, bC = tid & 31;
    const __half* bS1 = W16 + (size_t)bR * N + bC * 8;
    const __half* bS2 = W16 + (size_t)(bR + 16) * N + bC * 8;
    uint32_t bD1 = smemAddr(&B_sh[0][bR][bC * 8]);
    uint32_t bD2 = smemAddr(&B_sh[0][bR + 16][bC * 8]);
    const int A_BUF = 128 * 40 * 2;
    const int B_BUF = 32 * 264 * 2;

    uint32_t pa[4];
#define LOADA(off)                                                               \
    do {                                                                         \
        float4 t0 = *(const float4*)(aPtr + (off));                              \
        float4 t1 = *(const float4*)(aPtr + (off) + 4);                          \
        pa[0] = packh2(t0.x, t0.y); pa[1] = packh2(t0.z, t0.w);                  \
        pa[2] = packh2(t1.x, t1.y); pa[3] = packh2(t1.z, t1.w);                  \
    } while (0)
#define STOREA(BF) \
    *(uint4*)&A_sh[BF][aR][aC * 8] = make_uint4(pa[0], pa[1], pa[2], pa[3])
#define ISSUEB(st, koff)                                                         \
    do {                                                                         \
        CP16(bD1 + (st) * B_BUF, bS1 + (size_t)(koff) * N);                      \
        CP16(bD2 + (st) * B_BUF, bS2 + (size_t)(koff) * N);                      \
    } while (0)

    float acc[2][8][4];
#pragma unroll
    for (int i = 0; i < 2; i++)
#pragma unroll
        for (int j = 0; j < 8; j++)
#pragma unroll
            for (int l = 0; l < 4; l++) acc[i][j][l] = 0.0f;

    int wid = tid >> 5, lane = tid & 31;
    int wm = wid & 3, wn = wid >> 2;
    int lrow = lane & 15, lcol = lane >> 4;
    uint32_t aLd = smemAddr(&A_sh[0][wm * 32 + lrow][lcol * 8]);
    uint32_t bLd = smemAddr(&B_sh[0][lrow][wn * 64 + lcol * 8]);

    LOADA(0);
    ISSUEB(0, 0);
    CPCOMMIT();
    STOREA(0);
    CPWAIT0();
    __syncthreads();

    int buf = 0;
#pragma unroll 1
    for (int it = 0; it < 8; it++) {
        if (it + 1 < 8) {
            LOADA((it + 1) * 32);
            ISSUEB(buf ^ 1, (it + 1) * 32);
        }
        CPCOMMIT();
        uint32_t aB = aLd + buf * A_BUF;
        uint32_t bB = bLd + buf * B_BUF;
#pragma unroll
        for (int ks = 0; ks < 2; ks++) {
            uint32_t af[2][4];
#pragma unroll
            for (int mf = 0; mf < 2; mf++)
                LDSM4(af[mf], aB + mf * (16 * 80) + ks * 32);
            uint32_t bfm[4][4];
#pragma unroll
            for (int np = 0; np < 4; np++)
                LDSM4T(bfm[np], bB + ks * (16 * 528) + np * 32);
#pragma unroll
            for (int np = 0; np < 4; np++)
#pragma unroll
                for (int hh = 0; hh < 2; hh++) {
                    int nf = np * 2 + hh;
#pragma unroll
                    for (int mf = 0; mf < 2; mf++)
                        MMA16816(acc[mf][nf], af[mf], bfm[np][hh * 2], bfm[np][hh * 2 + 1]);
                }
        }
        if (it + 1 < 8) STOREA(buf ^ 1);
        CPWAIT0();
        __syncthreads();
        buf ^= 1;
    }
#undef LOADA
#undef STOREA
#undef ISSUEB

    int gid = lane >> 2, tig = lane & 3;
#pragma unroll
    for (int mf = 0; mf < 2; mf++) {
#pragma unroll
        for (int half = 0; half < 2; half++) {
            int r = r0 + wm * 32 + mf * 16 + gid + half * 8;
            bool rok = r < count;
#pragma unroll
            for (int nf = 0; nf < 8; nf++) {
                int cb = wn * 64 + nf * 8 + tig * 2;
                if (rok) {
                    float v0 = acc[mf][nf][half * 2 + 0] + bias[cb];
                    float v1 = acc[mf][nf][half * 2 + 1] + bias[cb + 1];
                    *(__half2*)&C[(size_t)r * N + cb] = __floats2half2_rn(v0, v1);
                }
            }
        }
    }
}

// ---------------- split-K reduction for FFN-2 (+bias +residual) -> out ----------------
__global__ void f2red_kernel(const float* __restrict__ bias, float* __restrict__ out) {
    int i = blockIdx.x * 256 + threadIdx.x;
    int c = i & 255;
    out[i] = g_me2[i] + bias[c]
           + g_f2part[i] + g_f2part[65536 + i]
           + g_f2part[131072 + i] + g_f2part[196608 + i];
}

// ---------------- attention: ONLINE softmax single pass (+ proj + resid + LN2) ------
__global__ __launch_bounds__(256)
void attn_kernel(const float* __restrict__ machine_emb,
                 const float* __restrict__ Wo, const float* __restrict__ bo,
                 const float* __restrict__ g2, const float* __restrict__ bn2) {
    __shared__ float ao[D_];
    __shared__ int   sn[N_];
    __shared__ float red[16];
    int row = blockIdx.x;
    int b = row >> 6;
    int tid = threadIdx.x, lane = tid & 31, h = tid >> 5;
    int cnt = g_actCnt[row];
    int start = g_rowStart[row];

    for (int i = tid; i < cnt; i += 256) sn[i] = g_actN[row * N_ + i];
    __syncthreads();

    int g = lane >> 3, d8 = lane & 7;
    const float* qkvRow = g_qkv + (size_t)row * 768;
    float4 q4  = ((const float4*)(qkvRow +       h * 32))[d8];
    float4 ks4 = ((const float4*)(qkvRow + 256 + h * 32))[d8];
    float4 vs4 = ((const float4*)(qkvRow + 512 + h * 32))[d8];

    float sSelf = q4.x * ks4.x + q4.y * ks4.y + q4.z * ks4.z + q4.w * ks4.w;
#pragma unroll
    for (int o = 1; o < 8; o <<= 1) sSelf += __shfl_xor_sync(0xffffffffu, sSelf, o);
    sSelf *= SCALE_;

    const __half* Eb = g_Eh  + (size_t)start * D_ + h * 32 + d8 * 4;
    const __half* Kb = g_kvh + (size_t)b * N_ * 512 + h * 32 + d8 * 4;
    const __half* Vb = Kb + 256;

    // per-group online state (group 0 seeded with the self term, p_self = 1)
    float mx = (g == 0) ? sSelf : BIG_NEG;
    float sm = (g == 0) ? 1.0f : 0.0f;
    float4 acc = make_float4(0.f, 0.f, 0.f, 0.f);
    if (g == 0) { acc.x = vs4.x; acc.y = vs4.y; acc.z = vs4.z; acc.w = vs4.w; }

#pragma unroll 2
    for (int j0 = 0; j0 < cnt; j0 += 4) {
        int j = j0 + g;
        bool ok = j < cnt;
        float t = 0.0f;
        float2 e01, e23, v01, v23;
        if (ok) {
            int n = sn[j];
            uint2 eu = *(const uint2*)(Eb + (size_t)j * D_);
            uint2 ku = *(const uint2*)(Kb + (size_t)n * 512);
            uint2 vu = *(const uint2*)(Vb + (size_t)n * 512);
            e01 = __half22float2(*(__half2*)&eu.x);
            e23 = __half22float2(*(__half2*)&eu.y);
            float2 k01 = __half22float2(*(__half2*)&ku.x);
            float2 k23 = __half22float2(*(__half2*)&ku.y);
            v01 = __half22float2(*(__half2*)&vu.x);
            v23 = __half22float2(*(__half2*)&vu.y);
            t = (q4.x + e01.x) * (k01.x + e01.x) + (q4.y + e01.y) * (k01.y + e01.y)
              + (q4.z + e23.x) * (k23.x + e23.x) + (q4.w + e23.y) * (k23.y + e23.y);
        }
#pragma unroll
        for (int o = 1; o < 8; o <<= 1) t += __shfl_xor_sync(0xffffffffu, t, o);
        if (ok) {
            t *= SCALE_;
            float nm = fmaxf(mx, t);
            float sc = __expf(mx - nm);
            float p  = __expf(t - nm);
            mx = nm;
            sm = sm * sc + p;
            acc.x = fmaf(acc.x, sc, p * (v01.x + e01.x));
            acc.y = fmaf(acc.y, sc, p * (v01.y + e01.y));
            acc.z = fmaf(acc.z, sc, p * (v23.x + e23.x));
            acc.w = fmaf(acc.w, sc, p * (v23.y + e23.y));
        }
    }

    // merge the 4 group states (same d8 across groups: lanes differ by 8/16)
#pragma unroll
    for (int o = 8; o < 32; o <<= 1) {
        float pmx = __shfl_xor_sync(0xffffffffu, mx, o);
        float psm = __shfl_xor_sync(0xffffffffu, sm, o);
        float pax = __shfl_xor_sync(0xffffffffu, acc.x, o);
        float pay = __shfl_xor_sync(0xffffffffu, acc.y, o);
        float paz = __shfl_xor_sync(0xffffffffu, acc.z, o);
        float paw = __shfl_xor_sync(0xffffffffu, acc.w, o);
        float nm = fmaxf(mx, pmx);
        float s1 = __expf(mx - nm);
        float s2 = __expf(pmx - nm);
        mx = nm;
        sm = sm * s1 + psm * s2;
        acc.x = acc.x * s1 + pax * s2;
        acc.y = acc.y * s1 + pay * s2;
        acc.z = acc.z * s1 + paz * s2;
        acc.w = acc.w * s1 + paw * s2;
    }
    if (g == 0) {
        float inv = 1.0f / sm;
        float4 r = make_float4(acc.x * inv, acc.y * inv, acc.z * inv, acc.w * inv);
        *(float4*)(ao + h * 32 + d8 * 4) = r;
    }
    __syncthreads();

    // output projection + residual
    float r = machine_emb[(size_t)row * D_ + tid] + bo[tid];
#pragma unroll 8
    for (int k = 0; k < D_; k++) r = fmaf(ao[k], Wo[(size_t)k * D_ + tid], r);
    g_me2[(size_t)row * D_ + tid] = r;

    // fused LN2 -> fp16
    float s  = warpSum(r);
    float s2 = warpSum(r * r);
    if ((tid & 31) == 0) { red[tid >> 5] = s; red[8 + (tid >> 5)] = s2; }
    __syncthreads();
    float sum = 0.f, sum2 = 0.f;
#pragma unroll
    for (int i = 0; i < 8; i++) { sum += red[i]; sum2 += red[8 + i]; }
    float mu  = sum * (1.0f / D_);
    float var = sum2 * (1.0f / D_) - mu * mu;
    float invs = rsqrtf(var + EPS_);
    g_h16[(size_t)row * D_ + tid] = __float2half((r - mu) * invs * g2[tid] + bn2[tid]);
}

// ---------------- launch ----------------
template <typename T>
static T* symAddr(const void* sym) {
    void* p = nullptr;
    cudaGetSymbolAddress(&p, sym);
    return (T*)p;
}

extern "C" void kernel_launch(void* const* d_in, const int* in_sizes, int n_in,
                              void* d_out, int out_size) {
    const float* machine_emb = (const float*)d_in[0];
    const float* op_emb      = (const float*)d_in[1];
    const float* edge_emb    = (const float*)d_in[2];
    const void*  mask        = d_in[3];
    const float* Wq  = (const float*)d_in[4];
    const float* bq  = (const float*)d_in[5];
    const float* Wk  = (const float*)d_in[6];
    const float* bk  = (const float*)d_in[7];
    const float* Wv  = (const float*)d_in[8];
    const float* bv  = (const float*)d_in[9];
    const float* Wo  = (const float*)d_in[10];
    const float* bo  = (const float*)d_in[11];
    const float* Wks = (const float*)d_in[12];
    const float* bks = (const float*)d_in[13];
    const float* Wvs = (const float*)d_in[14];
    const float* bvs = (const float*)d_in[15];
    const float* We  = (const float*)d_in[16];
    const float* be  = (const float*)d_in[17];
    const float* g1  = (const float*)d_in[18];
    const float* bn1 = (const float*)d_in[19];
    const float* g2  = (const float*)d_in[20];
    const float* bn2 = (const float*)d_in[21];
    const float* gop = (const float*)d_in[22];
    const float* bnop= (const float*)d_in[23];
    const float* Wf1 = (const float*)d_in[24];
    const float* bf1 = (const float*)d_in[25];
    const float* Wf2 = (const float*)d_in[26];
    const float* bf2 = (const float*)d_in[27];
    float* out = (float*)d_out;

    __half* p_mnorm16 = symAddr<__half>(g_mnorm16);
    __half* p_onorm16 = symAddr<__half>(g_onorm16);
    __half* p_Wqkv16  = symAddr<__half>(g_Wqkv16);
    __half* p_Wkv16   = symAddr<__half>(g_Wkv16);
    __half* p_We16    = symAddr<__half>(g_We16);
    __half* p_Wf1_16  = symAddr<__half>(g_Wf1_16);
    __half* p_Wf2_16  = symAddr<__half>(g_Wf2_16);
    __half* p_f1h     = symAddr<__half>(g_f1h);
    __half* p_h16     = symAddr<__half>(g_h16);
    __half* p_kvh     = symAddr<__half>(g_kvh);
    __half* p_Eh      = symAddr<__half>(g_Eh);
    float* p_bqkv = symAddr<float>(g_bqkv);
    float* p_bkv  = symAddr<float>(g_bkv);
    float* p_qkv  = symAddr<float>(g_qkv);
    float* p_f2p  = symAddr<float>(g_f2part);

    static cudaStream_t s1 = nullptr, s2 = nullptr;
    static cudaEvent_t eFork = nullptr, ePack = nullptr, eS1 = nullptr;
    if (!s1) {
        cudaStreamCreateWithFlags(&s1, cudaStreamNonBlocking);
        cudaStreamCreateWithFlags(&s2, cudaStreamNonBlocking);
        cudaEventCreateWithFlags(&eFork, cudaEventDisableTiming);
        cudaEventCreateWithFlags(&ePack, cudaEventDisableTiming);
        cudaEventCreateWithFlags(&eS1,   cudaEventDisableTiming);
    }

    // ---- fork ----
    cudaEventRecord(eFork, 0);
    cudaStreamWaitEvent(s1, eFork, 0);
    cudaStreamWaitEvent(s2, eFork, 0);

    // branch s2: weight packing (fp16)
    pack_kernel<<<320, 1024, 0, s2>>>(Wq, bq, Wks, bks, Wvs, bvs, Wk, bk, Wv, bv,
                                      Wf1, Wf2, We);
    cudaEventRecord(ePack, s2);

    // branch s1: layernorms -> fused projections
    ln_kernel<<<ROWS_M, 256, 0, s1>>>(machine_emb, g1, bn1, p_mnorm16);
    ln_kernel<<<ROWS_O, 256, 0, s1>>>(op_emb, gop, bnop, p_onorm16);
    cudaStreamWaitEvent(s1, ePack, 0);
    {
        dim3 gQ(ROWS_M / 128, 768 / 128);
        gemm_h<<<gQ, 256, 0, s1>>>(p_mnorm16, p_Wqkv16, p_bqkv, p_qkv, nullptr,
                                   D_, 768, D_, 0, 0);
        dim3 gKV(ROWS_O / 128, 512 / 128);
        gemm_h<<<gKV, 256, 0, s1>>>(p_onorm16, p_Wkv16, p_bkv, nullptr, p_kvh,
                                    D_, 512, D_, 0, FLAG_HALFOUT);
    }
    cudaEventRecord(eS1, s1);

    // main branch: compaction chain -> gathered edge GEMM
    detect_kernel<<<256, 256>>>((const unsigned char*)mask, in_sizes[3]);
    actlist_kernel<<<32, 256>>>(mask);
    prefixfill_kernel<<<ROWS_M, 256>>>();
    cudaStreamWaitEvent(0, ePack, 0);   // gather needs fp16 We
    {
        dim3 gE(NEDGE / 128, 1);
        gemm_gather<<<gE, 512>>>(edge_emb, p_We16, be, p_Eh);
    }

    // ---- join ----
    cudaStreamWaitEvent(0, eS1, 0);

    attn_kernel<<<ROWS_M, 256>>>(machine_emb, Wo, bo, g2, bn2);

    {
        dim3 gF1(ROWS_M / 128, F_ / 128);
        gemm_h<<<gF1, 256>>>(p_h16, p_Wf1_16, bf1, nullptr, p_f1h,
                             D_, F_, D_, 0, FLAG_RELU | FLAG_HALFOUT);
        dim3 gF2(ROWS_M / 128, D_ / 128, 4);
        gemm_h<<<gF2, 256>>>(p_f1h, p_Wf2_16, bf2, p_f2p, nullptr,
                             F_, D_, F_ / 4, ROWS_M * D_, FLAG_SPLIT);
    }
    f2red_kernel<<<ROWS_M, 256>>>(bf2, out);
}